// round 1
// baseline (speedup 1.0000x reference)
#include <cuda_runtime.h>
#include <cstddef>
#include <cstdint>

// Problem constants (hardcoded from reference): B=2, C=128, H=W=64
#define BATCH 2
#define CC 128
#define HH 64
#define WW 64
#define HW 4096
#define HEADS 4
#define HDIM 32
#define SCALE 0.17677669529663687f  // 32^-0.5

// ---------------- scratch (device globals; no allocation allowed) ----------------
__device__ float g_m1[BATCH * 32 * HW];    // relu(conv3x3(seg_mask))   (B,32,64,64)
__device__ float g_mf[BATCH * CC * HW];    // mask_feat                 (B,128,64,64)
__device__ float g_q[BATCH * CC * HW];
__device__ float g_k[BATCH * CC * HW];
__device__ float g_v[BATCH * CC * HW];
__device__ float g_gd[BATCH * CC * HW];    // guided (pre-Wo)

// ---------------- packed f32x2 helpers (Blackwell FFMA2 path) ----------------
typedef unsigned long long ull;

__device__ __forceinline__ ull pk2(float a, float b) {
    ull r;
    asm("mov.b64 %0, {%1, %2};" : "=l"(r) : "f"(a), "f"(b));
    return r;
}
__device__ __forceinline__ void upk2(ull v, float& a, float& b) {
    asm("mov.b64 {%0, %1}, %2;" : "=f"(a), "=f"(b) : "l"(v));
}
__device__ __forceinline__ ull fma2(ull a, ull b, ull c) {
    ull d;
    asm("fma.rn.f32x2 %0, %1, %2, %3;" : "=l"(d) : "l"(a), "l"(b), "l"(c));
    return d;
}
__device__ __forceinline__ ull mul2(ull a, ull b) {
    ull d;
    asm("mul.rn.f32x2 %0, %1, %2;" : "=l"(d) : "l"(a), "l"(b));
    return d;
}
__device__ __forceinline__ ull add2(ull a, ull b) {
    ull d;
    asm("add.rn.f32x2 %0, %1, %2;" : "=l"(d) : "l"(a), "l"(b));
    return d;
}

// ---------------- kernel 1: conv3x3(seg_mask) + relu -> g_m1 ----------------
__global__ void mask_conv1(const float* __restrict__ seg,
                           const float* __restrict__ Wm1,
                           const float* __restrict__ bm1) {
    int idx = blockIdx.x * 256 + threadIdx.x;   // (b,c,y,x), total 2*32*4096
    if (idx >= BATCH * 32 * HW) return;
    int x = idx & 63, y = (idx >> 6) & 63, c = (idx >> 12) & 31, b = idx >> 17;
    const float* w = Wm1 + c * 9;
    const float* s = seg + b * HW;
    float acc = bm1[c];
#pragma unroll
    for (int dy = 0; dy < 3; dy++) {
        int yy = y + dy - 1;
        if (yy < 0 || yy >= HH) continue;
#pragma unroll
        for (int dx = 0; dx < 3; dx++) {
            int xx = x + dx - 1;
            if (xx < 0 || xx >= WW) continue;
            acc += w[dy * 3 + dx] * s[yy * WW + xx];
        }
    }
    g_m1[idx] = fmaxf(acc, 0.0f);
}

// ---------------- kernel 2: conv3x3(g_m1) -> g_mf ----------------
// grid (64 rows, 2 batch), 256 threads. smem holds 3 input rows of all 32 ci.
__global__ __launch_bounds__(256) void mask_conv2(const float* __restrict__ Wm2,
                                                  const float* __restrict__ bm2) {
    int y = blockIdx.x, b = blockIdx.y;
    __shared__ float sm[32][3][66];  // [ci][row][x+1], zero-padded borders
    for (int i = threadIdx.x; i < 32 * 3 * 66; i += 256) {
        int ci = i / 198, rem = i % 198, r = rem / 66, x = rem % 66;
        int yy = y + r - 1, xx = x - 1;
        float v = 0.0f;
        if (yy >= 0 && yy < HH && xx >= 0 && xx < WW)
            v = g_m1[(((size_t)b * 32 + ci) * HH + yy) * WW + xx];
        sm[ci][r][x] = v;
    }
    __syncthreads();

    int co = threadIdx.x >> 1;
    int xh = (threadIdx.x & 1) * 32;
    float acc[32];
    float bb = bm2[co];
#pragma unroll
    for (int px = 0; px < 32; px++) acc[px] = bb;

    const float* w = Wm2 + co * 288;  // (32 ci * 9)
    for (int ci = 0; ci < 32; ci++) {
#pragma unroll
        for (int r = 0; r < 3; r++) {
            const float* row = &sm[ci][r][xh];
            float rv[34];
#pragma unroll
            for (int t = 0; t < 34; t++) rv[t] = row[t];
#pragma unroll
            for (int dx = 0; dx < 3; dx++) {
                float wv = w[(ci * 3 + r) * 3 + dx];
#pragma unroll
                for (int px = 0; px < 32; px++) acc[px] += wv * rv[px + dx];
            }
        }
    }
    float* out = g_mf + ((size_t)b * CC + co) * HW + y * WW + xh;
#pragma unroll
    for (int px = 0; px < 32; px++) out[px] = acc[px];
}

// ---------------- kernel 3: 1x1 conv as GEMM: Y[b,co,p] = sum_ci W[co,ci] X[b,ci,p] + bias ----
// grid (64 pixel-tiles, B), 256 threads. Each thread: one co, 32 pixels, packed FMA2.
__global__ __launch_bounds__(256) void gemm1x1(const float* __restrict__ X,
                                               const float* __restrict__ W,
                                               const float* __restrict__ bias,
                                               float* __restrict__ Y,
                                               const float* __restrict__ resid) {
    int b = blockIdx.y;
    int p0 = blockIdx.x * 64;
    __shared__ __align__(16) float xs[CC][64];
    for (int i = threadIdx.x; i < CC * 64; i += 256) {
        int c = i >> 6, px = i & 63;
        xs[c][px] = X[((size_t)b * CC + c) * HW + p0 + px];
    }
    __syncthreads();

    int co = threadIdx.x >> 1;
    int xh = (threadIdx.x & 1) * 32;
    ull acc2[16];
    float bb = bias[co];
    ull b2 = pk2(bb, bb);
#pragma unroll
    for (int dd = 0; dd < 16; dd++) acc2[dd] = b2;

    const float* wrow = W + co * CC;
#pragma unroll 4
    for (int ci = 0; ci < CC; ci++) {
        float w = wrow[ci];
        ull w2 = pk2(w, w);
        const ulonglong2* xr = (const ulonglong2*)&xs[ci][xh];
#pragma unroll
        for (int q = 0; q < 8; q++) {
            ulonglong2 xv = xr[q];
            acc2[2 * q]     = fma2(w2, xv.x, acc2[2 * q]);
            acc2[2 * q + 1] = fma2(w2, xv.y, acc2[2 * q + 1]);
        }
    }

    size_t off = ((size_t)b * CC + co) * HW + p0 + xh;
    if (resid != nullptr) {
        const ull* rr = (const ull*)(resid + off);
#pragma unroll
        for (int dd = 0; dd < 16; dd++) acc2[dd] = add2(acc2[dd], rr[dd]);
    }
    ull* yw = (ull*)(Y + off);
#pragma unroll
    for (int dd = 0; dd < 16; dd++) yw[dd] = acc2[dd];
}

// ---------------- kernel 4: flash attention, fp32 packed-FMA2 ----------------
// grid (HW/256, HEADS, B), 256 threads; thread = one query.
// smem K/V tiles stored d-interleaved: float2 (k[2dd][j], k[2dd+1][j]).
__global__ __launch_bounds__(256) void attn_kernel() {
    int p = blockIdx.x * 256 + threadIdx.x;
    int h = blockIdx.y;
    int b = blockIdx.z;
    size_t cbase = ((size_t)b * CC + h * HDIM) * HW;
    const float* qg = g_q + cbase;
    const float* kg = g_k + cbase;
    const float* vg = g_v + cbase;

    __shared__ __align__(16) float smK[HDIM * 128];  // 16 d-pairs x 128 keys x float2
    __shared__ __align__(16) float smV[HDIM * 128];

    ull q2[16];
#pragma unroll
    for (int dd = 0; dd < 16; dd++) {
        float a = qg[(size_t)(2 * dd) * HW + p] * SCALE;
        float c = qg[(size_t)(2 * dd + 1) * HW + p] * SCALE;
        q2[dd] = pk2(a, c);
    }
    ull acc2[16];
    ull z = pk2(0.0f, 0.0f);
#pragma unroll
    for (int dd = 0; dd < 16; dd++) acc2[dd] = z;
    float m = -1e30f, l = 0.0f;

    const ulonglong2* K2 = (const ulonglong2*)smK;
    const ulonglong2* V2 = (const ulonglong2*)smV;

    for (int k0 = 0; k0 < HW; k0 += 128) {
        __syncthreads();
        for (int i = threadIdx.x; i < HDIM * 128; i += 256) {
            int d = i >> 7, j = i & 127;
            int dst = ((d >> 1) * 128 + j) * 2 + (d & 1);
            smK[dst] = kg[(size_t)d * HW + k0 + j];
            smV[dst] = vg[(size_t)d * HW + k0 + j];
        }
        __syncthreads();

        for (int j2 = 0; j2 < 64; j2++) {
            // QK for key pair (2*j2, 2*j2+1), split accumulators for ILP
            ull s0a = z, s0b = z, s1a = z, s1b = z;
#pragma unroll
            for (int dd = 0; dd < 16; dd += 2) {
                ulonglong2 ka = K2[dd * 64 + j2];
                ulonglong2 kb = K2[(dd + 1) * 64 + j2];
                s0a = fma2(q2[dd], ka.x, s0a);
                s1a = fma2(q2[dd], ka.y, s1a);
                s0b = fma2(q2[dd + 1], kb.x, s0b);
                s1b = fma2(q2[dd + 1], kb.y, s1b);
            }
            ull s0 = add2(s0a, s0b), s1 = add2(s1a, s1b);
            float x0, x1, y0, y1;
            upk2(s0, x0, x1);
            upk2(s1, y0, y1);
            float sa = x0 + x1;
            float sb = y0 + y1;

            float mn = fmaxf(m, fmaxf(sa, sb));
            if (mn > m) {  // rare after warmup (~ln(N) times)
                float corr = __expf(m - mn);
                ull c2 = pk2(corr, corr);
#pragma unroll
                for (int dd = 0; dd < 16; dd++) acc2[dd] = mul2(acc2[dd], c2);
                l *= corr;
                m = mn;
            }
            float pa = __expf(sa - m);
            float pb = __expf(sb - m);
            l += pa + pb;
            ull pa2 = pk2(pa, pa), pb2 = pk2(pb, pb);
#pragma unroll
            for (int dd = 0; dd < 16; dd++) {
                ulonglong2 vv = V2[dd * 64 + j2];
                acc2[dd] = fma2(pa2, vv.x, acc2[dd]);
                acc2[dd] = fma2(pb2, vv.y, acc2[dd]);
            }
        }
    }

    float inv = 1.0f / l;
    float* og = g_gd + cbase + p;
#pragma unroll
    for (int dd = 0; dd < 16; dd++) {
        float a0, a1;
        upk2(acc2[dd], a0, a1);
        og[(size_t)(2 * dd) * HW]     = a0 * inv;
        og[(size_t)(2 * dd + 1) * HW] = a1 * inv;
    }
}

// ---------------- launch ----------------
extern "C" void kernel_launch(void* const* d_in, const int* in_sizes, int n_in,
                              void* d_out, int out_size) {
    const float* sr  = (const float*)d_in[0];
    const float* seg = (const float*)d_in[1];
    const float* Wq  = (const float*)d_in[2];
    const float* bq  = (const float*)d_in[3];
    const float* Wm1 = (const float*)d_in[4];
    const float* bm1 = (const float*)d_in[5];
    const float* Wm2 = (const float*)d_in[6];
    const float* bm2 = (const float*)d_in[7];
    const float* Wk  = (const float*)d_in[8];
    const float* bk  = (const float*)d_in[9];
    const float* Wv  = (const float*)d_in[10];
    const float* bv  = (const float*)d_in[11];
    const float* Wo  = (const float*)d_in[12];
    const float* bo  = (const float*)d_in[13];
    float* out = (float*)d_out;

    float *pmf, *pq, *pk, *pv, *pg;
    cudaGetSymbolAddress((void**)&pmf, g_mf);
    cudaGetSymbolAddress((void**)&pq, g_q);
    cudaGetSymbolAddress((void**)&pk, g_k);
    cudaGetSymbolAddress((void**)&pv, g_v);
    cudaGetSymbolAddress((void**)&pg, g_gd);

    mask_conv1<<<(BATCH * 32 * HW + 255) / 256, 256>>>(seg, Wm1, bm1);
    mask_conv2<<<dim3(64, BATCH), 256>>>(Wm2, bm2);
    gemm1x1<<<dim3(64, BATCH), 256>>>(sr,  Wq, bq, pq, nullptr);
    gemm1x1<<<dim3(64, BATCH), 256>>>(pmf, Wk, bk, pk, nullptr);
    gemm1x1<<<dim3(64, BATCH), 256>>>(pmf, Wv, bv, pv, nullptr);
    attn_kernel<<<dim3(HW / 256, HEADS, BATCH), 256>>>();
    gemm1x1<<<dim3(64, BATCH), 256>>>(pg, Wo, bo, out, sr);
}

// round 3
// speedup vs baseline: 2.0955x; 2.0955x over previous
#include <cuda_runtime.h>
#include <cuda_bf16.h>
#include <cstdint>
#include <cstddef>

#define BATCH 2
#define CC 128
#define HW 4096
#define HEADS 4
// 32^-0.5 * log2(e): softmax done in base-2
#define SCALE2 0.25500526764086436f

// ---------------- scratch ----------------
__device__ float g_m1[BATCH * 32 * HW];
__device__ float g_mf[BATCH * CC * HW];
__device__ float g_q[BATCH * CC * HW];
__device__ float g_k[BATCH * CC * HW];
__device__ float g_v[BATCH * CC * HW];
__device__ float g_gd[BATCH * CC * HW];

// ---------------- helpers ----------------
typedef unsigned long long ull;
__device__ __forceinline__ ull pk2(float a, float b) {
    ull r; asm("mov.b64 %0, {%1, %2};" : "=l"(r) : "f"(a), "f"(b)); return r;
}
__device__ __forceinline__ ull fma2(ull a, ull b, ull c) {
    ull d; asm("fma.rn.f32x2 %0, %1, %2, %3;" : "=l"(d) : "l"(a), "l"(b), "l"(c)); return d;
}
__device__ __forceinline__ ull add2(ull a, ull b) {
    ull d; asm("add.rn.f32x2 %0, %1, %2;" : "=l"(d) : "l"(a), "l"(b)); return d;
}
__device__ __forceinline__ uint32_t smem_u32(const void* p) {
    uint32_t a;
    asm("{ .reg .u64 t; cvta.to.shared.u64 t, %1; cvt.u32.u64 %0, t; }" : "=r"(a) : "l"(p));
    return a;
}
__device__ __forceinline__ float ex2f(float x) {
    float r; asm("ex2.approx.f32 %0, %1;" : "=f"(r) : "f"(x)); return r;
}
// pack: result.lo = lo, result.hi = hi
__device__ __forceinline__ uint32_t cvt_bf2(float hi, float lo) {
    uint32_t r; asm("cvt.rn.bf16x2.f32 %0, %1, %2;" : "=r"(r) : "f"(hi), "f"(lo)); return r;
}
__device__ __forceinline__ void ldsm4(uint32_t* r, uint32_t addr) {
    asm volatile("ldmatrix.sync.aligned.m8n8.x4.shared.b16 {%0,%1,%2,%3}, [%4];"
        : "=r"(r[0]), "=r"(r[1]), "=r"(r[2]), "=r"(r[3]) : "r"(addr));
}
__device__ __forceinline__ void mma16816(float* c, const uint32_t* a, const uint32_t* b) {
    asm volatile("mma.sync.aligned.m16n8k16.row.col.f32.bf16.bf16.f32 "
        "{%0,%1,%2,%3}, {%4,%5,%6,%7}, {%8,%9}, {%0,%1,%2,%3};"
        : "+f"(c[0]), "+f"(c[1]), "+f"(c[2]), "+f"(c[3])
        : "r"(a[0]), "r"(a[1]), "r"(a[2]), "r"(a[3]), "r"(b[0]), "r"(b[1]));
}

// smem layout inside attn (bytes): K stride 40 bf16 (80B), V stride 72 bf16 (144B)
#define KH_OFF 0
#define KL_OFF 5120
#define VH_OFF 10240
#define VL_OFF 14848
#define SBUF_BYTES 20480   // also fits Q staging: 256 rows * 40 bf16 * 2B

// ================= flash attention via HMMA (mma.sync bf16, hi/lo split) ======
// grid (16, HEADS, BATCH), 256 threads (8 warps). warp = 32 queries.
__global__ __launch_bounds__(256) void attn_mma() {
    __shared__ __align__(16) char sbuf[SBUF_BYTES];
    const int tid = threadIdx.x;
    const int lane = tid & 31;
    const int w = tid >> 5;
    const int h = blockIdx.y, b = blockIdx.z;
    const int qb = blockIdx.x * 256;
    const size_t cbase = ((size_t)b * CC + h * 32) * HW;
    const float* qg = g_q + cbase;
    const float* kg = g_k + cbase;
    const float* vg = g_v + cbase;
    const uint32_t sb = smem_u32(sbuf);

    // ---------- stage Q (hi then lo), build persistent A fragments ----------
    float qv[32];
#pragma unroll
    for (int d = 0; d < 32; d++) qv[d] = qg[(size_t)d * HW + qb + tid] * SCALE2;

    uint32_t qa_h[2][2][4], qa_l[2][2][4];
#pragma unroll
    for (int d = 0; d < 32; d++) {
        __nv_bfloat16 hv = __float2bfloat16(qv[d]);
        *(__nv_bfloat16*)(sbuf + (tid * 40 + d) * 2) = hv;
        qv[d] -= __bfloat162float(hv);
    }
    __syncthreads();
    {
        int row = w * 32 + (lane & 15);
        int colb = (lane >> 4) * 8;
#pragma unroll
        for (int m = 0; m < 2; m++)
#pragma unroll
            for (int ks = 0; ks < 2; ks++)
                ldsm4(qa_h[m][ks], sb + (((row + m * 16) * 40) + ks * 16 + colb) * 2);
    }
    __syncthreads();
#pragma unroll
    for (int d = 0; d < 32; d++)
        *(__nv_bfloat16*)(sbuf + (tid * 40 + d) * 2) = __float2bfloat16(qv[d]);
    __syncthreads();
    {
        int row = w * 32 + (lane & 15);
        int colb = (lane >> 4) * 8;
#pragma unroll
        for (int m = 0; m < 2; m++)
#pragma unroll
            for (int ks = 0; ks < 2; ks++)
                ldsm4(qa_l[m][ks], sb + (((row + m * 16) * 40) + ks * 16 + colb) * 2);
    }

    // running stats, O accumulators
    float mrow[2][2], lrow[2][2];
    float o[2][4][4];
#pragma unroll
    for (int m = 0; m < 2; m++) {
        mrow[m][0] = mrow[m][1] = -1e30f;
        lrow[m][0] = lrow[m][1] = 0.0f;
#pragma unroll
        for (int nt = 0; nt < 4; nt++)
#pragma unroll
            for (int i = 0; i < 4; i++) o[m][nt][i] = 0.0f;
    }

    // ldmatrix B-address lane pattern
    const int brow = (lane & 7) + ((lane & 16) >> 1);
    const int bcol8 = (lane & 8) ? 8 : 0;

    // per-thread load coordinates for the K/V tile (8 elems each)
    for (int t = 0; t < 64; t++) {
        const int k0 = t * 64;
        float kr[8], vr[8];
#pragma unroll
        for (int it = 0; it < 8; it++) {
            int idx = it * 256 + tid;
            int d = idx >> 6, j = idx & 63;
            kr[it] = kg[(size_t)d * HW + k0 + j];
            vr[it] = vg[(size_t)d * HW + k0 + j];
        }
        __syncthreads();  // prior tile's ldmatrix reads done
#pragma unroll
        for (int it = 0; it < 8; it++) {
            int idx = it * 256 + tid;
            int d = idx >> 6, j = idx & 63;
            __nv_bfloat16 khv = __float2bfloat16(kr[it]);
            *(__nv_bfloat16*)(sbuf + KH_OFF + (j * 40 + d) * 2) = khv;
            *(__nv_bfloat16*)(sbuf + KL_OFF + (j * 40 + d) * 2) =
                __float2bfloat16(kr[it] - __bfloat162float(khv));
            __nv_bfloat16 vhv = __float2bfloat16(vr[it]);
            *(__nv_bfloat16*)(sbuf + VH_OFF + (d * 72 + j) * 2) = vhv;
            *(__nv_bfloat16*)(sbuf + VL_OFF + (d * 72 + j) * 2) =
                __float2bfloat16(vr[it] - __bfloat162float(vhv));
        }
        __syncthreads();

        // ---------------- QK^T: S = Qh Kh + Qh Kl + Ql Kh ----------------
        float s[2][8][4];
#pragma unroll
        for (int m = 0; m < 2; m++)
#pragma unroll
            for (int nt = 0; nt < 8; nt++)
#pragma unroll
                for (int i = 0; i < 4; i++) s[m][nt][i] = 0.0f;

#pragma unroll
        for (int ks = 0; ks < 2; ks++) {
#pragma unroll
            for (int n0 = 0; n0 < 4; n0++) {
                uint32_t bh[4], bl[4];
                uint32_t ah = sb + KH_OFF + ((n0 * 16 + brow) * 40 + ks * 16 + bcol8) * 2;
                ldsm4(bh, ah);
                ldsm4(bl, ah + (KL_OFF - KH_OFF));
#pragma unroll
                for (int m = 0; m < 2; m++) {
                    mma16816(s[m][n0 * 2], qa_h[m][ks], bh);
                    mma16816(s[m][n0 * 2], qa_h[m][ks], bl);
                    mma16816(s[m][n0 * 2], qa_l[m][ks], bh);
                    mma16816(s[m][n0 * 2 + 1], qa_h[m][ks], bh + 2);
                    mma16816(s[m][n0 * 2 + 1], qa_h[m][ks], bl + 2);
                    mma16816(s[m][n0 * 2 + 1], qa_l[m][ks], bh + 2);
                }
            }
        }

        // ---------------- online softmax (base-2) ----------------
        uint32_t pu[2][8][2], pl[2][8][2];
#pragma unroll
        for (int m = 0; m < 2; m++) {
            float mt0 = -1e30f, mt1 = -1e30f;
#pragma unroll
            for (int nt = 0; nt < 8; nt++) {
                mt0 = fmaxf(mt0, fmaxf(s[m][nt][0], s[m][nt][1]));
                mt1 = fmaxf(mt1, fmaxf(s[m][nt][2], s[m][nt][3]));
            }
            mt0 = fmaxf(mt0, __shfl_xor_sync(0xffffffffu, mt0, 1));
            mt0 = fmaxf(mt0, __shfl_xor_sync(0xffffffffu, mt0, 2));
            mt1 = fmaxf(mt1, __shfl_xor_sync(0xffffffffu, mt1, 1));
            mt1 = fmaxf(mt1, __shfl_xor_sync(0xffffffffu, mt1, 2));
            float mn0 = fmaxf(mrow[m][0], mt0);
            float mn1 = fmaxf(mrow[m][1], mt1);
            float c0 = ex2f(mrow[m][0] - mn0);
            float c1 = ex2f(mrow[m][1] - mn1);
            mrow[m][0] = mn0; mrow[m][1] = mn1;
            float ls0 = 0.0f, ls1 = 0.0f;
#pragma unroll
            for (int nt = 0; nt < 8; nt++) {
                float p0 = ex2f(s[m][nt][0] - mn0);
                float p1 = ex2f(s[m][nt][1] - mn0);
                float p2 = ex2f(s[m][nt][2] - mn1);
                float p3 = ex2f(s[m][nt][3] - mn1);
                ls0 += p0 + p1;
                ls1 += p2 + p3;
                uint32_t h01 = cvt_bf2(p1, p0);
                uint32_t h23 = cvt_bf2(p3, p2);
                float hp0 = __uint_as_float(h01 << 16);
                float hp1 = __uint_as_float(h01 & 0xffff0000u);
                float hp2 = __uint_as_float(h23 << 16);
                float hp3 = __uint_as_float(h23 & 0xffff0000u);
                pu[m][nt][0] = h01;
                pu[m][nt][1] = h23;
                pl[m][nt][0] = cvt_bf2(p1 - hp1, p0 - hp0);
                pl[m][nt][1] = cvt_bf2(p3 - hp3, p2 - hp2);
            }
            lrow[m][0] = lrow[m][0] * c0 + ls0;
            lrow[m][1] = lrow[m][1] * c1 + ls1;
#pragma unroll
            for (int nt = 0; nt < 4; nt++) {
                o[m][nt][0] *= c0; o[m][nt][1] *= c0;
                o[m][nt][2] *= c1; o[m][nt][3] *= c1;
            }
        }

        // ---------------- PV: O += Ph Vh + Ph Vl + Pl Vh ----------------
#pragma unroll
        for (int ks = 0; ks < 4; ks++) {
#pragma unroll
            for (int n0 = 0; n0 < 2; n0++) {
                uint32_t vh[4], vl[4];
                uint32_t av = sb + VH_OFF + ((n0 * 16 + brow) * 72 + ks * 16 + bcol8) * 2;
                ldsm4(vh, av);
                ldsm4(vl, av + (VL_OFF - VH_OFF));
#pragma unroll
                for (int m = 0; m < 2; m++) {
                    uint32_t ah[4] = { pu[m][2 * ks][0], pu[m][2 * ks][1],
                                       pu[m][2 * ks + 1][0], pu[m][2 * ks + 1][1] };
                    uint32_t al[4] = { pl[m][2 * ks][0], pl[m][2 * ks][1],
                                       pl[m][2 * ks + 1][0], pl[m][2 * ks + 1][1] };
                    mma16816(o[m][n0 * 2], ah, vh);
                    mma16816(o[m][n0 * 2], ah, vl);
                    mma16816(o[m][n0 * 2], al, vh);
                    mma16816(o[m][n0 * 2 + 1], ah, vh + 2);
                    mma16816(o[m][n0 * 2 + 1], ah, vl + 2);
                    mma16816(o[m][n0 * 2 + 1], al, vh + 2);
                }
            }
        }
    }

    // ---------------- finalize + write ----------------
#pragma unroll
    for (int m = 0; m < 2; m++) {
        float l0 = lrow[m][0];
        l0 += __shfl_xor_sync(0xffffffffu, l0, 1);
        l0 += __shfl_xor_sync(0xffffffffu, l0, 2);
        float l1 = lrow[m][1];
        l1 += __shfl_xor_sync(0xffffffffu, l1, 1);
        l1 += __shfl_xor_sync(0xffffffffu, l1, 2);
        float i0 = 1.0f / l0, i1 = 1.0f / l1;
        int pix = qb + w * 32 + m * 16 + (lane >> 2);
#pragma unroll
        for (int nt = 0; nt < 4; nt++) {
            int d = nt * 8 + 2 * (lane & 3);
            g_gd[cbase + (size_t)d * HW + pix] = o[m][nt][0] * i0;
            g_gd[cbase + (size_t)(d + 1) * HW + pix] = o[m][nt][1] * i0;
            g_gd[cbase + (size_t)d * HW + pix + 8] = o[m][nt][2] * i1;
            g_gd[cbase + (size_t)(d + 1) * HW + pix + 8] = o[m][nt][3] * i1;
        }
    }
}

// ================= mask conv 1 =================
__global__ void mask_conv1(const float* __restrict__ seg,
                           const float* __restrict__ Wm1,
                           const float* __restrict__ bm1) {
    int idx = blockIdx.x * 256 + threadIdx.x;
    if (idx >= BATCH * 32 * HW) return;
    int x = idx & 63, y = (idx >> 6) & 63, c = (idx >> 12) & 31, b = idx >> 17;
    const float* w = Wm1 + c * 9;
    const float* s = seg + b * HW;
    float acc = bm1[c];
#pragma unroll
    for (int dy = 0; dy < 3; dy++) {
        int yy = y + dy - 1;
        if (yy < 0 || yy >= 64) continue;
#pragma unroll
        for (int dx = 0; dx < 3; dx++) {
            int xx = x + dx - 1;
            if (xx < 0 || xx >= 64) continue;
            acc += w[dy * 3 + dx] * s[yy * 64 + xx];
        }
    }
    g_m1[idx] = fmaxf(acc, 0.0f);
}

// ================= mask conv 2 =================
__global__ __launch_bounds__(256) void mask_conv2(const float* __restrict__ Wm2,
                                                  const float* __restrict__ bm2) {
    int y = blockIdx.x, b = blockIdx.y;
    __shared__ float sm[32][3][66];
    for (int i = threadIdx.x; i < 32 * 3 * 66; i += 256) {
        int ci = i / 198, rem = i % 198, r = rem / 66, x = rem % 66;
        int yy = y + r - 1, xx = x - 1;
        float v = 0.0f;
        if (yy >= 0 && yy < 64 && xx >= 0 && xx < 64)
            v = g_m1[(((size_t)b * 32 + ci) * 64 + yy) * 64 + xx];
        sm[ci][r][x] = v;
    }
    __syncthreads();
    int co = threadIdx.x >> 1;
    int xh = (threadIdx.x & 1) * 32;
    float acc[32];
    float bb = bm2[co];
#pragma unroll
    for (int px = 0; px < 32; px++) acc[px] = bb;
    const float* w = Wm2 + co * 288;
    for (int ci = 0; ci < 32; ci++) {
#pragma unroll
        for (int r = 0; r < 3; r++) {
            const float* row = &sm[ci][r][xh];
            float rv[34];
#pragma unroll
            for (int t = 0; t < 34; t++) rv[t] = row[t];
#pragma unroll
            for (int dx = 0; dx < 3; dx++) {
                float wv = w[(ci * 3 + r) * 3 + dx];
#pragma unroll
                for (int px = 0; px < 32; px++) acc[px] += wv * rv[px + dx];
            }
        }
    }
    float* out = g_mf + ((size_t)b * CC + co) * HW + y * 64 + xh;
#pragma unroll
    for (int px = 0; px < 32; px++) out[px] = acc[px];
}

// ================= 1x1 conv GEMM (32-pixel tiles) =================
__global__ __launch_bounds__(256) void gemm1x1(const float* __restrict__ X,
                                               const float* __restrict__ W,
                                               const float* __restrict__ bias,
                                               float* __restrict__ Y,
                                               const float* __restrict__ resid) {
    int b = blockIdx.y;
    int p0 = blockIdx.x * 32;
    __shared__ __align__(16) float xs[CC][32];
    for (int i = threadIdx.x; i < CC * 32; i += 256) {
        int c = i >> 5, px = i & 31;
        xs[c][px] = X[((size_t)b * CC + c) * HW + p0 + px];
    }
    __syncthreads();
    int co = threadIdx.x >> 1;
    int xh = (threadIdx.x & 1) * 16;
    ull acc[8];
    float bb = bias[co];
    ull b2 = pk2(bb, bb);
#pragma unroll
    for (int q = 0; q < 8; q++) acc[q] = b2;
    const float* wr = W + co * CC;
#pragma unroll 4
    for (int ci = 0; ci < CC; ci++) {
        float w = wr[ci];
        ull w2 = pk2(w, w);
        const ulonglong2* xr = (const ulonglong2*)&xs[ci][xh];
#pragma unroll
        for (int q = 0; q < 4; q++) {
            ulonglong2 xv = xr[q];
            acc[2 * q]     = fma2(w2, xv.x, acc[2 * q]);
            acc[2 * q + 1] = fma2(w2, xv.y, acc[2 * q + 1]);
        }
    }
    size_t off = ((size_t)b * CC + co) * HW + p0 + xh;
    if (resid != nullptr) {
        const ull* rr = (const ull*)(resid + off);
#pragma unroll
        for (int q = 0; q < 8; q++) acc[q] = add2(acc[q], rr[q]);
    }
    ull* yw = (ull*)(Y + off);
#pragma unroll
    for (int q = 0; q < 8; q++) yw[q] = acc[q];
}

// fused K+V gemm (shared X tile)
__global__ __launch_bounds__(256) void gemm1x1_kv(const float* __restrict__ X,
                                                  const float* __restrict__ Wk,
                                                  const float* __restrict__ bk,
                                                  float* __restrict__ Yk,
                                                  const float* __restrict__ Wv,
                                                  const float* __restrict__ bv,
                                                  float* __restrict__ Yv) {
    int b = blockIdx.y;
    int p0 = blockIdx.x * 32;
    __shared__ __align__(16) float xs[CC][32];
    for (int i = threadIdx.x; i < CC * 32; i += 256) {
        int c = i >> 5, px = i & 31;
        xs[c][px] = X[((size_t)b * CC + c) * HW + p0 + px];
    }
    __syncthreads();
    int co = threadIdx.x >> 1;
    int xh = (threadIdx.x & 1) * 16;
    ull acck[8], accv[8];
    ull bk2 = pk2(bk[co], bk[co]);
    ull bv2 = pk2(bv[co], bv[co]);
#pragma unroll
    for (int q = 0; q < 8; q++) { acck[q] = bk2; accv[q] = bv2; }
    const float* wkr = Wk + co * CC;
    const float* wvr = Wv + co * CC;
#pragma unroll 2
    for (int ci = 0; ci < CC; ci++) {
        ull wk2 = pk2(wkr[ci], wkr[ci]);
        ull wv2 = pk2(wvr[ci], wvr[ci]);
        const ulonglong2* xr = (const ulonglong2*)&xs[ci][xh];
#pragma unroll
        for (int q = 0; q < 4; q++) {
            ulonglong2 xv = xr[q];
            acck[2 * q]     = fma2(wk2, xv.x, acck[2 * q]);
            acck[2 * q + 1] = fma2(wk2, xv.y, acck[2 * q + 1]);
            accv[2 * q]     = fma2(wv2, xv.x, accv[2 * q]);
            accv[2 * q + 1] = fma2(wv2, xv.y, accv[2 * q + 1]);
        }
    }
    size_t off = ((size_t)b * CC + co) * HW + p0 + xh;
    ull* yk = (ull*)(Yk + off);
    ull* yv = (ull*)(Yv + off);
#pragma unroll
    for (int q = 0; q < 8; q++) { yk[q] = acck[q]; yv[q] = accv[q]; }
}

// ---------------- launch ----------------
extern "C" void kernel_launch(void* const* d_in, const int* in_sizes, int n_in,
                              void* d_out, int out_size) {
    const float* sr  = (const float*)d_in[0];
    const float* seg = (const float*)d_in[1];
    const float* Wq  = (const float*)d_in[2];
    const float* bq  = (const float*)d_in[3];
    const float* Wm1 = (const float*)d_in[4];
    const float* bm1 = (const float*)d_in[5];
    const float* Wm2 = (const float*)d_in[6];
    const float* bm2 = (const float*)d_in[7];
    const float* Wk  = (const float*)d_in[8];
    const float* bk  = (const float*)d_in[9];
    const float* Wv  = (const float*)d_in[10];
    const float* bv  = (const float*)d_in[11];
    const float* Wo  = (const float*)d_in[12];
    const float* bo  = (const float*)d_in[13];
    float* out = (float*)d_out;

    float *pmf, *pq, *pk, *pv, *pg;
    cudaGetSymbolAddress((void**)&pmf, g_mf);
    cudaGetSymbolAddress((void**)&pq, g_q);
    cudaGetSymbolAddress((void**)&pk, g_k);
    cudaGetSymbolAddress((void**)&pv, g_v);
    cudaGetSymbolAddress((void**)&pg, g_gd);

    mask_conv1<<<(BATCH * 32 * HW + 255) / 256, 256>>>(seg, Wm1, bm1);
    mask_conv2<<<dim3(64, BATCH), 256>>>(Wm2, bm2);
    gemm1x1<<<dim3(HW / 32, BATCH), 256>>>(sr, Wq, bq, pq, nullptr);
    gemm1x1_kv<<<dim3(HW / 32, BATCH), 256>>>(pmf, Wk, bk, pk, Wv, bv, pv);
    attn_mma<<<dim3(HW / 256, HEADS, BATCH), 256>>>();
    gemm1x1<<<dim3(HW / 32, BATCH), 256>>>(pg, Wo, bo, out, sr);
}

// round 4
// speedup vs baseline: 3.5495x; 1.6939x over previous
#include <cuda_runtime.h>
#include <cuda_fp16.h>
#include <cstdint>
#include <cstddef>

#define BATCH 2
#define CC 128
#define HW 4096
#define HEADS 4
// 32^-0.5 * log2(e): softmax in base-2
#define SCALE2 0.25500526764086436f

// ---------------- scratch ----------------
__device__ float g_m1[BATCH * 32 * HW];
__device__ float g_mf[BATCH * CC * HW];
__device__ float g_q[BATCH * CC * HW];
__device__ float g_k[BATCH * CC * HW];
__device__ float g_v[BATCH * CC * HW];
__device__ float g_gd[BATCH * CC * HW];

// ---------------- helpers ----------------
__device__ __forceinline__ uint32_t smem_u32(const void* p) {
    uint32_t a;
    asm("{ .reg .u64 t; cvta.to.shared.u64 t, %1; cvt.u32.u64 %0, t; }" : "=r"(a) : "l"(p));
    return a;
}
__device__ __forceinline__ float ex2f(float x) {
    float r; asm("ex2.approx.f32 %0, %1;" : "=f"(r) : "f"(x)); return r;
}
// pack two f32 -> f16x2 (hi goes to upper half, lo to lower half)
__device__ __forceinline__ uint32_t cvt_f16x2(float hi, float lo) {
    uint32_t r; asm("cvt.rn.f16x2.f32 %0, %1, %2;" : "=r"(r) : "f"(hi), "f"(lo)); return r;
}
__device__ __forceinline__ void ldsm4(uint32_t* r, uint32_t addr) {
    asm volatile("ldmatrix.sync.aligned.m8n8.x4.shared.b16 {%0,%1,%2,%3}, [%4];"
        : "=r"(r[0]), "=r"(r[1]), "=r"(r[2]), "=r"(r[3]) : "r"(addr));
}
__device__ __forceinline__ void mma16816(float* c, const uint32_t* a, const uint32_t* b) {
    asm volatile("mma.sync.aligned.m16n8k16.row.col.f32.f16.f16.f32 "
        "{%0,%1,%2,%3}, {%4,%5,%6,%7}, {%8,%9}, {%0,%1,%2,%3};"
        : "+f"(c[0]), "+f"(c[1]), "+f"(c[2]), "+f"(c[3])
        : "r"(a[0]), "r"(a[1]), "r"(a[2]), "r"(a[3]), "r"(b[0]), "r"(b[1]));
}

// ================================================================
// flash attention: fp16 2-term (Q split hi/lo vs K hi; P hi vs V split hi/lo)
// grid (16, HEADS, BATCH), 256 threads (8 warps). warp = 32 queries.
// ================================================================
#define KH_OFF 0
#define VH_OFF 5120
#define VL_OFF 9728
#define SBUF_BYTES 20480   // Q staging needs 256*40*2 = 20480

__global__ __launch_bounds__(256) void attn_mma() {
    __shared__ __align__(16) char sbuf[SBUF_BYTES];
    const int tid = threadIdx.x;
    const int lane = tid & 31;
    const int w = tid >> 5;
    const int h = blockIdx.y, b = blockIdx.z;
    const int qb = blockIdx.x * 256;
    const size_t cbase = ((size_t)b * CC + h * 32) * HW;
    const float* qg = g_q + cbase;
    const float* kg = g_k + cbase;
    const float* vg = g_v + cbase;
    const uint32_t sb = smem_u32(sbuf);

    // ---------- stage Q (hi then lo), build persistent A fragments ----------
    float qv[32];
#pragma unroll
    for (int d = 0; d < 32; d++) qv[d] = qg[(size_t)d * HW + qb + tid] * SCALE2;

    uint32_t qa_h[2][2][4], qa_l[2][2][4];
#pragma unroll
    for (int d = 0; d < 32; d++) {
        __half hv = __float2half(qv[d]);
        *(__half*)(sbuf + (tid * 40 + d) * 2) = hv;
        qv[d] -= __half2float(hv);
    }
    __syncthreads();
    {
        int row = w * 32 + (lane & 15);
        int colb = (lane >> 4) * 8;
#pragma unroll
        for (int m = 0; m < 2; m++)
#pragma unroll
            for (int ks = 0; ks < 2; ks++)
                ldsm4(qa_h[m][ks], sb + (((row + m * 16) * 40) + ks * 16 + colb) * 2);
    }
    __syncthreads();
#pragma unroll
    for (int d = 0; d < 32; d++)
        *(__half*)(sbuf + (tid * 40 + d) * 2) = __float2half(qv[d]);
    __syncthreads();
    {
        int row = w * 32 + (lane & 15);
        int colb = (lane >> 4) * 8;
#pragma unroll
        for (int m = 0; m < 2; m++)
#pragma unroll
            for (int ks = 0; ks < 2; ks++)
                ldsm4(qa_l[m][ks], sb + (((row + m * 16) * 40) + ks * 16 + colb) * 2);
    }

    float mrow[2][2], lrow[2][2];
    float o[2][4][4];
#pragma unroll
    for (int m = 0; m < 2; m++) {
        mrow[m][0] = mrow[m][1] = -1e30f;
        lrow[m][0] = lrow[m][1] = 0.0f;
#pragma unroll
        for (int nt = 0; nt < 4; nt++)
#pragma unroll
            for (int i = 0; i < 4; i++) o[m][nt][i] = 0.0f;
    }

    const int brow = (lane & 7) + ((lane & 16) >> 1);
    const int bcol8 = (lane & 8) ? 8 : 0;

    for (int t = 0; t < 64; t++) {
        const int k0 = t * 64;
        float kr[8], vr[8];
#pragma unroll
        for (int it = 0; it < 8; it++) {
            int idx = it * 256 + tid;
            int d = idx >> 6, j = idx & 63;
            kr[it] = kg[(size_t)d * HW + k0 + j];
            vr[it] = vg[(size_t)d * HW + k0 + j];
        }
        __syncthreads();
#pragma unroll
        for (int it = 0; it < 8; it++) {
            int idx = it * 256 + tid;
            int d = idx >> 6, j = idx & 63;
            *(__half*)(sbuf + KH_OFF + (j * 40 + d) * 2) = __float2half(kr[it]);
            __half vhv = __float2half(vr[it]);
            *(__half*)(sbuf + VH_OFF + (d * 72 + j) * 2) = vhv;
            *(__half*)(sbuf + VL_OFF + (d * 72 + j) * 2) =
                __float2half(vr[it] - __half2float(vhv));
        }
        __syncthreads();

        // ---------------- QK^T: S = (Qh + Ql) Kh ----------------
        float s[2][8][4];
#pragma unroll
        for (int m = 0; m < 2; m++)
#pragma unroll
            for (int nt = 0; nt < 8; nt++)
#pragma unroll
                for (int i = 0; i < 4; i++) s[m][nt][i] = 0.0f;

#pragma unroll
        for (int ks = 0; ks < 2; ks++) {
#pragma unroll
            for (int n0 = 0; n0 < 4; n0++) {
                uint32_t bh[4];
                ldsm4(bh, sb + KH_OFF + ((n0 * 16 + brow) * 40 + ks * 16 + bcol8) * 2);
#pragma unroll
                for (int m = 0; m < 2; m++) {
                    mma16816(s[m][n0 * 2], qa_h[m][ks], bh);
                    mma16816(s[m][n0 * 2], qa_l[m][ks], bh);
                    mma16816(s[m][n0 * 2 + 1], qa_h[m][ks], bh + 2);
                    mma16816(s[m][n0 * 2 + 1], qa_l[m][ks], bh + 2);
                }
            }
        }

        // ---------------- online softmax (base-2) ----------------
        uint32_t pu[2][8][2];
#pragma unroll
        for (int m = 0; m < 2; m++) {
            float mt0 = -1e30f, mt1 = -1e30f;
#pragma unroll
            for (int nt = 0; nt < 8; nt++) {
                mt0 = fmaxf(mt0, fmaxf(s[m][nt][0], s[m][nt][1]));
                mt1 = fmaxf(mt1, fmaxf(s[m][nt][2], s[m][nt][3]));
            }
            mt0 = fmaxf(mt0, __shfl_xor_sync(0xffffffffu, mt0, 1));
            mt0 = fmaxf(mt0, __shfl_xor_sync(0xffffffffu, mt0, 2));
            mt1 = fmaxf(mt1, __shfl_xor_sync(0xffffffffu, mt1, 1));
            mt1 = fmaxf(mt1, __shfl_xor_sync(0xffffffffu, mt1, 2));
            float mn0 = fmaxf(mrow[m][0], mt0);
            float mn1 = fmaxf(mrow[m][1], mt1);
            float c0 = ex2f(mrow[m][0] - mn0);
            float c1 = ex2f(mrow[m][1] - mn1);
            mrow[m][0] = mn0; mrow[m][1] = mn1;
            float ls0 = 0.0f, ls1 = 0.0f;
#pragma unroll
            for (int nt = 0; nt < 8; nt++) {
                float p0 = ex2f(s[m][nt][0] - mn0);
                float p1 = ex2f(s[m][nt][1] - mn0);
                float p2 = ex2f(s[m][nt][2] - mn1);
                float p3 = ex2f(s[m][nt][3] - mn1);
                ls0 += p0 + p1;
                ls1 += p2 + p3;
                pu[m][nt][0] = cvt_f16x2(p1, p0);
                pu[m][nt][1] = cvt_f16x2(p3, p2);
            }
            lrow[m][0] = lrow[m][0] * c0 + ls0;
            lrow[m][1] = lrow[m][1] * c1 + ls1;
#pragma unroll
            for (int nt = 0; nt < 4; nt++) {
                o[m][nt][0] *= c0; o[m][nt][1] *= c0;
                o[m][nt][2] *= c1; o[m][nt][3] *= c1;
            }
        }

        // ---------------- PV: O += Ph (Vh + Vl) ----------------
#pragma unroll
        for (int ks = 0; ks < 4; ks++) {
#pragma unroll
            for (int n0 = 0; n0 < 2; n0++) {
                uint32_t vh[4], vl[4];
                uint32_t av = sb + VH_OFF + ((n0 * 16 + brow) * 72 + ks * 16 + bcol8) * 2;
                ldsm4(vh, av);
                ldsm4(vl, av + (VL_OFF - VH_OFF));
#pragma unroll
                for (int m = 0; m < 2; m++) {
                    uint32_t ah[4] = { pu[m][2 * ks][0], pu[m][2 * ks][1],
                                       pu[m][2 * ks + 1][0], pu[m][2 * ks + 1][1] };
                    mma16816(o[m][n0 * 2], ah, vh);
                    mma16816(o[m][n0 * 2], ah, vl);
                    mma16816(o[m][n0 * 2 + 1], ah, vh + 2);
                    mma16816(o[m][n0 * 2 + 1], ah, vl + 2);
                }
            }
        }
    }

    // ---------------- finalize ----------------
#pragma unroll
    for (int m = 0; m < 2; m++) {
        float l0 = lrow[m][0];
        l0 += __shfl_xor_sync(0xffffffffu, l0, 1);
        l0 += __shfl_xor_sync(0xffffffffu, l0, 2);
        float l1 = lrow[m][1];
        l1 += __shfl_xor_sync(0xffffffffu, l1, 1);
        l1 += __shfl_xor_sync(0xffffffffu, l1, 2);
        float i0 = 1.0f / l0, i1 = 1.0f / l1;
        int pix = qb + w * 32 + m * 16 + (lane >> 2);
#pragma unroll
        for (int nt = 0; nt < 4; nt++) {
            int d = nt * 8 + 2 * (lane & 3);
            g_gd[cbase + (size_t)d * HW + pix] = o[m][nt][0] * i0;
            g_gd[cbase + (size_t)(d + 1) * HW + pix] = o[m][nt][1] * i0;
            g_gd[cbase + (size_t)d * HW + pix + 8] = o[m][nt][2] * i1;
            g_gd[cbase + (size_t)(d + 1) * HW + pix + 8] = o[m][nt][3] * i1;
        }
    }
}

// ================================================================
// 1x1 conv via HMMA: Y[co][p] = W[co][ci] X[ci][p] + bias (+resid)
// m = co (A = W hi, fp16), n = 64 pixels (B = X hi/lo), k = ci = 128
// grid (HW/64, BATCH), 256 threads (8 warps), warp = 16 co rows.
// ================================================================
template<bool DUAL>
__global__ __launch_bounds__(256) void conv1x1_tc(
    const float* __restrict__ X,
    const float* __restrict__ W1, const float* __restrict__ b1, float* __restrict__ Y1,
    const float* __restrict__ W2, const float* __restrict__ b2, float* __restrict__ Y2,
    const float* __restrict__ resid) {
    __shared__ __align__(16) char sbuf[34816];
    const int tid = threadIdx.x;
    const int lane = tid & 31;
    const int w = tid >> 5;
    const int bb = blockIdx.y;
    const int p0 = blockIdx.x * 64;
    const uint32_t sb = smem_u32(sbuf);
    const int brow = (lane & 7) + ((lane & 16) >> 1);
    const int bcol8 = (lane & 8) ? 8 : 0;

    uint32_t wa1[8][4], wa2[8][4];
    // ---- stage W1 (hi fp16), extract A fragments ----
    {
#pragma unroll
        for (int i = 0; i < 16; i++) {
            int idx = i * 256 + tid;
            int co = idx >> 5, ci = (idx & 31) * 4;
            float4 v = *(const float4*)(W1 + co * CC + ci);
            __half* d = (__half*)(sbuf) + co * 136 + ci;
            d[0] = __float2half(v.x); d[1] = __float2half(v.y);
            d[2] = __float2half(v.z); d[3] = __float2half(v.w);
        }
        __syncthreads();
        int row = w * 16 + (lane & 15);
        int colb = (lane >> 4) * 8;
#pragma unroll
        for (int ks = 0; ks < 8; ks++)
            ldsm4(wa1[ks], sb + (row * 136 + ks * 16 + colb) * 2);
        __syncthreads();
    }
    if (DUAL) {
#pragma unroll
        for (int i = 0; i < 16; i++) {
            int idx = i * 256 + tid;
            int co = idx >> 5, ci = (idx & 31) * 4;
            float4 v = *(const float4*)(W2 + co * CC + ci);
            __half* d = (__half*)(sbuf) + co * 136 + ci;
            d[0] = __float2half(v.x); d[1] = __float2half(v.y);
            d[2] = __float2half(v.z); d[3] = __float2half(v.w);
        }
        __syncthreads();
        int row = w * 16 + (lane & 15);
        int colb = (lane >> 4) * 8;
#pragma unroll
        for (int ks = 0; ks < 8; ks++)
            ldsm4(wa2[ks], sb + (row * 136 + ks * 16 + colb) * 2);
        __syncthreads();
    }

    // ---- stage X tile: [px 64][ci 136] hi at 0, lo at +17408B ----
#pragma unroll
    for (int i = 0; i < 8; i++) {
        int idx = i * 256 + tid;
        int ci = idx >> 4, px = (idx & 15) * 4;
        float4 v = *(const float4*)(X + ((size_t)bb * CC + ci) * HW + p0 + px);
        float vv[4] = { v.x, v.y, v.z, v.w };
#pragma unroll
        for (int j = 0; j < 4; j++) {
            __half hv = __float2half(vv[j]);
            *((__half*)(sbuf) + (px + j) * 136 + ci) = hv;
            *((__half*)(sbuf + 17408) + (px + j) * 136 + ci) =
                __float2half(vv[j] - __half2float(hv));
        }
    }
    __syncthreads();

    // ---- MMA mainloop ----
    float acc1[8][4], acc2[8][4];
#pragma unroll
    for (int nt = 0; nt < 8; nt++)
#pragma unroll
        for (int i = 0; i < 4; i++) { acc1[nt][i] = 0.0f; acc2[nt][i] = 0.0f; }

#pragma unroll
    for (int ks = 0; ks < 8; ks++) {
#pragma unroll
        for (int n0 = 0; n0 < 4; n0++) {
            uint32_t bh[4], bl[4];
            uint32_t a = sb + ((n0 * 16 + brow) * 136 + ks * 16 + bcol8) * 2;
            ldsm4(bh, a);
            ldsm4(bl, a + 17408);
            mma16816(acc1[n0 * 2], wa1[ks], bh);
            mma16816(acc1[n0 * 2], wa1[ks], bl);
            mma16816(acc1[n0 * 2 + 1], wa1[ks], bh + 2);
            mma16816(acc1[n0 * 2 + 1], wa1[ks], bl + 2);
            if (DUAL) {
                mma16816(acc2[n0 * 2], wa2[ks], bh);
                mma16816(acc2[n0 * 2], wa2[ks], bl);
                mma16816(acc2[n0 * 2 + 1], wa2[ks], bh + 2);
                mma16816(acc2[n0 * 2 + 1], wa2[ks], bl + 2);
            }
        }
    }

    // ---- epilogue ----
    int coA = w * 16 + (lane >> 2);
    int coB = coA + 8;
    float b1A = b1[coA], b1B = b1[coB];
    float b2A = 0.0f, b2B = 0.0f;
    if (DUAL) { b2A = b2[coA]; b2B = b2[coB]; }
    size_t baseA = ((size_t)bb * CC + coA) * HW + p0;
    size_t baseB = ((size_t)bb * CC + coB) * HW + p0;
#pragma unroll
    for (int nt = 0; nt < 8; nt++) {
        int px = nt * 8 + 2 * (lane & 3);
        float vA0 = acc1[nt][0] + b1A, vA1 = acc1[nt][1] + b1A;
        float vB0 = acc1[nt][2] + b1B, vB1 = acc1[nt][3] + b1B;
        if (resid != nullptr) {
            float2 rA = *(const float2*)(resid + baseA + px);
            float2 rB = *(const float2*)(resid + baseB + px);
            vA0 += rA.x; vA1 += rA.y; vB0 += rB.x; vB1 += rB.y;
        }
        *(float2*)(Y1 + baseA + px) = make_float2(vA0, vA1);
        *(float2*)(Y1 + baseB + px) = make_float2(vB0, vB1);
        if (DUAL) {
            *(float2*)(Y2 + baseA + px) =
                make_float2(acc2[nt][0] + b2A, acc2[nt][1] + b2A);
            *(float2*)(Y2 + baseB + px) =
                make_float2(acc2[nt][2] + b2B, acc2[nt][3] + b2B);
        }
    }
}

// ================= mask conv 1 =================
__global__ void mask_conv1(const float* __restrict__ seg,
                           const float* __restrict__ Wm1,
                           const float* __restrict__ bm1) {
    int idx = blockIdx.x * 256 + threadIdx.x;
    if (idx >= BATCH * 32 * HW) return;
    int x = idx & 63, y = (idx >> 6) & 63, c = (idx >> 12) & 31, b = idx >> 17;
    const float* w = Wm1 + c * 9;
    const float* s = seg + b * HW;
    float acc = bm1[c];
#pragma unroll
    for (int dy = 0; dy < 3; dy++) {
        int yy = y + dy - 1;
        if (yy < 0 || yy >= 64) continue;
#pragma unroll
        for (int dx = 0; dx < 3; dx++) {
            int xx = x + dx - 1;
            if (xx < 0 || xx >= 64) continue;
            acc += w[dy * 3 + dx] * s[yy * 64 + xx];
        }
    }
    g_m1[idx] = fmaxf(acc, 0.0f);
}

// ================= mask conv 2 =================
__global__ __launch_bounds__(256) void mask_conv2(const float* __restrict__ Wm2,
                                                  const float* __restrict__ bm2) {
    int y = blockIdx.x, b = blockIdx.y;
    __shared__ float sm[32][3][66];
    for (int i = threadIdx.x; i < 32 * 3 * 66; i += 256) {
        int ci = i / 198, rem = i % 198, r = rem / 66, x = rem % 66;
        int yy = y + r - 1, xx = x - 1;
        float v = 0.0f;
        if (yy >= 0 && yy < 64 && xx >= 0 && xx < 64)
            v = g_m1[(((size_t)b * 32 + ci) * 64 + yy) * 64 + xx];
        sm[ci][r][x] = v;
    }
    __syncthreads();
    int co = threadIdx.x >> 1;
    int xh = (threadIdx.x & 1) * 32;
    float acc[32];
    float bb = bm2[co];
#pragma unroll
    for (int px = 0; px < 32; px++) acc[px] = bb;
    const float* w = Wm2 + co * 288;
    for (int ci = 0; ci < 32; ci++) {
#pragma unroll
        for (int r = 0; r < 3; r++) {
            const float* row = &sm[ci][r][xh];
            float rv[34];
#pragma unroll
            for (int t = 0; t < 34; t++) rv[t] = row[t];
#pragma unroll
            for (int dx = 0; dx < 3; dx++) {
                float wv = w[(ci * 3 + r) * 3 + dx];
#pragma unroll
                for (int px = 0; px < 32; px++) acc[px] += wv * rv[px + dx];
            }
        }
    }
    float* out = g_mf + ((size_t)b * CC + co) * HW + y * 64 + xh;
#pragma unroll
    for (int px = 0; px < 32; px++) out[px] = acc[px];
}

// ---------------- launch ----------------
extern "C" void kernel_launch(void* const* d_in, const int* in_sizes, int n_in,
                              void* d_out, int out_size) {
    const float* sr  = (const float*)d_in[0];
    const float* seg = (const float*)d_in[1];
    const float* Wq  = (const float*)d_in[2];
    const float* bq  = (const float*)d_in[3];
    const float* Wm1 = (const float*)d_in[4];
    const float* bm1 = (const float*)d_in[5];
    const float* Wm2 = (const float*)d_in[6];
    const float* bm2 = (const float*)d_in[7];
    const float* Wk  = (const float*)d_in[8];
    const float* bk  = (const float*)d_in[9];
    const float* Wv  = (const float*)d_in[10];
    const float* bv  = (const float*)d_in[11];
    const float* Wo  = (const float*)d_in[12];
    const float* bo  = (const float*)d_in[13];
    float* out = (float*)d_out;

    float *pmf, *pq, *pk, *pv, *pg;
    cudaGetSymbolAddress((void**)&pmf, g_mf);
    cudaGetSymbolAddress((void**)&pq, g_q);
    cudaGetSymbolAddress((void**)&pk, g_k);
    cudaGetSymbolAddress((void**)&pv, g_v);
    cudaGetSymbolAddress((void**)&pg, g_gd);

    mask_conv1<<<(BATCH * 32 * HW + 255) / 256, 256>>>(seg, Wm1, bm1);
    mask_conv2<<<dim3(64, BATCH), 256>>>(Wm2, bm2);
    conv1x1_tc<false><<<dim3(HW / 64, BATCH), 256>>>(
        sr, Wq, bq, pq, nullptr, nullptr, nullptr, nullptr);
    conv1x1_tc<true><<<dim3(HW / 64, BATCH), 256>>>(
        pmf, Wk, bk, pk, Wv, bv, pv, nullptr);
    attn_mma<<<dim3(HW / 256, HEADS, BATCH), 256>>>();
    conv1x1_tc<false><<<dim3(HW / 64, BATCH), 256>>>(
        pg, Wo, bo, out, nullptr, nullptr, nullptr, sr);
}

// round 6
// speedup vs baseline: 4.9593x; 1.3972x over previous
#include <cuda_runtime.h>
#include <cuda_fp16.h>
#include <cstdint>
#include <cstddef>

#define BATCH 2
#define CC 128
#define HW 4096
#define HEADS 4
// 32^-0.5 * log2(e): softmax in base-2
#define SCALE2 0.25500526764086436f

// ---------------- scratch ----------------
__device__ float g_m1[BATCH * 32 * HW];
__device__ float g_mf[BATCH * CC * HW];
__device__ float g_q[BATCH * CC * HW];
__device__ float g_gd[BATCH * CC * HW];
__device__ __align__(16) __half g_kh[BATCH * CC * HW];
__device__ __align__(16) __half g_vh[BATCH * CC * HW];

// ---------------- helpers ----------------
__device__ __forceinline__ uint32_t smem_u32(const void* p) {
    uint32_t a;
    asm("{ .reg .u64 t; cvta.to.shared.u64 t, %1; cvt.u32.u64 %0, t; }" : "=r"(a) : "l"(p));
    return a;
}
__device__ __forceinline__ float ex2f(float x) {
    float r; asm("ex2.approx.f32 %0, %1;" : "=f"(r) : "f"(x)); return r;
}
// pack two f32 -> f16x2 (first operand to upper half, second to lower)
__device__ __forceinline__ uint32_t cvt_f16x2(float hi, float lo) {
    uint32_t r; asm("cvt.rn.f16x2.f32 %0, %1, %2;" : "=r"(r) : "f"(hi), "f"(lo)); return r;
}
__device__ __forceinline__ uint32_t ex2_h2(uint32_t a) {
    uint32_t r; asm("ex2.approx.f16x2 %0, %1;" : "=r"(r) : "r"(a)); return r;
}
__device__ __forceinline__ void ldsm4(uint32_t* r, uint32_t addr) {
    asm volatile("ldmatrix.sync.aligned.m8n8.x4.shared.b16 {%0,%1,%2,%3}, [%4];"
        : "=r"(r[0]), "=r"(r[1]), "=r"(r[2]), "=r"(r[3]) : "r"(addr));
}
__device__ __forceinline__ void ldsm4t(uint32_t* r, uint32_t addr) {
    asm volatile("ldmatrix.sync.aligned.m8n8.x4.trans.shared.b16 {%0,%1,%2,%3}, [%4];"
        : "=r"(r[0]), "=r"(r[1]), "=r"(r[2]), "=r"(r[3]) : "r"(addr));
}
__device__ __forceinline__ void ldsm2(uint32_t* r, uint32_t addr) {
    asm volatile("ldmatrix.sync.aligned.m8n8.x2.shared.b16 {%0,%1}, [%2];"
        : "=r"(r[0]), "=r"(r[1]) : "r"(addr));
}
__device__ __forceinline__ void mma16816(float* c, const uint32_t* a, const uint32_t* b) {
    asm volatile("mma.sync.aligned.m16n8k16.row.col.f32.f16.f16.f32 "
        "{%0,%1,%2,%3}, {%4,%5,%6,%7}, {%8,%9}, {%0,%1,%2,%3};"
        : "+f"(c[0]), "+f"(c[1]), "+f"(c[2]), "+f"(c[3])
        : "r"(a[0]), "r"(a[1]), "r"(a[2]), "r"(a[3]), "r"(b[0]), "r"(b[1]));
}

// ================================================================
// flash attention: fp16 single-term QK/PV, l via ones-row MMA column
// grid (32, HEADS, BATCH), 256 threads (8 warps), warp = 16 queries.
// smem: K [32 d][72] halves at 0, V [40][72] halves at 4608 (rows 32-39:
// row32 = ones for the l column, 33-39 zero). Q staged in same buffer first.
// ================================================================
#define SB_K 0
#define SB_V 4608
#define SBUF_BYTES 10368

__global__ __launch_bounds__(256) void attn_mma() {
    __shared__ __align__(16) char sbuf[SBUF_BYTES];
    const int tid = threadIdx.x;
    const int lane = tid & 31;
    const int w = tid >> 5;
    const int h = blockIdx.y, b = blockIdx.z;
    const int qb = blockIdx.x * 128;
    const size_t cbase = ((size_t)b * CC + h * 32) * HW;
    const float* qg = g_q + cbase;
    const __half* kgp = g_kh + cbase;
    const __half* vgp = g_vh + cbase;
    const uint32_t sb = smem_u32(sbuf);

    // ---- stage Q hi (scaled), extract A-fragments ----
    {
        int q = tid >> 1, dh = (tid & 1) * 16;
#pragma unroll
        for (int i = 0; i < 16; i++) {
            float v = qg[(size_t)(dh + i) * HW + qb + q] * SCALE2;
            *(__half*)(sbuf + (q * 40 + dh + i) * 2) = __float2half(v);
        }
    }
    __syncthreads();
    uint32_t qa[2][4];
    {
        int row = w * 16 + (lane & 15);
        int colb = (lane >> 4) * 8;
#pragma unroll
        for (int ks = 0; ks < 2; ks++)
            ldsm4(qa[ks], sb + (row * 40 + ks * 16 + colb) * 2);
    }
    __syncthreads();
    // init V rows 32-39: row 32 = ones (l column), rows 33-39 = zeros
    for (int i = tid; i < 8 * 36; i += 256)
        *(uint32_t*)(sbuf + SB_V + 32 * 72 * 2 + i * 4) = (i < 36) ? 0x3C003C00u : 0u;

    float mrow0 = -1e30f, mrow1 = -1e30f;
    float o[4][4], ol[4];
#pragma unroll
    for (int nt = 0; nt < 4; nt++)
#pragma unroll
        for (int i = 0; i < 4; i++) o[nt][i] = 0.0f;
#pragma unroll
    for (int i = 0; i < 4; i++) ol[i] = 0.0f;

    const int brow = (lane & 7) + ((lane & 16) >> 1);
    const int bcol8 = (lane & 8) ? 8 : 0;
    const int cd = tid >> 3;          // copy: d row 0..31
    const int cj = (tid & 7) * 8;     // copy: j col block

    for (int t = 0; t < 64; t++) {
        const int k0 = t * 64;
        __syncthreads();
        *(uint4*)(sbuf + SB_K + (cd * 72 + cj) * 2) =
            *(const uint4*)(kgp + (size_t)cd * HW + k0 + cj);
        *(uint4*)(sbuf + SB_V + (cd * 72 + cj) * 2) =
            *(const uint4*)(vgp + (size_t)cd * HW + k0 + cj);
        __syncthreads();

        // ---------------- QK^T (K via trans ldsm from [d][j]) ----------------
        float s[8][4];
#pragma unroll
        for (int nt = 0; nt < 8; nt++)
#pragma unroll
            for (int i = 0; i < 4; i++) s[nt][i] = 0.0f;

#pragma unroll
        for (int ks = 0; ks < 2; ks++) {
#pragma unroll
            for (int n0 = 0; n0 < 4; n0++) {
                uint32_t bh[4];
                ldsm4t(bh, sb + SB_K +
                    ((ks * 16 + (lane & 15)) * 72 + n0 * 16 + (lane >> 4) * 8) * 2);
                mma16816(s[n0 * 2], qa[ks], bh);
                mma16816(s[n0 * 2 + 1], qa[ks], bh + 2);
            }
        }

        // ---------------- online softmax (base-2, fp16 exp) ----------------
        float mt0 = -1e30f, mt1 = -1e30f;
#pragma unroll
        for (int nt = 0; nt < 8; nt++) {
            mt0 = fmaxf(mt0, fmaxf(s[nt][0], s[nt][1]));
            mt1 = fmaxf(mt1, fmaxf(s[nt][2], s[nt][3]));
        }
        mt0 = fmaxf(mt0, __shfl_xor_sync(0xffffffffu, mt0, 1));
        mt0 = fmaxf(mt0, __shfl_xor_sync(0xffffffffu, mt0, 2));
        mt1 = fmaxf(mt1, __shfl_xor_sync(0xffffffffu, mt1, 1));
        mt1 = fmaxf(mt1, __shfl_xor_sync(0xffffffffu, mt1, 2));
        float mn0 = fmaxf(mrow0, mt0);
        float mn1 = fmaxf(mrow1, mt1);
        float c0 = ex2f(mrow0 - mn0);
        float c1 = ex2f(mrow1 - mn1);
        mrow0 = mn0; mrow1 = mn1;

        uint32_t pu[8][2];
#pragma unroll
        for (int nt = 0; nt < 8; nt++) {
            pu[nt][0] = ex2_h2(cvt_f16x2(s[nt][1] - mn0, s[nt][0] - mn0));
            pu[nt][1] = ex2_h2(cvt_f16x2(s[nt][3] - mn1, s[nt][2] - mn1));
        }
#pragma unroll
        for (int nt = 0; nt < 4; nt++) {
            o[nt][0] *= c0; o[nt][1] *= c0;
            o[nt][2] *= c1; o[nt][3] *= c1;
        }
        ol[0] *= c0; ol[1] *= c0; ol[2] *= c1; ol[3] *= c1;

        // ---------------- PV (+ ones column -> l) ----------------
#pragma unroll
        for (int ks = 0; ks < 4; ks++) {
            uint32_t ah[4] = { pu[2 * ks][0], pu[2 * ks][1],
                               pu[2 * ks + 1][0], pu[2 * ks + 1][1] };
#pragma unroll
            for (int n0 = 0; n0 < 2; n0++) {
                uint32_t vh[4];
                ldsm4(vh, sb + SB_V + ((n0 * 16 + brow) * 72 + ks * 16 + bcol8) * 2);
                mma16816(o[n0 * 2], ah, vh);
                mma16816(o[n0 * 2 + 1], ah, vh + 2);
            }
            uint32_t b2[2];
            ldsm2(b2, sb + SB_V + ((32 + (lane & 7)) * 72 + ks * 16 + bcol8) * 2);
            mma16816(ol, ah, b2);
        }
    }

    // ---------------- finalize ----------------
    float l0 = __shfl_sync(0xffffffffu, ol[0], lane & 28);
    float l1 = __shfl_sync(0xffffffffu, ol[2], lane & 28);
    float i0 = 1.0f / l0, i1 = 1.0f / l1;
    int pix = qb + w * 16 + (lane >> 2);
#pragma unroll
    for (int nt = 0; nt < 4; nt++) {
        int d = nt * 8 + 2 * (lane & 3);
        g_gd[cbase + (size_t)d * HW + pix] = o[nt][0] * i0;
        g_gd[cbase + (size_t)(d + 1) * HW + pix] = o[nt][1] * i0;
        g_gd[cbase + (size_t)d * HW + pix + 8] = o[nt][2] * i1;
        g_gd[cbase + (size_t)(d + 1) * HW + pix + 8] = o[nt][3] * i1;
    }
}

// ================================================================
// 1x1 conv via HMMA, 32-pixel tiles. Optional fp32 outputs (with resid)
// and/or fp16 outputs. grid (HW/32, BATCH), 256 threads, warp = 16 co.
// NOTE: sbuf must hold the full W staging (128 rows x 136 halves = 34816 B);
// the X tile (17408 B) reuses the same buffer after fragment extraction.
// ================================================================
template<bool DUAL>
__global__ __launch_bounds__(256) void conv1x1_tc(
    const float* __restrict__ X,
    const float* __restrict__ W1, const float* __restrict__ b1, float* __restrict__ Y1,
    const float* __restrict__ W2, const float* __restrict__ b2, float* __restrict__ Y2,
    const float* __restrict__ resid,
    __half* __restrict__ H1, __half* __restrict__ H2) {
    __shared__ __align__(16) char sbuf[34816];
    const int tid = threadIdx.x;
    const int lane = tid & 31;
    const int w = tid >> 5;
    const int bb = blockIdx.y;
    const int p0 = blockIdx.x * 32;
    const uint32_t sb = smem_u32(sbuf);
    const int brow = (lane & 7) + ((lane & 16) >> 1);
    const int bcol8 = (lane & 8) ? 8 : 0;

    uint32_t wa1[8][4], wa2[8][4];
    // ---- stage W1 (hi fp16), extract A fragments ----
    {
#pragma unroll
        for (int i = 0; i < 16; i++) {
            int idx = i * 256 + tid;
            int co = idx >> 5, ci = (idx & 31) * 4;
            float4 v = *(const float4*)(W1 + co * CC + ci);
            __half* d = (__half*)(sbuf) + co * 136 + ci;
            d[0] = __float2half(v.x); d[1] = __float2half(v.y);
            d[2] = __float2half(v.z); d[3] = __float2half(v.w);
        }
        __syncthreads();
        int row = w * 16 + (lane & 15);
        int colb = (lane >> 4) * 8;
#pragma unroll
        for (int ks = 0; ks < 8; ks++)
            ldsm4(wa1[ks], sb + (row * 136 + ks * 16 + colb) * 2);
        __syncthreads();
    }
    if (DUAL) {
#pragma unroll
        for (int i = 0; i < 16; i++) {
            int idx = i * 256 + tid;
            int co = idx >> 5, ci = (idx & 31) * 4;
            float4 v = *(const float4*)(W2 + co * CC + ci);
            __half* d = (__half*)(sbuf) + co * 136 + ci;
            d[0] = __float2half(v.x); d[1] = __float2half(v.y);
            d[2] = __float2half(v.z); d[3] = __float2half(v.w);
        }
        __syncthreads();
        int row = w * 16 + (lane & 15);
        int colb = (lane >> 4) * 8;
#pragma unroll
        for (int ks = 0; ks < 8; ks++)
            ldsm4(wa2[ks], sb + (row * 136 + ks * 16 + colb) * 2);
        __syncthreads();
    }

    // ---- stage X tile: [px 32][ci 136] hi at 0, lo at +8704B ----
#pragma unroll
    for (int i = 0; i < 4; i++) {
        int idx = i * 256 + tid;
        int ci = idx >> 3, px = (idx & 7) * 4;
        float4 v = *(const float4*)(X + ((size_t)bb * CC + ci) * HW + p0 + px);
        float vv[4] = { v.x, v.y, v.z, v.w };
#pragma unroll
        for (int j = 0; j < 4; j++) {
            __half hv = __float2half(vv[j]);
            *((__half*)(sbuf) + (px + j) * 136 + ci) = hv;
            *((__half*)(sbuf + 8704) + (px + j) * 136 + ci) =
                __float2half(vv[j] - __half2float(hv));
        }
    }
    __syncthreads();

    // ---- MMA mainloop ----
    float acc1[4][4], acc2[4][4];
#pragma unroll
    for (int nt = 0; nt < 4; nt++)
#pragma unroll
        for (int i = 0; i < 4; i++) { acc1[nt][i] = 0.0f; acc2[nt][i] = 0.0f; }

#pragma unroll
    for (int ks = 0; ks < 8; ks++) {
#pragma unroll
        for (int n0 = 0; n0 < 2; n0++) {
            uint32_t bh[4], bl[4];
            uint32_t a = sb + ((n0 * 16 + brow) * 136 + ks * 16 + bcol8) * 2;
            ldsm4(bh, a);
            ldsm4(bl, a + 8704);
            mma16816(acc1[n0 * 2], wa1[ks], bh);
            mma16816(acc1[n0 * 2], wa1[ks], bl);
            mma16816(acc1[n0 * 2 + 1], wa1[ks], bh + 2);
            mma16816(acc1[n0 * 2 + 1], wa1[ks], bl + 2);
            if (DUAL) {
                mma16816(acc2[n0 * 2], wa2[ks], bh);
                mma16816(acc2[n0 * 2], wa2[ks], bl);
                mma16816(acc2[n0 * 2 + 1], wa2[ks], bh + 2);
                mma16816(acc2[n0 * 2 + 1], wa2[ks], bl + 2);
            }
        }
    }

    // ---- epilogue ----
    int coA = w * 16 + (lane >> 2);
    int coB = coA + 8;
    float b1A = b1[coA], b1B = b1[coB];
    float b2A = 0.0f, b2B = 0.0f;
    if (DUAL) { b2A = b2[coA]; b2B = b2[coB]; }
    size_t baseA = ((size_t)bb * CC + coA) * HW + p0;
    size_t baseB = ((size_t)bb * CC + coB) * HW + p0;
#pragma unroll
    for (int nt = 0; nt < 4; nt++) {
        int px = nt * 8 + 2 * (lane & 3);
        float vA0 = acc1[nt][0] + b1A, vA1 = acc1[nt][1] + b1A;
        float vB0 = acc1[nt][2] + b1B, vB1 = acc1[nt][3] + b1B;
        if (resid != nullptr) {
            float2 rA = *(const float2*)(resid + baseA + px);
            float2 rB = *(const float2*)(resid + baseB + px);
            vA0 += rA.x; vA1 += rA.y; vB0 += rB.x; vB1 += rB.y;
        }
        if (Y1 != nullptr) {
            *(float2*)(Y1 + baseA + px) = make_float2(vA0, vA1);
            *(float2*)(Y1 + baseB + px) = make_float2(vB0, vB1);
        }
        if (H1 != nullptr) {
            *(uint32_t*)(H1 + baseA + px) = cvt_f16x2(vA1, vA0);
            *(uint32_t*)(H1 + baseB + px) = cvt_f16x2(vB1, vB0);
        }
        if (DUAL) {
            float uA0 = acc2[nt][0] + b2A, uA1 = acc2[nt][1] + b2A;
            float uB0 = acc2[nt][2] + b2B, uB1 = acc2[nt][3] + b2B;
            if (Y2 != nullptr) {
                *(float2*)(Y2 + baseA + px) = make_float2(uA0, uA1);
                *(float2*)(Y2 + baseB + px) = make_float2(uB0, uB1);
            }
            if (H2 != nullptr) {
                *(uint32_t*)(H2 + baseA + px) = cvt_f16x2(uA1, uA0);
                *(uint32_t*)(H2 + baseB + px) = cvt_f16x2(uB1, uB0);
            }
        }
    }
}

// ================= mask conv 1 =================
__global__ void mask_conv1(const float* __restrict__ seg,
                           const float* __restrict__ Wm1,
                           const float* __restrict__ bm1) {
    int idx = blockIdx.x * 256 + threadIdx.x;
    if (idx >= BATCH * 32 * HW) return;
    int x = idx & 63, y = (idx >> 6) & 63, c = (idx >> 12) & 31, b = idx >> 17;
    const float* w = Wm1 + c * 9;
    const float* s = seg + b * HW;
    float acc = bm1[c];
#pragma unroll
    for (int dy = 0; dy < 3; dy++) {
        int yy = y + dy - 1;
        if (yy < 0 || yy >= 64) continue;
#pragma unroll
        for (int dx = 0; dx < 3; dx++) {
            int xx = x + dx - 1;
            if (xx < 0 || xx >= 64) continue;
            acc += w[dy * 3 + dx] * s[yy * 64 + xx];
        }
    }
    g_m1[idx] = fmaxf(acc, 0.0f);
}

// ================= mask conv 2 =================
__global__ __launch_bounds__(256) void mask_conv2(const float* __restrict__ Wm2,
                                                  const float* __restrict__ bm2) {
    int y = blockIdx.x, b = blockIdx.y;
    __shared__ float sm[32][3][66];
    for (int i = threadIdx.x; i < 32 * 3 * 66; i += 256) {
        int ci = i / 198, rem = i % 198, r = rem / 66, x = rem % 66;
        int yy = y + r - 1, xx = x - 1;
        float v = 0.0f;
        if (yy >= 0 && yy < 64 && xx >= 0 && xx < 64)
            v = g_m1[(((size_t)b * 32 + ci) * 64 + yy) * 64 + xx];
        sm[ci][r][x] = v;
    }
    __syncthreads();
    int co = threadIdx.x >> 1;
    int xh = (threadIdx.x & 1) * 32;
    float acc[32];
    float bb = bm2[co];
#pragma unroll
    for (int px = 0; px < 32; px++) acc[px] = bb;
    const float* w = Wm2 + co * 288;
    for (int ci = 0; ci < 32; ci++) {
#pragma unroll
        for (int r = 0; r < 3; r++) {
            const float* row = &sm[ci][r][xh];
            float rv[34];
#pragma unroll
            for (int t = 0; t < 34; t++) rv[t] = row[t];
#pragma unroll
            for (int dx = 0; dx < 3; dx++) {
                float wv = w[(ci * 3 + r) * 3 + dx];
#pragma unroll
                for (int px = 0; px < 32; px++) acc[px] += wv * rv[px + dx];
            }
        }
    }
    float* out = g_mf + ((size_t)b * CC + co) * HW + y * 64 + xh;
#pragma unroll
    for (int px = 0; px < 32; px++) out[px] = acc[px];
}

// ---------------- launch ----------------
extern "C" void kernel_launch(void* const* d_in, const int* in_sizes, int n_in,
                              void* d_out, int out_size) {
    const float* sr  = (const float*)d_in[0];
    const float* seg = (const float*)d_in[1];
    const float* Wq  = (const float*)d_in[2];
    const float* bq  = (const float*)d_in[3];
    const float* Wm1 = (const float*)d_in[4];
    const float* bm1 = (const float*)d_in[5];
    const float* Wm2 = (const float*)d_in[6];
    const float* bm2 = (const float*)d_in[7];
    const float* Wk  = (const float*)d_in[8];
    const float* bk  = (const float*)d_in[9];
    const float* Wv  = (const float*)d_in[10];
    const float* bv  = (const float*)d_in[11];
    const float* Wo  = (const float*)d_in[12];
    const float* bo  = (const float*)d_in[13];
    float* out = (float*)d_out;

    float *pmf, *pq, *pg;
    __half *pkh, *pvh;
    cudaGetSymbolAddress((void**)&pmf, g_mf);
    cudaGetSymbolAddress((void**)&pq, g_q);
    cudaGetSymbolAddress((void**)&pg, g_gd);
    cudaGetSymbolAddress((void**)&pkh, g_kh);
    cudaGetSymbolAddress((void**)&pvh, g_vh);

    mask_conv1<<<(BATCH * 32 * HW + 255) / 256, 256>>>(seg, Wm1, bm1);
    mask_conv2<<<dim3(64, BATCH), 256>>>(Wm2, bm2);
    conv1x1_tc<false><<<dim3(HW / 32, BATCH), 256>>>(
        sr, Wq, bq, pq, nullptr, nullptr, nullptr, nullptr, nullptr, nullptr);
    conv1x1_tc<true><<<dim3(HW / 32, BATCH), 256>>>(
        pmf, Wk, bk, nullptr, Wv, bv, nullptr, nullptr, pkh, pvh);
    attn_mma<<<dim3(32, HEADS, BATCH), 256>>>();
    conv1x1_tc<false><<<dim3(HW / 32, BATCH), 256>>>(
        pg, Wo, bo, out, nullptr, nullptr, nullptr, sr, nullptr, nullptr);
}

// round 7
// speedup vs baseline: 5.2408x; 1.0568x over previous
#include <cuda_runtime.h>
#include <cuda_fp16.h>
#include <cstdint>
#include <cstddef>

#define BATCH 2
#define CC 128
#define HW 4096
#define HEADS 4
// 32^-0.5 * log2(e): softmax in base-2
#define SCALE2 0.25500526764086436f

// ---------------- scratch ----------------
__device__ float g_m1[BATCH * 32 * HW];
__device__ float g_mf[BATCH * CC * HW];
__device__ float g_q[BATCH * CC * HW];
__device__ float g_gd[BATCH * CC * HW];
__device__ __align__(16) __half g_kh[BATCH * CC * HW];
__device__ __align__(16) __half g_vh[BATCH * CC * HW];

// ---------------- helpers ----------------
__device__ __forceinline__ uint32_t smem_u32(const void* p) {
    uint32_t a;
    asm("{ .reg .u64 t; cvta.to.shared.u64 t, %1; cvt.u32.u64 %0, t; }" : "=r"(a) : "l"(p));
    return a;
}
__device__ __forceinline__ float ex2f(float x) {
    float r; asm("ex2.approx.f32 %0, %1;" : "=f"(r) : "f"(x)); return r;
}
// pack two f32 -> f16x2 (first operand to upper half, second to lower)
__device__ __forceinline__ uint32_t cvt_f16x2(float hi, float lo) {
    uint32_t r; asm("cvt.rn.f16x2.f32 %0, %1, %2;" : "=r"(r) : "f"(hi), "f"(lo)); return r;
}
__device__ __forceinline__ uint32_t ex2_h2(uint32_t a) {
    uint32_t r; asm("ex2.approx.f16x2 %0, %1;" : "=r"(r) : "r"(a)); return r;
}
__device__ __forceinline__ void ldsm4(uint32_t* r, uint32_t addr) {
    asm volatile("ldmatrix.sync.aligned.m8n8.x4.shared.b16 {%0,%1,%2,%3}, [%4];"
        : "=r"(r[0]), "=r"(r[1]), "=r"(r[2]), "=r"(r[3]) : "r"(addr));
}
__device__ __forceinline__ void ldsm4t(uint32_t* r, uint32_t addr) {
    asm volatile("ldmatrix.sync.aligned.m8n8.x4.trans.shared.b16 {%0,%1,%2,%3}, [%4];"
        : "=r"(r[0]), "=r"(r[1]), "=r"(r[2]), "=r"(r[3]) : "r"(addr));
}
__device__ __forceinline__ void ldsm2(uint32_t* r, uint32_t addr) {
    asm volatile("ldmatrix.sync.aligned.m8n8.x2.shared.b16 {%0,%1}, [%2];"
        : "=r"(r[0]), "=r"(r[1]) : "r"(addr));
}
__device__ __forceinline__ void mma16816(float* c, const uint32_t* a, const uint32_t* b) {
    asm volatile("mma.sync.aligned.m16n8k16.row.col.f32.f16.f16.f32 "
        "{%0,%1,%2,%3}, {%4,%5,%6,%7}, {%8,%9}, {%0,%1,%2,%3};"
        : "+f"(c[0]), "+f"(c[1]), "+f"(c[2]), "+f"(c[3])
        : "r"(a[0]), "r"(a[1]), "r"(a[2]), "r"(a[3]), "r"(b[0]), "r"(b[1]));
}
__device__ __forceinline__ void cp16(uint32_t saddr, const void* g) {
    asm volatile("cp.async.cg.shared.global [%0], [%1], 16;" :: "r"(saddr), "l"(g));
}
#define CP_COMMIT() asm volatile("cp.async.commit_group;" ::: "memory")
#define CP_WAIT1()  asm volatile("cp.async.wait_group 1;" ::: "memory")

// ================================================================
// flash attention: fp16 single-term QK/PV, l via ones-row MMA column,
// double-buffered cp.async K/V pipeline.
// grid (32, HEADS, BATCH), 256 threads (8 warps), warp = 16 queries.
// stage layout (10368 B): K [32 d][72] at +0, V [40][72] at +4608
// (V rows 32-39: row32 = ones for the l column, 33-39 zero).
// Q staged into stage-0 region before the pipeline starts.
// ================================================================
#define SB_V 4608
#define STAGE 10368
#define SBUF_BYTES (2 * STAGE)

__global__ __launch_bounds__(256) void attn_mma() {
    __shared__ __align__(16) char sbuf[SBUF_BYTES];
    const int tid = threadIdx.x;
    const int lane = tid & 31;
    const int w = tid >> 5;
    const int h = blockIdx.y, b = blockIdx.z;
    const int qb = blockIdx.x * 128;
    const size_t cbase = ((size_t)b * CC + h * 32) * HW;
    const float* qg = g_q + cbase;
    const __half* kgp = g_kh + cbase;
    const __half* vgp = g_vh + cbase;
    const uint32_t sb = smem_u32(sbuf);

    // ---- stage Q hi (scaled), extract A-fragments ----
    {
        int q = tid >> 1, dh = (tid & 1) * 16;
#pragma unroll
        for (int i = 0; i < 16; i++) {
            float v = qg[(size_t)(dh + i) * HW + qb + q] * SCALE2;
            *(__half*)(sbuf + (q * 40 + dh + i) * 2) = __float2half(v);
        }
    }
    __syncthreads();
    uint32_t qa[2][4];
    {
        int row = w * 16 + (lane & 15);
        int colb = (lane >> 4) * 8;
#pragma unroll
        for (int ks = 0; ks < 2; ks++)
            ldsm4(qa[ks], sb + (row * 40 + ks * 16 + colb) * 2);
    }
    __syncthreads();   // Q region free; safe to overwrite with K/V stages

    // init V rows 32-39 in BOTH stages: row 32 = ones, rows 33-39 = zero
    for (int i = tid; i < 8 * 36; i += 256) {
        uint32_t v = (i < 36) ? 0x3C003C00u : 0u;
        *(uint32_t*)(sbuf + SB_V + 32 * 144 + i * 4) = v;
        *(uint32_t*)(sbuf + STAGE + SB_V + 32 * 144 + i * 4) = v;
    }

    const int cd = tid >> 3;          // copy: d row 0..31
    const int cj = (tid & 7) * 8;     // copy: j col block
    const uint32_t cpK = sb + (cd * 72 + cj) * 2;
    const uint32_t cpV = sb + SB_V + (cd * 72 + cj) * 2;
    const __half* gK = kgp + (size_t)cd * HW + cj;
    const __half* gV = vgp + (size_t)cd * HW + cj;

    // prologue: prefetch tiles 0 and 1
    cp16(cpK, gK);
    cp16(cpV, gV);
    CP_COMMIT();
    cp16(cpK + STAGE, gK + 64);
    cp16(cpV + STAGE, gV + 64);
    CP_COMMIT();

    float mrow0 = -1e30f, mrow1 = -1e30f;
    float o[4][4], ol[4];
#pragma unroll
    for (int nt = 0; nt < 4; nt++)
#pragma unroll
        for (int i = 0; i < 4; i++) o[nt][i] = 0.0f;
#pragma unroll
    for (int i = 0; i < 4; i++) ol[i] = 0.0f;

    const int brow = (lane & 7) + ((lane & 16) >> 1);
    const int bcol8 = (lane & 8) ? 8 : 0;

    for (int t = 0; t < 64; t++) {
        const uint32_t base = sb + (t & 1) * STAGE;
        CP_WAIT1();
        __syncthreads();

        // ---------------- QK^T (K via trans ldsm from [d][j]) ----------------
        float s[8][4];
#pragma unroll
        for (int nt = 0; nt < 8; nt++)
#pragma unroll
            for (int i = 0; i < 4; i++) s[nt][i] = 0.0f;

#pragma unroll
        for (int ks = 0; ks < 2; ks++) {
#pragma unroll
            for (int n0 = 0; n0 < 4; n0++) {
                uint32_t bh[4];
                ldsm4t(bh, base +
                    ((ks * 16 + (lane & 15)) * 72 + n0 * 16 + (lane >> 4) * 8) * 2);
                mma16816(s[n0 * 2], qa[ks], bh);
                mma16816(s[n0 * 2 + 1], qa[ks], bh + 2);
            }
        }

        // ---------------- online softmax (base-2, fp16 exp) ----------------
        float mt0 = -1e30f, mt1 = -1e30f;
#pragma unroll
        for (int nt = 0; nt < 8; nt++) {
            mt0 = fmaxf(mt0, fmaxf(s[nt][0], s[nt][1]));
            mt1 = fmaxf(mt1, fmaxf(s[nt][2], s[nt][3]));
        }
        mt0 = fmaxf(mt0, __shfl_xor_sync(0xffffffffu, mt0, 1));
        mt0 = fmaxf(mt0, __shfl_xor_sync(0xffffffffu, mt0, 2));
        mt1 = fmaxf(mt1, __shfl_xor_sync(0xffffffffu, mt1, 1));
        mt1 = fmaxf(mt1, __shfl_xor_sync(0xffffffffu, mt1, 2));
        float mn0 = fmaxf(mrow0, mt0);
        float mn1 = fmaxf(mrow1, mt1);
        float c0 = ex2f(mrow0 - mn0);
        float c1 = ex2f(mrow1 - mn1);
        mrow0 = mn0; mrow1 = mn1;

        uint32_t pu[8][2];
#pragma unroll
        for (int nt = 0; nt < 8; nt++) {
            pu[nt][0] = ex2_h2(cvt_f16x2(s[nt][1] - mn0, s[nt][0] - mn0));
            pu[nt][1] = ex2_h2(cvt_f16x2(s[nt][3] - mn1, s[nt][2] - mn1));
        }
#pragma unroll
        for (int nt = 0; nt < 4; nt++) {
            o[nt][0] *= c0; o[nt][1] *= c0;
            o[nt][2] *= c1; o[nt][3] *= c1;
        }
        ol[0] *= c0; ol[1] *= c0; ol[2] *= c1; ol[3] *= c1;

        // ---------------- PV (+ ones column -> l) ----------------
#pragma unroll
        for (int ks = 0; ks < 4; ks++) {
            uint32_t ah[4] = { pu[2 * ks][0], pu[2 * ks][1],
                               pu[2 * ks + 1][0], pu[2 * ks + 1][1] };
#pragma unroll
            for (int n0 = 0; n0 < 2; n0++) {
                uint32_t vh[4];
                ldsm4(vh, base + SB_V + ((n0 * 16 + brow) * 72 + ks * 16 + bcol8) * 2);
                mma16816(o[n0 * 2], ah, vh);
                mma16816(o[n0 * 2 + 1], ah, vh + 2);
            }
            uint32_t b2[2];
            ldsm2(b2, base + SB_V + ((32 + (lane & 7)) * 72 + ks * 16 + bcol8) * 2);
            mma16816(ol, ah, b2);
        }

        __syncthreads();   // all reads of this stage done
        int tn = t + 2;
        if (tn < 64) {
            cp16(cpK + (t & 1) * STAGE, gK + tn * 64);
            cp16(cpV + (t & 1) * STAGE, gV + tn * 64);
        }
        CP_COMMIT();       // always commit so wait_group counting stays uniform
    }

    // ---------------- finalize ----------------
    float l0 = __shfl_sync(0xffffffffu, ol[0], lane & 28);
    float l1 = __shfl_sync(0xffffffffu, ol[2], lane & 28);
    float i0 = 1.0f / l0, i1 = 1.0f / l1;
    int pix = qb + w * 16 + (lane >> 2);
#pragma unroll
    for (int nt = 0; nt < 4; nt++) {
        int d = nt * 8 + 2 * (lane & 3);
        g_gd[cbase + (size_t)d * HW + pix] = o[nt][0] * i0;
        g_gd[cbase + (size_t)(d + 1) * HW + pix] = o[nt][1] * i0;
        g_gd[cbase + (size_t)d * HW + pix + 8] = o[nt][2] * i1;
        g_gd[cbase + (size_t)(d + 1) * HW + pix + 8] = o[nt][3] * i1;
    }
}

// ================================================================
// 1x1 conv via HMMA, 32-pixel tiles. X global loads hoisted above the
// W staging phases so their latency overlaps fragment extraction.
// grid (HW/32, BATCH), 256 threads, warp = 16 co.
// ================================================================
template<bool DUAL>
__global__ __launch_bounds__(256) void conv1x1_tc(
    const float* __restrict__ X,
    const float* __restrict__ W1, const float* __restrict__ b1, float* __restrict__ Y1,
    const float* __restrict__ W2, const float* __restrict__ b2, float* __restrict__ Y2,
    const float* __restrict__ resid,
    __half* __restrict__ H1, __half* __restrict__ H2) {
    __shared__ __align__(16) char sbuf[34816];
    const int tid = threadIdx.x;
    const int lane = tid & 31;
    const int w = tid >> 5;
    const int bb = blockIdx.y;
    const int p0 = blockIdx.x * 32;
    const uint32_t sb = smem_u32(sbuf);
    const int brow = (lane & 7) + ((lane & 16) >> 1);
    const int bcol8 = (lane & 8) ? 8 : 0;

    // ---- issue X loads FIRST (latency hidden behind W staging) ----
    float4 xreg[4];
#pragma unroll
    for (int i = 0; i < 4; i++) {
        int idx = i * 256 + tid;
        int ci = idx >> 3, px = (idx & 7) * 4;
        xreg[i] = *(const float4*)(X + ((size_t)bb * CC + ci) * HW + p0 + px);
    }

    uint32_t wa1[8][4], wa2[8][4];
    // ---- stage W1 (hi fp16), extract A fragments ----
    {
#pragma unroll
        for (int i = 0; i < 16; i++) {
            int idx = i * 256 + tid;
            int co = idx >> 5, ci = (idx & 31) * 4;
            float4 v = *(const float4*)(W1 + co * CC + ci);
            __half* d = (__half*)(sbuf) + co * 136 + ci;
            d[0] = __float2half(v.x); d[1] = __float2half(v.y);
            d[2] = __float2half(v.z); d[3] = __float2half(v.w);
        }
        __syncthreads();
        int row = w * 16 + (lane & 15);
        int colb = (lane >> 4) * 8;
#pragma unroll
        for (int ks = 0; ks < 8; ks++)
            ldsm4(wa1[ks], sb + (row * 136 + ks * 16 + colb) * 2);
        __syncthreads();
    }
    if (DUAL) {
#pragma unroll
        for (int i = 0; i < 16; i++) {
            int idx = i * 256 + tid;
            int co = idx >> 5, ci = (idx & 31) * 4;
            float4 v = *(const float4*)(W2 + co * CC + ci);
            __half* d = (__half*)(sbuf) + co * 136 + ci;
            d[0] = __float2half(v.x); d[1] = __float2half(v.y);
            d[2] = __float2half(v.z); d[3] = __float2half(v.w);
        }
        __syncthreads();
        int row = w * 16 + (lane & 15);
        int colb = (lane >> 4) * 8;
#pragma unroll
        for (int ks = 0; ks < 8; ks++)
            ldsm4(wa2[ks], sb + (row * 136 + ks * 16 + colb) * 2);
        __syncthreads();
    }

    // ---- stage X tile from regs: [px 32][ci 136] hi at 0, lo at +8704B ----
#pragma unroll
    for (int i = 0; i < 4; i++) {
        int idx = i * 256 + tid;
        int ci = idx >> 3, px = (idx & 7) * 4;
        float vv[4] = { xreg[i].x, xreg[i].y, xreg[i].z, xreg[i].w };
#pragma unroll
        for (int j = 0; j < 4; j++) {
            __half hv = __float2half(vv[j]);
            *((__half*)(sbuf) + (px + j) * 136 + ci) = hv;
            *((__half*)(sbuf + 8704) + (px + j) * 136 + ci) =
                __float2half(vv[j] - __half2float(hv));
        }
    }
    __syncthreads();

    // ---- MMA mainloop ----
    float acc1[4][4], acc2[4][4];
#pragma unroll
    for (int nt = 0; nt < 4; nt++)
#pragma unroll
        for (int i = 0; i < 4; i++) { acc1[nt][i] = 0.0f; acc2[nt][i] = 0.0f; }

#pragma unroll
    for (int ks = 0; ks < 8; ks++) {
#pragma unroll
        for (int n0 = 0; n0 < 2; n0++) {
            uint32_t bh[4], bl[4];
            uint32_t a = sb + ((n0 * 16 + brow) * 136 + ks * 16 + bcol8) * 2;
            ldsm4(bh, a);
            ldsm4(bl, a + 8704);
            mma16816(acc1[n0 * 2], wa1[ks], bh);
            mma16816(acc1[n0 * 2], wa1[ks], bl);
            mma16816(acc1[n0 * 2 + 1], wa1[ks], bh + 2);
            mma16816(acc1[n0 * 2 + 1], wa1[ks], bl + 2);
            if (DUAL) {
                mma16816(acc2[n0 * 2], wa2[ks], bh);
                mma16816(acc2[n0 * 2], wa2[ks], bl);
                mma16816(acc2[n0 * 2 + 1], wa2[ks], bh + 2);
                mma16816(acc2[n0 * 2 + 1], wa2[ks], bl + 2);
            }
        }
    }

    // ---- epilogue ----
    int coA = w * 16 + (lane >> 2);
    int coB = coA + 8;
    float b1A = b1[coA], b1B = b1[coB];
    float b2A = 0.0f, b2B = 0.0f;
    if (DUAL) { b2A = b2[coA]; b2B = b2[coB]; }
    size_t baseA = ((size_t)bb * CC + coA) * HW + p0;
    size_t baseB = ((size_t)bb * CC + coB) * HW + p0;
#pragma unroll
    for (int nt = 0; nt < 4; nt++) {
        int px = nt * 8 + 2 * (lane & 3);
        float vA0 = acc1[nt][0] + b1A, vA1 = acc1[nt][1] + b1A;
        float vB0 = acc1[nt][2] + b1B, vB1 = acc1[nt][3] + b1B;
        if (resid != nullptr) {
            float2 rA = *(const float2*)(resid + baseA + px);
            float2 rB = *(const float2*)(resid + baseB + px);
            vA0 += rA.x; vA1 += rA.y; vB0 += rB.x; vB1 += rB.y;
        }
        if (Y1 != nullptr) {
            *(float2*)(Y1 + baseA + px) = make_float2(vA0, vA1);
            *(float2*)(Y1 + baseB + px) = make_float2(vB0, vB1);
        }
        if (H1 != nullptr) {
            *(uint32_t*)(H1 + baseA + px) = cvt_f16x2(vA1, vA0);
            *(uint32_t*)(H1 + baseB + px) = cvt_f16x2(vB1, vB0);
        }
        if (DUAL) {
            float uA0 = acc2[nt][0] + b2A, uA1 = acc2[nt][1] + b2A;
            float uB0 = acc2[nt][2] + b2B, uB1 = acc2[nt][3] + b2B;
            if (Y2 != nullptr) {
                *(float2*)(Y2 + baseA + px) = make_float2(uA0, uA1);
                *(float2*)(Y2 + baseB + px) = make_float2(uB0, uB1);
            }
            if (H2 != nullptr) {
                *(uint32_t*)(H2 + baseA + px) = cvt_f16x2(uA1, uA0);
                *(uint32_t*)(H2 + baseB + px) = cvt_f16x2(uB1, uB0);
            }
        }
    }
}

// ================= mask conv 1 =================
__global__ void mask_conv1(const float* __restrict__ seg,
                           const float* __restrict__ Wm1,
                           const float* __restrict__ bm1) {
    int idx = blockIdx.x * 256 + threadIdx.x;
    if (idx >= BATCH * 32 * HW) return;
    int x = idx & 63, y = (idx >> 6) & 63, c = (idx >> 12) & 31, b = idx >> 17;
    const float* w = Wm1 + c * 9;
    const float* s = seg + b * HW;
    float acc = bm1[c];
#pragma unroll
    for (int dy = 0; dy < 3; dy++) {
        int yy = y + dy - 1;
        if (yy < 0 || yy >= 64) continue;
#pragma unroll
        for (int dx = 0; dx < 3; dx++) {
            int xx = x + dx - 1;
            if (xx < 0 || xx >= 64) continue;
            acc += w[dy * 3 + dx] * s[yy * 64 + xx];
        }
    }
    g_m1[idx] = fmaxf(acc, 0.0f);
}

// ================= mask conv 2 =================
__global__ __launch_bounds__(256) void mask_conv2(const float* __restrict__ Wm2,
                                                  const float* __restrict__ bm2) {
    int y = blockIdx.x, b = blockIdx.y;
    __shared__ float sm[32][3][66];
    for (int i = threadIdx.x; i < 32 * 3 * 66; i += 256) {
        int ci = i / 198, rem = i % 198, r = rem / 66, x = rem % 66;
        int yy = y + r - 1, xx = x - 1;
        float v = 0.0f;
        if (yy >= 0 && yy < 64 && xx >= 0 && xx < 64)
            v = g_m1[(((size_t)b * 32 + ci) * 64 + yy) * 64 + xx];
        sm[ci][r][x] = v;
    }
    __syncthreads();
    int co = threadIdx.x >> 1;
    int xh = (threadIdx.x & 1) * 32;
    float acc[32];
    float bb = bm2[co];
#pragma unroll
    for (int px = 0; px < 32; px++) acc[px] = bb;
    const float* w = Wm2 + co * 288;
    for (int ci = 0; ci < 32; ci++) {
#pragma unroll
        for (int r = 0; r < 3; r++) {
            const float* row = &sm[ci][r][xh];
            float rv[34];
#pragma unroll
            for (int t = 0; t < 34; t++) rv[t] = row[t];
#pragma unroll
            for (int dx = 0; dx < 3; dx++) {
                float wv = w[(ci * 3 + r) * 3 + dx];
#pragma unroll
                for (int px = 0; px < 32; px++) acc[px] += wv * rv[px + dx];
            }
        }
    }
    float* out = g_mf + ((size_t)b * CC + co) * HW + y * 64 + xh;
#pragma unroll
    for (int px = 0; px < 32; px++) out[px] = acc[px];
}

// ---------------- launch ----------------
extern "C" void kernel_launch(void* const* d_in, const int* in_sizes, int n_in,
                              void* d_out, int out_size) {
    const float* sr  = (const float*)d_in[0];
    const float* seg = (const float*)d_in[1];
    const float* Wq  = (const float*)d_in[2];
    const float* bq  = (const float*)d_in[3];
    const float* Wm1 = (const float*)d_in[4];
    const float* bm1 = (const float*)d_in[5];
    const float* Wm2 = (const float*)d_in[6];
    const float* bm2 = (const float*)d_in[7];
    const float* Wk  = (const float*)d_in[8];
    const float* bk  = (const float*)d_in[9];
    const float* Wv  = (const float*)d_in[10];
    const float* bv  = (const float*)d_in[11];
    const float* Wo  = (const float*)d_in[12];
    const float* bo  = (const float*)d_in[13];
    float* out = (float*)d_out;

    float *pmf, *pq, *pg;
    __half *pkh, *pvh;
    cudaGetSymbolAddress((void**)&pmf, g_mf);
    cudaGetSymbolAddress((void**)&pq, g_q);
    cudaGetSymbolAddress((void**)&pg, g_gd);
    cudaGetSymbolAddress((void**)&pkh, g_kh);
    cudaGetSymbolAddress((void**)&pvh, g_vh);

    mask_conv1<<<(BATCH * 32 * HW + 255) / 256, 256>>>(seg, Wm1, bm1);
    mask_conv2<<<dim3(64, BATCH), 256>>>(Wm2, bm2);
    conv1x1_tc<false><<<dim3(HW / 32, BATCH), 256>>>(
        sr, Wq, bq, pq, nullptr, nullptr, nullptr, nullptr, nullptr, nullptr);
    conv1x1_tc<true><<<dim3(HW / 32, BATCH), 256>>>(
        pmf, Wk, bk, nullptr, Wv, bv, nullptr, nullptr, pkh, pvh);
    attn_mma<<<dim3(32, HEADS, BATCH), 256>>>();
    conv1x1_tc<false><<<dim3(HW / 32, BATCH), 256>>>(
        pg, Wo, bo, out, nullptr, nullptr, nullptr, sr, nullptr, nullptr);
}

// round 8
// speedup vs baseline: 5.2978x; 1.0109x over previous
#include <cuda_runtime.h>
#include <cuda_fp16.h>
#include <cstdint>
#include <cstddef>

#define BATCH 2
#define CC 128
#define HW 4096
#define HEADS 4
// 32^-0.5 * log2(e): softmax in base-2
#define SCALE2 0.25500526764086436f

// ---------------- scratch ----------------
__device__ float g_mf[BATCH * CC * HW];
__device__ float g_q[BATCH * CC * HW];
__device__ float g_gd[BATCH * CC * HW];
__device__ __align__(16) __half g_kh[BATCH * CC * HW];
__device__ __align__(16) __half g_vh[BATCH * CC * HW];

// ---------------- helpers ----------------
__device__ __forceinline__ uint32_t smem_u32(const void* p) {
    uint32_t a;
    asm("{ .reg .u64 t; cvta.to.shared.u64 t, %1; cvt.u32.u64 %0, t; }" : "=r"(a) : "l"(p));
    return a;
}
__device__ __forceinline__ float ex2f(float x) {
    float r; asm("ex2.approx.f32 %0, %1;" : "=f"(r) : "f"(x)); return r;
}
__device__ __forceinline__ uint32_t cvt_f16x2(float hi, float lo) {
    uint32_t r; asm("cvt.rn.f16x2.f32 %0, %1, %2;" : "=r"(r) : "f"(hi), "f"(lo)); return r;
}
__device__ __forceinline__ uint32_t ex2_h2(uint32_t a) {
    uint32_t r; asm("ex2.approx.f16x2 %0, %1;" : "=r"(r) : "r"(a)); return r;
}
__device__ __forceinline__ void ldsm4(uint32_t* r, uint32_t addr) {
    asm volatile("ldmatrix.sync.aligned.m8n8.x4.shared.b16 {%0,%1,%2,%3}, [%4];"
        : "=r"(r[0]), "=r"(r[1]), "=r"(r[2]), "=r"(r[3]) : "r"(addr));
}
__device__ __forceinline__ void ldsm4t(uint32_t* r, uint32_t addr) {
    asm volatile("ldmatrix.sync.aligned.m8n8.x4.trans.shared.b16 {%0,%1,%2,%3}, [%4];"
        : "=r"(r[0]), "=r"(r[1]), "=r"(r[2]), "=r"(r[3]) : "r"(addr));
}
__device__ __forceinline__ void ldsm2(uint32_t* r, uint32_t addr) {
    asm volatile("ldmatrix.sync.aligned.m8n8.x2.shared.b16 {%0,%1}, [%2];"
        : "=r"(r[0]), "=r"(r[1]) : "r"(addr));
}
__device__ __forceinline__ void mma16816(float* c, const uint32_t* a, const uint32_t* b) {
    asm volatile("mma.sync.aligned.m16n8k16.row.col.f32.f16.f16.f32 "
        "{%0,%1,%2,%3}, {%4,%5,%6,%7}, {%8,%9}, {%0,%1,%2,%3};"
        : "+f"(c[0]), "+f"(c[1]), "+f"(c[2]), "+f"(c[3])
        : "r"(a[0]), "r"(a[1]), "r"(a[2]), "r"(a[3]), "r"(b[0]), "r"(b[1]));
}
__device__ __forceinline__ void cp16(uint32_t saddr, const void* g) {
    asm volatile("cp.async.cg.shared.global [%0], [%1], 16;" :: "r"(saddr), "l"(g));
}
#define CP_COMMIT() asm volatile("cp.async.commit_group;" ::: "memory")
#define CP_WAIT1()  asm volatile("cp.async.wait_group 1;" ::: "memory")

// ================================================================
// flash attention: fp16 QK/PV, l via ones-row MMA column.
// 128-key double-buffered cp.async stages; compute in two 64-key halves.
// grid (32, HEADS, BATCH), 256 threads (8 warps), warp = 16 queries.
// stage (19584 B): K [32 d][136 j] at +0, V [40][136] at +8704
// (V rows 32-39: row 32 = ones for the l column, 33-39 zero).
// ================================================================
#define SB_V 8704
#define STAGE 19584
#define SBUF_BYTES (2 * STAGE)

__global__ void __launch_bounds__(256, 2) attn_mma() {
    __shared__ __align__(16) char sbuf[SBUF_BYTES];
    const int tid = threadIdx.x;
    const int lane = tid & 31;
    const int w = tid >> 5;
    const int h = blockIdx.y, b = blockIdx.z;
    const int qb = blockIdx.x * 128;
    const size_t cbase = ((size_t)b * CC + h * 32) * HW;
    const float* qg = g_q + cbase;
    const __half* kgp = g_kh + cbase;
    const __half* vgp = g_vh + cbase;
    const uint32_t sb = smem_u32(sbuf);

    // ---- stage Q hi (scaled), extract A-fragments ----
    {
        int q = tid >> 1, dh = (tid & 1) * 16;
#pragma unroll
        for (int i = 0; i < 16; i++) {
            float v = qg[(size_t)(dh + i) * HW + qb + q] * SCALE2;
            *(__half*)(sbuf + (q * 40 + dh + i) * 2) = __float2half(v);
        }
    }
    __syncthreads();
    uint32_t qa[2][4];
    {
        int row = w * 16 + (lane & 15);
        int colb = (lane >> 4) * 8;
#pragma unroll
        for (int ks = 0; ks < 2; ks++)
            ldsm4(qa[ks], sb + (row * 40 + ks * 16 + colb) * 2);
    }
    __syncthreads();   // Q region free

    // init V rows 32-39 in BOTH stages: row 32 = ones, rows 33-39 = zero
    for (int i = tid; i < 544; i += 256) {
        uint32_t v = (i < 68) ? 0x3C003C00u : 0u;
        *(uint32_t*)(sbuf + SB_V + 8704 + i * 4) = v;
        *(uint32_t*)(sbuf + STAGE + SB_V + 8704 + i * 4) = v;
    }

    const int cd = tid >> 3;          // copy: d row 0..31
    const int cjh = (tid & 7) * 16;   // copy: j col (halves)
    const uint32_t cpK = sb + (cd * 136 + cjh) * 2;
    const uint32_t cpV = sb + SB_V + (cd * 136 + cjh) * 2;
    const __half* gK = kgp + (size_t)cd * HW + cjh;
    const __half* gV = vgp + (size_t)cd * HW + cjh;

    // prologue: prefetch 128-key tiles 0 and 1
    cp16(cpK, gK);       cp16(cpK + 16, gK + 8);
    cp16(cpV, gV);       cp16(cpV + 16, gV + 8);
    CP_COMMIT();
    cp16(cpK + STAGE, gK + 128); cp16(cpK + STAGE + 16, gK + 136);
    cp16(cpV + STAGE, gV + 128); cp16(cpV + STAGE + 16, gV + 136);
    CP_COMMIT();

    float mrow0 = -1e30f, mrow1 = -1e30f;
    float o[4][4], ol[4];
#pragma unroll
    for (int nt = 0; nt < 4; nt++)
#pragma unroll
        for (int i = 0; i < 4; i++) o[nt][i] = 0.0f;
#pragma unroll
    for (int i = 0; i < 4; i++) ol[i] = 0.0f;

    const int brow = (lane & 7) + ((lane & 16) >> 1);
    const int bcol8 = (lane & 8) ? 8 : 0;

    for (int t = 0; t < 32; t++) {
        const uint32_t base = sb + (t & 1) * STAGE;
        CP_WAIT1();
        __syncthreads();

#pragma unroll
        for (int half = 0; half < 2; half++) {
            const int joff = half * 64;

            // ---------------- QK^T (K via trans ldsm from [d][j]) ----------
            float s[8][4];
#pragma unroll
            for (int nt = 0; nt < 8; nt++)
#pragma unroll
                for (int i = 0; i < 4; i++) s[nt][i] = 0.0f;

#pragma unroll
            for (int ks = 0; ks < 2; ks++) {
#pragma unroll
                for (int n0 = 0; n0 < 4; n0++) {
                    uint32_t bh[4];
                    ldsm4t(bh, base + ((ks * 16 + (lane & 15)) * 136 +
                                       joff + n0 * 16 + (lane >> 4) * 8) * 2);
                    mma16816(s[n0 * 2], qa[ks], bh);
                    mma16816(s[n0 * 2 + 1], qa[ks], bh + 2);
                }
            }

            // ---------------- online softmax (base-2, fp16 exp) ------------
            float mt0 = -1e30f, mt1 = -1e30f;
#pragma unroll
            for (int nt = 0; nt < 8; nt++) {
                mt0 = fmaxf(mt0, fmaxf(s[nt][0], s[nt][1]));
                mt1 = fmaxf(mt1, fmaxf(s[nt][2], s[nt][3]));
            }
            mt0 = fmaxf(mt0, __shfl_xor_sync(0xffffffffu, mt0, 1));
            mt0 = fmaxf(mt0, __shfl_xor_sync(0xffffffffu, mt0, 2));
            mt1 = fmaxf(mt1, __shfl_xor_sync(0xffffffffu, mt1, 1));
            mt1 = fmaxf(mt1, __shfl_xor_sync(0xffffffffu, mt1, 2));
            float mn0 = fmaxf(mrow0, mt0);
            float mn1 = fmaxf(mrow1, mt1);
            // rescale only when some lane's max actually increased
            if (__any_sync(0xffffffffu, (mn0 > mrow0) || (mn1 > mrow1))) {
                float c0 = ex2f(mrow0 - mn0);
                float c1 = ex2f(mrow1 - mn1);
#pragma unroll
                for (int nt = 0; nt < 4; nt++) {
                    o[nt][0] *= c0; o[nt][1] *= c0;
                    o[nt][2] *= c1; o[nt][3] *= c1;
                }
                ol[0] *= c0; ol[1] *= c0; ol[2] *= c1; ol[3] *= c1;
            }
            mrow0 = mn0; mrow1 = mn1;

            uint32_t pu[8][2];
#pragma unroll
            for (int nt = 0; nt < 8; nt++) {
                pu[nt][0] = ex2_h2(cvt_f16x2(s[nt][1] - mn0, s[nt][0] - mn0));
                pu[nt][1] = ex2_h2(cvt_f16x2(s[nt][3] - mn1, s[nt][2] - mn1));
            }

            // ---------------- PV (+ ones column -> l) ----------------------
#pragma unroll
            for (int ks = 0; ks < 4; ks++) {
                uint32_t ah[4] = { pu[2 * ks][0], pu[2 * ks][1],
                                   pu[2 * ks + 1][0], pu[2 * ks + 1][1] };
#pragma unroll
                for (int n0 = 0; n0 < 2; n0++) {
                    uint32_t vh[4];
                    ldsm4(vh, base + SB_V + ((n0 * 16 + brow) * 136 +
                                             joff + ks * 16 + bcol8) * 2);
                    mma16816(o[n0 * 2], ah, vh);
                    mma16816(o[n0 * 2 + 1], ah, vh + 2);
                }
                uint32_t b2[2];
                ldsm2(b2, base + SB_V + ((32 + (lane & 7)) * 136 +
                                         joff + ks * 16 + bcol8) * 2);
                mma16816(ol, ah, b2);
            }
        }

        __syncthreads();   // all reads of this stage done
        int tn = t + 2;
        if (tn < 32) {
            const uint32_t so = (t & 1) * STAGE;
            const int go = tn * 128;
            cp16(cpK + so, gK + go);       cp16(cpK + so + 16, gK + go + 8);
            cp16(cpV + so, gV + go);       cp16(cpV + so + 16, gV + go + 8);
        }
        CP_COMMIT();
    }

    // ---------------- finalize ----------------
    float l0 = __shfl_sync(0xffffffffu, ol[0], lane & 28);
    float l1 = __shfl_sync(0xffffffffu, ol[2], lane & 28);
    float i0 = 1.0f / l0, i1 = 1.0f / l1;
    int pix = qb + w * 16 + (lane >> 2);
#pragma unroll
    for (int nt = 0; nt < 4; nt++) {
        int d = nt * 8 + 2 * (lane & 3);
        g_gd[cbase + (size_t)d * HW + pix] = o[nt][0] * i0;
        g_gd[cbase + (size_t)(d + 1) * HW + pix] = o[nt][1] * i0;
        g_gd[cbase + (size_t)d * HW + pix + 8] = o[nt][2] * i1;
        g_gd[cbase + (size_t)(d + 1) * HW + pix + 8] = o[nt][3] * i1;
    }
}

// ================================================================
// 1x1 conv via HMMA, 32-pixel tiles (unchanged from R7).
// ================================================================
template<bool DUAL>
__global__ __launch_bounds__(256) void conv1x1_tc(
    const float* __restrict__ X,
    const float* __restrict__ W1, const float* __restrict__ b1, float* __restrict__ Y1,
    const float* __restrict__ W2, const float* __restrict__ b2, float* __restrict__ Y2,
    const float* __restrict__ resid,
    __half* __restrict__ H1, __half* __restrict__ H2) {
    __shared__ __align__(16) char sbuf[34816];
    const int tid = threadIdx.x;
    const int lane = tid & 31;
    const int w = tid >> 5;
    const int bb = blockIdx.y;
    const int p0 = blockIdx.x * 32;
    const uint32_t sb = smem_u32(sbuf);
    const int brow = (lane & 7) + ((lane & 16) >> 1);
    const int bcol8 = (lane & 8) ? 8 : 0;

    float4 xreg[4];
#pragma unroll
    for (int i = 0; i < 4; i++) {
        int idx = i * 256 + tid;
        int ci = idx >> 3, px = (idx & 7) * 4;
        xreg[i] = *(const float4*)(X + ((size_t)bb * CC + ci) * HW + p0 + px);
    }

    uint32_t wa1[8][4], wa2[8][4];
    {
#pragma unroll
        for (int i = 0; i < 16; i++) {
            int idx = i * 256 + tid;
            int co = idx >> 5, ci = (idx & 31) * 4;
            float4 v = *(const float4*)(W1 + co * CC + ci);
            __half* d = (__half*)(sbuf) + co * 136 + ci;
            d[0] = __float2half(v.x); d[1] = __float2half(v.y);
            d[2] = __float2half(v.z); d[3] = __float2half(v.w);
        }
        __syncthreads();
        int row = w * 16 + (lane & 15);
        int colb = (lane >> 4) * 8;
#pragma unroll
        for (int ks = 0; ks < 8; ks++)
            ldsm4(wa1[ks], sb + (row * 136 + ks * 16 + colb) * 2);
        __syncthreads();
    }
    if (DUAL) {
#pragma unroll
        for (int i = 0; i < 16; i++) {
            int idx = i * 256 + tid;
            int co = idx >> 5, ci = (idx & 31) * 4;
            float4 v = *(const float4*)(W2 + co * CC + ci);
            __half* d = (__half*)(sbuf) + co * 136 + ci;
            d[0] = __float2half(v.x); d[1] = __float2half(v.y);
            d[2] = __float2half(v.z); d[3] = __float2half(v.w);
        }
        __syncthreads();
        int row = w * 16 + (lane & 15);
        int colb = (lane >> 4) * 8;
#pragma unroll
        for (int ks = 0; ks < 8; ks++)
            ldsm4(wa2[ks], sb + (row * 136 + ks * 16 + colb) * 2);
        __syncthreads();
    }

#pragma unroll
    for (int i = 0; i < 4; i++) {
        int idx = i * 256 + tid;
        int ci = idx >> 3, px = (idx & 7) * 4;
        float vv[4] = { xreg[i].x, xreg[i].y, xreg[i].z, xreg[i].w };
#pragma unroll
        for (int j = 0; j < 4; j++) {
            __half hv = __float2half(vv[j]);
            *((__half*)(sbuf) + (px + j) * 136 + ci) = hv;
            *((__half*)(sbuf + 8704) + (px + j) * 136 + ci) =
                __float2half(vv[j] - __half2float(hv));
        }
    }
    __syncthreads();

    float acc1[4][4], acc2[4][4];
#pragma unroll
    for (int nt = 0; nt < 4; nt++)
#pragma unroll
        for (int i = 0; i < 4; i++) { acc1[nt][i] = 0.0f; acc2[nt][i] = 0.0f; }

#pragma unroll
    for (int ks = 0; ks < 8; ks++) {
#pragma unroll
        for (int n0 = 0; n0 < 2; n0++) {
            uint32_t bh[4], bl[4];
            uint32_t a = sb + ((n0 * 16 + brow) * 136 + ks * 16 + bcol8) * 2;
            ldsm4(bh, a);
            ldsm4(bl, a + 8704);
            mma16816(acc1[n0 * 2], wa1[ks], bh);
            mma16816(acc1[n0 * 2], wa1[ks], bl);
            mma16816(acc1[n0 * 2 + 1], wa1[ks], bh + 2);
            mma16816(acc1[n0 * 2 + 1], wa1[ks], bl + 2);
            if (DUAL) {
                mma16816(acc2[n0 * 2], wa2[ks], bh);
                mma16816(acc2[n0 * 2], wa2[ks], bl);
                mma16816(acc2[n0 * 2 + 1], wa2[ks], bh + 2);
                mma16816(acc2[n0 * 2 + 1], wa2[ks], bl + 2);
            }
        }
    }

    int coA = w * 16 + (lane >> 2);
    int coB = coA + 8;
    float b1A = b1[coA], b1B = b1[coB];
    float b2A = 0.0f, b2B = 0.0f;
    if (DUAL) { b2A = b2[coA]; b2B = b2[coB]; }
    size_t baseA = ((size_t)bb * CC + coA) * HW + p0;
    size_t baseB = ((size_t)bb * CC + coB) * HW + p0;
#pragma unroll
    for (int nt = 0; nt < 4; nt++) {
        int px = nt * 8 + 2 * (lane & 3);
        float vA0 = acc1[nt][0] + b1A, vA1 = acc1[nt][1] + b1A;
        float vB0 = acc1[nt][2] + b1B, vB1 = acc1[nt][3] + b1B;
        if (resid != nullptr) {
            float2 rA = *(const float2*)(resid + baseA + px);
            float2 rB = *(const float2*)(resid + baseB + px);
            vA0 += rA.x; vA1 += rA.y; vB0 += rB.x; vB1 += rB.y;
        }
        if (Y1 != nullptr) {
            *(float2*)(Y1 + baseA + px) = make_float2(vA0, vA1);
            *(float2*)(Y1 + baseB + px) = make_float2(vB0, vB1);
        }
        if (H1 != nullptr) {
            *(uint32_t*)(H1 + baseA + px) = cvt_f16x2(vA1, vA0);
            *(uint32_t*)(H1 + baseB + px) = cvt_f16x2(vB1, vB0);
        }
        if (DUAL) {
            float uA0 = acc2[nt][0] + b2A, uA1 = acc2[nt][1] + b2A;
            float uB0 = acc2[nt][2] + b2B, uB1 = acc2[nt][3] + b2B;
            if (Y2 != nullptr) {
                *(float2*)(Y2 + baseA + px) = make_float2(uA0, uA1);
                *(float2*)(Y2 + baseB + px) = make_float2(uB0, uB1);
            }
            if (H2 != nullptr) {
                *(uint32_t*)(H2 + baseA + px) = cvt_f16x2(uA1, uA0);
                *(uint32_t*)(H2 + baseB + px) = cvt_f16x2(uB1, uB0);
            }
        }
    }
}

// ================= fused mask convs: seg -> relu(conv3x3) -> conv3x3 =========
__global__ __launch_bounds__(256) void mask_fused(const float* __restrict__ seg,
                                                  const float* __restrict__ Wm1,
                                                  const float* __restrict__ bm1,
                                                  const float* __restrict__ Wm2,
                                                  const float* __restrict__ bm2) {
    int y = blockIdx.x, b = blockIdx.y;
    __shared__ float sseg[5][66];
    __shared__ float sm[32][3][66];
    const float* sgb = seg + (size_t)b * HW;
    for (int i = threadIdx.x; i < 5 * 66; i += 256) {
        int r = i / 66, x = i % 66;
        int yy = y + r - 2, xx = x - 1;
        sseg[r][x] = (yy >= 0 && yy < 64 && xx >= 0 && xx < 64)
                     ? sgb[yy * 64 + xx] : 0.0f;
    }
    __syncthreads();
    // compute m1 = relu(conv3x3(seg)) for rows y-1..y+1, all 32 channels
    for (int i = threadIdx.x; i < 32 * 3 * 66; i += 256) {
        int c = i / 198, rem = i % 198, r = rem / 66, x = rem % 66;
        int yy = y + r - 1, xx = x - 1;
        float v = 0.0f;
        if (yy >= 0 && yy < 64 && xx >= 0 && xx < 64) {
            float acc = bm1[c];
            const float* wp = Wm1 + c * 9;
#pragma unroll
            for (int dy = 0; dy < 3; dy++)
#pragma unroll
                for (int dx = 0; dx < 3; dx++)
                    acc += wp[dy * 3 + dx] * sseg[r + dy][x + dx - 1];
            v = fmaxf(acc, 0.0f);
        }
        sm[c][r][x] = v;
    }
    __syncthreads();
    // second conv
    int co = threadIdx.x >> 1;
    int xh = (threadIdx.x & 1) * 32;
    float acc[32];
    float bb = bm2[co];
#pragma unroll
    for (int px = 0; px < 32; px++) acc[px] = bb;
    const float* w = Wm2 + co * 288;
    for (int ci = 0; ci < 32; ci++) {
#pragma unroll
        for (int r = 0; r < 3; r++) {
            const float* row = &sm[ci][r][xh];
            float rv[34];
#pragma unroll
            for (int t = 0; t < 34; t++) rv[t] = row[t];
#pragma unroll
            for (int dx = 0; dx < 3; dx++) {
                float wv = w[(ci * 3 + r) * 3 + dx];
#pragma unroll
                for (int px = 0; px < 32; px++) acc[px] += wv * rv[px + dx];
            }
        }
    }
    float* out = g_mf + ((size_t)b * CC + co) * HW + y * 64 + xh;
#pragma unroll
    for (int px = 0; px < 32; px++) out[px] = acc[px];
}

// ---------------- launch ----------------
extern "C" void kernel_launch(void* const* d_in, const int* in_sizes, int n_in,
                              void* d_out, int out_size) {
    const float* sr  = (const float*)d_in[0];
    const float* seg = (const float*)d_in[1];
    const float* Wq  = (const float*)d_in[2];
    const float* bq  = (const float*)d_in[3];
    const float* Wm1 = (const float*)d_in[4];
    const float* bm1 = (const float*)d_in[5];
    const float* Wm2 = (const float*)d_in[6];
    const float* bm2 = (const float*)d_in[7];
    const float* Wk  = (const float*)d_in[8];
    const float* bk  = (const float*)d_in[9];
    const float* Wv  = (const float*)d_in[10];
    const float* bv  = (const float*)d_in[11];
    const float* Wo  = (const float*)d_in[12];
    const float* bo  = (const float*)d_in[13];
    float* out = (float*)d_out;

    float *pmf, *pq, *pg;
    __half *pkh, *pvh;
    cudaGetSymbolAddress((void**)&pmf, g_mf);
    cudaGetSymbolAddress((void**)&pq, g_q);
    cudaGetSymbolAddress((void**)&pg, g_gd);
    cudaGetSymbolAddress((void**)&pkh, g_kh);
    cudaGetSymbolAddress((void**)&pvh, g_vh);

    mask_fused<<<dim3(64, BATCH), 256>>>(seg, Wm1, bm1, Wm2, bm2);
    conv1x1_tc<false><<<dim3(HW / 32, BATCH), 256>>>(
        sr, Wq, bq, pq, nullptr, nullptr, nullptr, nullptr, nullptr, nullptr);
    conv1x1_tc<true><<<dim3(HW / 32, BATCH), 256>>>(
        pmf, Wk, bk, nullptr, Wv, bv, nullptr, nullptr, pkh, pvh);
    attn_mma<<<dim3(32, HEADS, BATCH), 256>>>();
    conv1x1_tc<false><<<dim3(HW / 32, BATCH), 256>>>(
        pg, Wo, bo, out, nullptr, nullptr, nullptr, sr, nullptr, nullptr);
}

// round 9
// speedup vs baseline: 5.4477x; 1.0283x over previous
#include <cuda_runtime.h>
#include <cuda_fp16.h>
#include <cstdint>
#include <cstddef>

#define BATCH 2
#define CC 128
#define HW 4096
#define HEADS 4
// 32^-0.5 * log2(e): softmax in base-2
#define SCALE2 0.25500526764086436f

// ---------------- scratch ----------------
__device__ float g_mf[BATCH * CC * HW];
__device__ float g_q[BATCH * CC * HW];
__device__ float g_gd[BATCH * CC * HW];
__device__ __align__(16) __half g_kh[BATCH * CC * HW];
__device__ __align__(16) __half g_vh[BATCH * CC * HW];

// ---------------- helpers ----------------
__device__ __forceinline__ uint32_t smem_u32(const void* p) {
    uint32_t a;
    asm("{ .reg .u64 t; cvta.to.shared.u64 t, %1; cvt.u32.u64 %0, t; }" : "=r"(a) : "l"(p));
    return a;
}
__device__ __forceinline__ float ex2f(float x) {
    float r; asm("ex2.approx.f32 %0, %1;" : "=f"(r) : "f"(x)); return r;
}
__device__ __forceinline__ uint32_t cvt_f16x2(float hi, float lo) {
    uint32_t r; asm("cvt.rn.f16x2.f32 %0, %1, %2;" : "=r"(r) : "f"(hi), "f"(lo)); return r;
}
__device__ __forceinline__ uint32_t ex2_h2(uint32_t a) {
    uint32_t r; asm("ex2.approx.f16x2 %0, %1;" : "=r"(r) : "r"(a)); return r;
}
__device__ __forceinline__ void ldsm4(uint32_t* r, uint32_t addr) {
    asm volatile("ldmatrix.sync.aligned.m8n8.x4.shared.b16 {%0,%1,%2,%3}, [%4];"
        : "=r"(r[0]), "=r"(r[1]), "=r"(r[2]), "=r"(r[3]) : "r"(addr));
}
__device__ __forceinline__ void ldsm4t(uint32_t* r, uint32_t addr) {
    asm volatile("ldmatrix.sync.aligned.m8n8.x4.trans.shared.b16 {%0,%1,%2,%3}, [%4];"
        : "=r"(r[0]), "=r"(r[1]), "=r"(r[2]), "=r"(r[3]) : "r"(addr));
}
__device__ __forceinline__ void mma16816(float* c, const uint32_t* a, const uint32_t* b) {
    asm volatile("mma.sync.aligned.m16n8k16.row.col.f32.f16.f16.f32 "
        "{%0,%1,%2,%3}, {%4,%5,%6,%7}, {%8,%9}, {%0,%1,%2,%3};"
        : "+f"(c[0]), "+f"(c[1]), "+f"(c[2]), "+f"(c[3])
        : "r"(a[0]), "r"(a[1]), "r"(a[2]), "r"(a[3]), "r"(b[0]), "r"(b[1]));
}
__device__ __forceinline__ void cp16(uint32_t saddr, const void* g) {
    asm volatile("cp.async.cg.shared.global [%0], [%1], 16;" :: "r"(saddr), "l"(g));
}
#define CP_COMMIT() asm volatile("cp.async.commit_group;" ::: "memory")
#define CP_WAIT1()  asm volatile("cp.async.wait_group 1;" ::: "memory")

// ================================================================
// flash attention: fp16 QK/PV. l via constant ones-column B fragment.
// Lazy-max softmax: QK accumulators initialized to -m, so the fast path
// needs no per-score subtraction; rescale branch is warp-uniform & rare.
// grid (32, HEADS, BATCH), 256 threads (8 warps), warp = 16 queries.
// stage (17408 B): K [32 d][136 j] at +0, V [32 d][136 j] at +8704.
// Q staged in its own region at +34816 so cp.async prologue issues first.
// ================================================================
#define SB_V 8704
#define STAGE 17408
#define SB_Q (2 * STAGE)
#define SBUF_BYTES (2 * STAGE + 10240)

__global__ void __launch_bounds__(256, 2) attn_mma() {
    __shared__ __align__(16) char sbuf[SBUF_BYTES];
    const int tid = threadIdx.x;
    const int lane = tid & 31;
    const int w = tid >> 5;
    const int h = blockIdx.y, b = blockIdx.z;
    const int qb = blockIdx.x * 128;
    const size_t cbase = ((size_t)b * CC + h * 32) * HW;
    const float* qg = g_q + cbase;
    const __half* kgp = g_kh + cbase;
    const __half* vgp = g_vh + cbase;
    const uint32_t sb = smem_u32(sbuf);

    // ---- cp.async prologue FIRST: prefetch 128-key tiles 0 and 1 ----
    const int cd = tid >> 3;          // d row 0..31
    const int cjh = (tid & 7) * 16;   // j col (halves)
    const uint32_t cpK = sb + (cd * 136 + cjh) * 2;
    const uint32_t cpV = sb + SB_V + (cd * 136 + cjh) * 2;
    const __half* gK = kgp + (size_t)cd * HW + cjh;
    const __half* gV = vgp + (size_t)cd * HW + cjh;
    cp16(cpK, gK);       cp16(cpK + 16, gK + 8);
    cp16(cpV, gV);       cp16(cpV + 16, gV + 8);
    CP_COMMIT();
    cp16(cpK + STAGE, gK + 128); cp16(cpK + STAGE + 16, gK + 136);
    cp16(cpV + STAGE, gV + 128); cp16(cpV + STAGE + 16, gV + 136);
    CP_COMMIT();

    // ---- stage Q hi (scaled) in its own region, extract A-fragments ----
    {
        int q = tid >> 1, dh = (tid & 1) * 16;
#pragma unroll
        for (int i = 0; i < 16; i++) {
            float v = qg[(size_t)(dh + i) * HW + qb + q] * SCALE2;
            *(__half*)(sbuf + SB_Q + (q * 40 + dh + i) * 2) = __float2half(v);
        }
    }
    __syncthreads();
    uint32_t qa[2][4];
    {
        int row = w * 16 + (lane & 15);
        int colb = (lane >> 4) * 8;
#pragma unroll
        for (int ks = 0; ks < 2; ks++)
            ldsm4(qa[ks], sb + SB_Q + (row * 40 + ks * 16 + colb) * 2);
    }

    // constant B-fragment for the ones column (l accumulation):
    // B[k][n] = (n == 0), so lanes 0-3 hold {1,1}, others 0 (both regs).
    const uint32_t b2c[2] = { (lane < 4) ? 0x3C003C00u : 0u,
                              (lane < 4) ? 0x3C003C00u : 0u };

    float mrow0 = 0.0f, mrow1 = 0.0f;   // running max (lazy)
    float o[4][4], ol[4];
#pragma unroll
    for (int nt = 0; nt < 4; nt++)
#pragma unroll
        for (int i = 0; i < 4; i++) o[nt][i] = 0.0f;
#pragma unroll
    for (int i = 0; i < 4; i++) ol[i] = 0.0f;

    const int brow = (lane & 7) + ((lane & 16) >> 1);
    const int bcol8 = (lane & 8) ? 8 : 0;

    for (int t = 0; t < 32; t++) {
        const uint32_t base = sb + (t & 1) * STAGE;
        CP_WAIT1();
        __syncthreads();

#pragma unroll
        for (int half = 0; half < 2; half++) {
            const int joff = half * 64;

            // ---------------- QK^T, C initialized to -m ----------------
            float s[8][4];
            {
                float ns0 = -mrow0, ns1 = -mrow1;
#pragma unroll
                for (int nt = 0; nt < 8; nt++) {
                    s[nt][0] = ns0; s[nt][1] = ns0;
                    s[nt][2] = ns1; s[nt][3] = ns1;
                }
            }
#pragma unroll
            for (int ks = 0; ks < 2; ks++) {
#pragma unroll
                for (int n0 = 0; n0 < 4; n0++) {
                    uint32_t bh[4];
                    ldsm4t(bh, base + ((ks * 16 + (lane & 15)) * 136 +
                                       joff + n0 * 16 + (lane >> 4) * 8) * 2);
                    mma16816(s[n0 * 2], qa[ks], bh);
                    mma16816(s[n0 * 2 + 1], qa[ks], bh + 2);
                }
            }

            // ---------------- lazy-max softmax ----------------
            float mt0 = s[0][0], mt1 = s[0][2];
#pragma unroll
            for (int nt = 0; nt < 8; nt++) {
                mt0 = fmaxf(mt0, fmaxf(s[nt][0], s[nt][1]));
                mt1 = fmaxf(mt1, fmaxf(s[nt][2], s[nt][3]));
            }
            mt0 = fmaxf(mt0, __shfl_xor_sync(0xffffffffu, mt0, 1));
            mt0 = fmaxf(mt0, __shfl_xor_sync(0xffffffffu, mt0, 2));
            mt1 = fmaxf(mt1, __shfl_xor_sync(0xffffffffu, mt1, 1));
            mt1 = fmaxf(mt1, __shfl_xor_sync(0xffffffffu, mt1, 2));
            if (__any_sync(0xffffffffu, (mt0 > 0.0f) || (mt1 > 0.0f))) {
                float d0 = fmaxf(mt0, 0.0f), d1 = fmaxf(mt1, 0.0f);
                float c0 = ex2f(-d0), c1 = ex2f(-d1);
                mrow0 += d0; mrow1 += d1;
#pragma unroll
                for (int nt = 0; nt < 4; nt++) {
                    o[nt][0] *= c0; o[nt][1] *= c0;
                    o[nt][2] *= c1; o[nt][3] *= c1;
                }
                ol[0] *= c0; ol[1] *= c0; ol[2] *= c1; ol[3] *= c1;
#pragma unroll
                for (int nt = 0; nt < 8; nt++) {
                    s[nt][0] -= d0; s[nt][1] -= d0;
                    s[nt][2] -= d1; s[nt][3] -= d1;
                }
            }
            uint32_t pu[8][2];
#pragma unroll
            for (int nt = 0; nt < 8; nt++) {
                pu[nt][0] = ex2_h2(cvt_f16x2(s[nt][1], s[nt][0]));
                pu[nt][1] = ex2_h2(cvt_f16x2(s[nt][3], s[nt][2]));
            }

            // ---------------- PV (+ constant ones column -> l) ----------
#pragma unroll
            for (int ks = 0; ks < 4; ks++) {
                uint32_t ah[4] = { pu[2 * ks][0], pu[2 * ks][1],
                                   pu[2 * ks + 1][0], pu[2 * ks + 1][1] };
#pragma unroll
                for (int n0 = 0; n0 < 2; n0++) {
                    uint32_t vh[4];
                    ldsm4(vh, base + SB_V + ((n0 * 16 + brow) * 136 +
                                             joff + ks * 16 + bcol8) * 2);
                    mma16816(o[n0 * 2], ah, vh);
                    mma16816(o[n0 * 2 + 1], ah, vh + 2);
                }
                mma16816(ol, ah, b2c);
            }
        }

        __syncthreads();   // all reads of this stage done
        int tn = t + 2;
        if (tn < 32) {
            const uint32_t so = (t & 1) * STAGE;
            const int go = tn * 128;
            cp16(cpK + so, gK + go);       cp16(cpK + so + 16, gK + go + 8);
            cp16(cpV + so, gV + go);       cp16(cpV + so + 16, gV + go + 8);
        }
        CP_COMMIT();
    }

    // ---------------- finalize ----------------
    float l0 = __shfl_sync(0xffffffffu, ol[0], lane & 28);
    float l1 = __shfl_sync(0xffffffffu, ol[2], lane & 28);
    float i0 = 1.0f / l0, i1 = 1.0f / l1;
    int pix = qb + w * 16 + (lane >> 2);
#pragma unroll
    for (int nt = 0; nt < 4; nt++) {
        int d = nt * 8 + 2 * (lane & 3);
        g_gd[cbase + (size_t)d * HW + pix] = o[nt][0] * i0;
        g_gd[cbase + (size_t)(d + 1) * HW + pix] = o[nt][1] * i0;
        g_gd[cbase + (size_t)d * HW + pix + 8] = o[nt][2] * i1;
        g_gd[cbase + (size_t)(d + 1) * HW + pix + 8] = o[nt][3] * i1;
    }
}

// ================================================================
// 1x1 conv via HMMA, 32-pixel tiles. XLO: include X lo-correction term
// (only needed when the fp32 output precision matters downstream).
// ================================================================
template<bool DUAL, bool XLO>
__global__ __launch_bounds__(256) void conv1x1_tc(
    const float* __restrict__ X,
    const float* __restrict__ W1, const float* __restrict__ b1, float* __restrict__ Y1,
    const float* __restrict__ W2, const float* __restrict__ b2, float* __restrict__ Y2,
    const float* __restrict__ resid,
    __half* __restrict__ H1, __half* __restrict__ H2) {
    __shared__ __align__(16) char sbuf[34816];
    const int tid = threadIdx.x;
    const int lane = tid & 31;
    const int w = tid >> 5;
    const int bb = blockIdx.y;
    const int p0 = blockIdx.x * 32;
    const uint32_t sb = smem_u32(sbuf);
    const int brow = (lane & 7) + ((lane & 16) >> 1);
    const int bcol8 = (lane & 8) ? 8 : 0;

    float4 xreg[4];
#pragma unroll
    for (int i = 0; i < 4; i++) {
        int idx = i * 256 + tid;
        int ci = idx >> 3, px = (idx & 7) * 4;
        xreg[i] = *(const float4*)(X + ((size_t)bb * CC + ci) * HW + p0 + px);
    }

    uint32_t wa1[8][4], wa2[8][4];
    {
#pragma unroll
        for (int i = 0; i < 16; i++) {
            int idx = i * 256 + tid;
            int co = idx >> 5, ci = (idx & 31) * 4;
            float4 v = *(const float4*)(W1 + co * CC + ci);
            __half* d = (__half*)(sbuf) + co * 136 + ci;
            d[0] = __float2half(v.x); d[1] = __float2half(v.y);
            d[2] = __float2half(v.z); d[3] = __float2half(v.w);
        }
        __syncthreads();
        int row = w * 16 + (lane & 15);
        int colb = (lane >> 4) * 8;
#pragma unroll
        for (int ks = 0; ks < 8; ks++)
            ldsm4(wa1[ks], sb + (row * 136 + ks * 16 + colb) * 2);
        __syncthreads();
    }
    if (DUAL) {
#pragma unroll
        for (int i = 0; i < 16; i++) {
            int idx = i * 256 + tid;
            int co = idx >> 5, ci = (idx & 31) * 4;
            float4 v = *(const float4*)(W2 + co * CC + ci);
            __half* d = (__half*)(sbuf) + co * 136 + ci;
            d[0] = __float2half(v.x); d[1] = __float2half(v.y);
            d[2] = __float2half(v.z); d[3] = __float2half(v.w);
        }
        __syncthreads();
        int row = w * 16 + (lane & 15);
        int colb = (lane >> 4) * 8;
#pragma unroll
        for (int ks = 0; ks < 8; ks++)
            ldsm4(wa2[ks], sb + (row * 136 + ks * 16 + colb) * 2);
        __syncthreads();
    }

#pragma unroll
    for (int i = 0; i < 4; i++) {
        int idx = i * 256 + tid;
        int ci = idx >> 3, px = (idx & 7) * 4;
        float vv[4] = { xreg[i].x, xreg[i].y, xreg[i].z, xreg[i].w };
#pragma unroll
        for (int j = 0; j < 4; j++) {
            __half hv = __float2half(vv[j]);
            *((__half*)(sbuf) + (px + j) * 136 + ci) = hv;
            if (XLO)
                *((__half*)(sbuf + 8704) + (px + j) * 136 + ci) =
                    __float2half(vv[j] - __half2float(hv));
        }
    }
    __syncthreads();

    float acc1[4][4], acc2[4][4];
#pragma unroll
    for (int nt = 0; nt < 4; nt++)
#pragma unroll
        for (int i = 0; i < 4; i++) { acc1[nt][i] = 0.0f; acc2[nt][i] = 0.0f; }

#pragma unroll
    for (int ks = 0; ks < 8; ks++) {
#pragma unroll
        for (int n0 = 0; n0 < 2; n0++) {
            uint32_t bh[4], bl[4];
            uint32_t a = sb + ((n0 * 16 + brow) * 136 + ks * 16 + bcol8) * 2;
            ldsm4(bh, a);
            if (XLO) ldsm4(bl, a + 8704);
            mma16816(acc1[n0 * 2], wa1[ks], bh);
            if (XLO) mma16816(acc1[n0 * 2], wa1[ks], bl);
            mma16816(acc1[n0 * 2 + 1], wa1[ks], bh + 2);
            if (XLO) mma16816(acc1[n0 * 2 + 1], wa1[ks], bl + 2);
            if (DUAL) {
                mma16816(acc2[n0 * 2], wa2[ks], bh);
                if (XLO) mma16816(acc2[n0 * 2], wa2[ks], bl);
                mma16816(acc2[n0 * 2 + 1], wa2[ks], bh + 2);
                if (XLO) mma16816(acc2[n0 * 2 + 1], wa2[ks], bl + 2);
            }
        }
    }

    int coA = w * 16 + (lane >> 2);
    int coB = coA + 8;
    float b1A = b1[coA], b1B = b1[coB];
    float b2A = 0.0f, b2B = 0.0f;
    if (DUAL) { b2A = b2[coA]; b2B = b2[coB]; }
    size_t baseA = ((size_t)bb * CC + coA) * HW + p0;
    size_t baseB = ((size_t)bb * CC + coB) * HW + p0;
#pragma unroll
    for (int nt = 0; nt < 4; nt++) {
        int px = nt * 8 + 2 * (lane & 3);
        float vA0 = acc1[nt][0] + b1A, vA1 = acc1[nt][1] + b1A;
        float vB0 = acc1[nt][2] + b1B, vB1 = acc1[nt][3] + b1B;
        if (resid != nullptr) {
            float2 rA = *(const float2*)(resid + baseA + px);
            float2 rB = *(const float2*)(resid + baseB + px);
            vA0 += rA.x; vA1 += rA.y; vB0 += rB.x; vB1 += rB.y;
        }
        if (Y1 != nullptr) {
            *(float2*)(Y1 + baseA + px) = make_float2(vA0, vA1);
            *(float2*)(Y1 + baseB + px) = make_float2(vB0, vB1);
        }
        if (H1 != nullptr) {
            *(uint32_t*)(H1 + baseA + px) = cvt_f16x2(vA1, vA0);
            *(uint32_t*)(H1 + baseB + px) = cvt_f16x2(vB1, vB0);
        }
        if (DUAL) {
            float uA0 = acc2[nt][0] + b2A, uA1 = acc2[nt][1] + b2A;
            float uB0 = acc2[nt][2] + b2B, uB1 = acc2[nt][3] + b2B;
            if (Y2 != nullptr) {
                *(float2*)(Y2 + baseA + px) = make_float2(uA0, uA1);
                *(float2*)(Y2 + baseB + px) = make_float2(uB0, uB1);
            }
            if (H2 != nullptr) {
                *(uint32_t*)(H2 + baseA + px) = cvt_f16x2(uA1, uA0);
                *(uint32_t*)(H2 + baseB + px) = cvt_f16x2(uB1, uB0);
            }
        }
    }
}

// ================= fused mask convs: seg -> relu(conv3x3) -> conv3x3 =========
__global__ __launch_bounds__(256) void mask_fused(const float* __restrict__ seg,
                                                  const float* __restrict__ Wm1,
                                                  const float* __restrict__ bm1,
                                                  const float* __restrict__ Wm2,
                                                  const float* __restrict__ bm2) {
    int y = blockIdx.x, b = blockIdx.y;
    __shared__ float sseg[5][66];
    __shared__ float sm[32][3][66];
    const float* sgb = seg + (size_t)b * HW;
    for (int i = threadIdx.x; i < 5 * 66; i += 256) {
        int r = i / 66, x = i % 66;
        int yy = y + r - 2, xx = x - 1;
        sseg[r][x] = (yy >= 0 && yy < 64 && xx >= 0 && xx < 64)
                     ? sgb[yy * 64 + xx] : 0.0f;
    }
    __syncthreads();
    for (int i = threadIdx.x; i < 32 * 3 * 66; i += 256) {
        int c = i / 198, rem = i % 198, r = rem / 66, x = rem % 66;
        int yy = y + r - 1, xx = x - 1;
        float v = 0.0f;
        if (yy >= 0 && yy < 64 && xx >= 0 && xx < 64) {
            float acc = bm1[c];
            const float* wp = Wm1 + c * 9;
#pragma unroll
            for (int dy = 0; dy < 3; dy++)
#pragma unroll
                for (int dx = 0; dx < 3; dx++)
                    acc += wp[dy * 3 + dx] * sseg[r + dy][x + dx - 1];
            v = fmaxf(acc, 0.0f);
        }
        sm[c][r][x] = v;
    }
    __syncthreads();
    int co = threadIdx.x >> 1;
    int xh = (threadIdx.x & 1) * 32;
    float acc[32];
    float bb = bm2[co];
#pragma unroll
    for (int px = 0; px < 32; px++) acc[px] = bb;
    const float* w = Wm2 + co * 288;
    for (int ci = 0; ci < 32; ci++) {
#pragma unroll
        for (int r = 0; r < 3; r++) {
            const float* row = &sm[ci][r][xh];
            float rv[34];
#pragma unroll
            for (int t = 0; t < 34; t++) rv[t] = row[t];
#pragma unroll
            for (int dx = 0; dx < 3; dx++) {
                float wv = w[(ci * 3 + r) * 3 + dx];
#pragma unroll
                for (int px = 0; px < 32; px++) acc[px] += wv * rv[px + dx];
            }
        }
    }
    float* out = g_mf + ((size_t)b * CC + co) * HW + y * 64 + xh;
#pragma unroll
    for (int px = 0; px < 32; px++) out[px] = acc[px];
}

// ---------------- launch ----------------
extern "C" void kernel_launch(void* const* d_in, const int* in_sizes, int n_in,
                              void* d_out, int out_size) {
    const float* sr  = (const float*)d_in[0];
    const float* seg = (const float*)d_in[1];
    const float* Wq  = (const float*)d_in[2];
    const float* bq  = (const float*)d_in[3];
    const float* Wm1 = (const float*)d_in[4];
    const float* bm1 = (const float*)d_in[5];
    const float* Wm2 = (const float*)d_in[6];
    const float* bm2 = (const float*)d_in[7];
    const float* Wk  = (const float*)d_in[8];
    const float* bk  = (const float*)d_in[9];
    const float* Wv  = (const float*)d_in[10];
    const float* bv  = (const float*)d_in[11];
    const float* Wo  = (const float*)d_in[12];
    const float* bo  = (const float*)d_in[13];
    float* out = (float*)d_out;

    float *pmf, *pq, *pg;
    __half *pkh, *pvh;
    cudaGetSymbolAddress((void**)&pmf, g_mf);
    cudaGetSymbolAddress((void**)&pq, g_q);
    cudaGetSymbolAddress((void**)&pg, g_gd);
    cudaGetSymbolAddress((void**)&pkh, g_kh);
    cudaGetSymbolAddress((void**)&pvh, g_vh);

    mask_fused<<<dim3(64, BATCH), 256>>>(seg, Wm1, bm1, Wm2, bm2);
    conv1x1_tc<false, false><<<dim3(HW / 32, BATCH), 256>>>(
        sr, Wq, bq, pq, nullptr, nullptr, nullptr, nullptr, nullptr, nullptr);
    conv1x1_tc<true, false><<<dim3(HW / 32, BATCH), 256>>>(
        pmf, Wk, bk, nullptr, Wv, bv, nullptr, nullptr, pkh, pvh);
    attn_mma<<<dim3(32, HEADS, BATCH), 256>>>();
    conv1x1_tc<false, true><<<dim3(HW / 32, BATCH), 256>>>(
        pg, Wo, bo, out, nullptr, nullptr, nullptr, sr, nullptr, nullptr);
}

// round 10
// speedup vs baseline: 5.5339x; 1.0158x over previous
#include <cuda_runtime.h>
#include <cuda_fp16.h>
#include <cstdint>
#include <cstddef>

#define BATCH 2
#define CC 128
#define HW 4096
#define HEADS 4
// 32^-0.5 * log2(e): softmax in base-2
#define SCALE2 0.25500526764086436f

// ---------------- scratch ----------------
__device__ float g_mf[BATCH * CC * HW];
__device__ float g_gd[BATCH * CC * HW];
__device__ __align__(16) __half g_qh[BATCH * CC * HW];
__device__ __align__(16) __half g_kh[BATCH * CC * HW];
__device__ __align__(16) __half g_vh[BATCH * CC * HW];

// ---------------- helpers ----------------
__device__ __forceinline__ uint32_t smem_u32(const void* p) {
    uint32_t a;
    asm("{ .reg .u64 t; cvta.to.shared.u64 t, %1; cvt.u32.u64 %0, t; }" : "=r"(a) : "l"(p));
    return a;
}
__device__ __forceinline__ float ex2f(float x) {
    float r; asm("ex2.approx.f32 %0, %1;" : "=f"(r) : "f"(x)); return r;
}
__device__ __forceinline__ uint32_t cvt_f16x2(float hi, float lo) {
    uint32_t r; asm("cvt.rn.f16x2.f32 %0, %1, %2;" : "=r"(r) : "f"(hi), "f"(lo)); return r;
}
__device__ __forceinline__ uint32_t ex2_h2(uint32_t a) {
    uint32_t r; asm("ex2.approx.f16x2 %0, %1;" : "=r"(r) : "r"(a)); return r;
}
__device__ __forceinline__ void ldsm4(uint32_t* r, uint32_t addr) {
    asm volatile("ldmatrix.sync.aligned.m8n8.x4.shared.b16 {%0,%1,%2,%3}, [%4];"
        : "=r"(r[0]), "=r"(r[1]), "=r"(r[2]), "=r"(r[3]) : "r"(addr));
}
__device__ __forceinline__ void ldsm4t(uint32_t* r, uint32_t addr) {
    asm volatile("ldmatrix.sync.aligned.m8n8.x4.trans.shared.b16 {%0,%1,%2,%3}, [%4];"
        : "=r"(r[0]), "=r"(r[1]), "=r"(r[2]), "=r"(r[3]) : "r"(addr));
}
__device__ __forceinline__ void mma16816(float* c, const uint32_t* a, const uint32_t* b) {
    asm volatile("mma.sync.aligned.m16n8k16.row.col.f32.f16.f16.f32 "
        "{%0,%1,%2,%3}, {%4,%5,%6,%7}, {%8,%9}, {%0,%1,%2,%3};"
        : "+f"(c[0]), "+f"(c[1]), "+f"(c[2]), "+f"(c[3])
        : "r"(a[0]), "r"(a[1]), "r"(a[2]), "r"(a[3]), "r"(b[0]), "r"(b[1]));
}
__device__ __forceinline__ void cp16(uint32_t saddr, const void* g) {
    asm volatile("cp.async.cg.shared.global [%0], [%1], 16;" :: "r"(saddr), "l"(g));
}
#define CP_COMMIT() asm volatile("cp.async.commit_group;" ::: "memory")
#define CP_WAIT1()  asm volatile("cp.async.wait_group 1;" ::: "memory")
#define CP_WAIT2()  asm volatile("cp.async.wait_group 2;" ::: "memory")

// ================================================================
// flash attention: fp16 QK/PV, Q fp16 prescaled via cp.async.
// Lazy-max softmax (accumulators init to -m). Intra-tile pipeline:
// PV(half0) interleaved with QK(half1).
// grid (32, HEADS, BATCH), 256 threads (8 warps), warp = 16 queries.
// stage (17408 B): K [32 d][136 j], V [32 d][136 j] at +8704.
// Q tile [32 d][136 q] at +34816 (persistent).
// ================================================================
#define SB_V 8704
#define STAGE 17408
#define SB_Q (2 * STAGE)
#define SBUF_BYTES (SB_Q + 8704)

__global__ void __launch_bounds__(256, 2) attn_mma() {
    __shared__ __align__(16) char sbuf[SBUF_BYTES];
    const int tid = threadIdx.x;
    const int lane = tid & 31;
    const int w = tid >> 5;
    const int h = blockIdx.y, b = blockIdx.z;
    const int qb = blockIdx.x * 128;
    const size_t cbase = ((size_t)b * CC + h * 32) * HW;
    const __half* qgp = g_qh + cbase;
    const __half* kgp = g_kh + cbase;
    const __half* vgp = g_vh + cbase;
    const uint32_t sb = smem_u32(sbuf);

    // ---- cp.async prologue: Q tile (group 0), K/V tiles 0,1 ----
    const int cd = tid >> 3;          // d row 0..31
    const int cjh = (tid & 7) * 16;   // col (halves)
    const uint32_t cpQ = sb + SB_Q + (cd * 136 + cjh) * 2;
    const uint32_t cpK = sb + (cd * 136 + cjh) * 2;
    const uint32_t cpV = sb + SB_V + (cd * 136 + cjh) * 2;
    const __half* gQ = qgp + (size_t)cd * HW + qb + cjh;
    const __half* gK = kgp + (size_t)cd * HW + cjh;
    const __half* gV = vgp + (size_t)cd * HW + cjh;
    cp16(cpQ, gQ); cp16(cpQ + 16, gQ + 8);
    CP_COMMIT();
    cp16(cpK, gK);       cp16(cpK + 16, gK + 8);
    cp16(cpV, gV);       cp16(cpV + 16, gV + 8);
    CP_COMMIT();
    cp16(cpK + STAGE, gK + 128); cp16(cpK + STAGE + 16, gK + 136);
    cp16(cpV + STAGE, gV + 128); cp16(cpV + STAGE + 16, gV + 136);
    CP_COMMIT();

    const int brow = (lane & 7) + ((lane & 16) >> 1);
    const int bcol8 = (lane & 8) ? 8 : 0;

    // ---- Q A-fragments from [d][q] via trans ldsm ----
    CP_WAIT2();
    __syncthreads();
    uint32_t qa[2][4];
#pragma unroll
    for (int ks = 0; ks < 2; ks++)
        ldsm4t(qa[ks], sb + SB_Q + ((ks * 16 + brow) * 136 + w * 16 + bcol8) * 2);

    // constant ones-column B-fragment (l accumulation)
    const uint32_t b2c[2] = { (lane < 4) ? 0x3C003C00u : 0u,
                              (lane < 4) ? 0x3C003C00u : 0u };

    float mrow0 = 0.0f, mrow1 = 0.0f;
    float o[4][4], ol[4];
#pragma unroll
    for (int nt = 0; nt < 4; nt++)
#pragma unroll
        for (int i = 0; i < 4; i++) o[nt][i] = 0.0f;
#pragma unroll
    for (int i = 0; i < 4; i++) ol[i] = 0.0f;

    float s[8][4];
    uint32_t pu[8][2];
    uint32_t base = 0;

    auto s_init = [&]() {
        float ns0 = -mrow0, ns1 = -mrow1;
#pragma unroll
        for (int nt = 0; nt < 8; nt++) {
            s[nt][0] = ns0; s[nt][1] = ns0;
            s[nt][2] = ns1; s[nt][3] = ns1;
        }
    };
    auto qk_piece = [&](int idx, int joff) {
        int ks = idx >> 2, n0 = idx & 3;
        uint32_t bh[4];
        ldsm4t(bh, base + ((ks * 16 + (lane & 15)) * 136 +
                           joff + n0 * 16 + (lane >> 4) * 8) * 2);
        mma16816(s[n0 * 2], qa[ks], bh);
        mma16816(s[n0 * 2 + 1], qa[ks], bh + 2);
    };
    auto pv_piece = [&](int ks, int joff) {
        uint32_t ah[4] = { pu[2 * ks][0], pu[2 * ks][1],
                           pu[2 * ks + 1][0], pu[2 * ks + 1][1] };
#pragma unroll
        for (int n0 = 0; n0 < 2; n0++) {
            uint32_t vh[4];
            ldsm4(vh, base + SB_V + ((n0 * 16 + brow) * 136 +
                                     joff + ks * 16 + bcol8) * 2);
            mma16816(o[n0 * 2], ah, vh);
            mma16816(o[n0 * 2 + 1], ah, vh + 2);
        }
        mma16816(ol, ah, b2c);
    };
    auto softmax = [&]() {
        float mt0 = s[0][0], mt1 = s[0][2];
#pragma unroll
        for (int nt = 0; nt < 8; nt++) {
            mt0 = fmaxf(mt0, fmaxf(s[nt][0], s[nt][1]));
            mt1 = fmaxf(mt1, fmaxf(s[nt][2], s[nt][3]));
        }
        mt0 = fmaxf(mt0, __shfl_xor_sync(0xffffffffu, mt0, 1));
        mt0 = fmaxf(mt0, __shfl_xor_sync(0xffffffffu, mt0, 2));
        mt1 = fmaxf(mt1, __shfl_xor_sync(0xffffffffu, mt1, 1));
        mt1 = fmaxf(mt1, __shfl_xor_sync(0xffffffffu, mt1, 2));
        if (__any_sync(0xffffffffu, (mt0 > 0.0f) || (mt1 > 0.0f))) {
            float d0 = fmaxf(mt0, 0.0f), d1 = fmaxf(mt1, 0.0f);
            float c0 = ex2f(-d0), c1 = ex2f(-d1);
            mrow0 += d0; mrow1 += d1;
#pragma unroll
            for (int nt = 0; nt < 4; nt++) {
                o[nt][0] *= c0; o[nt][1] *= c0;
                o[nt][2] *= c1; o[nt][3] *= c1;
            }
            ol[0] *= c0; ol[1] *= c0; ol[2] *= c1; ol[3] *= c1;
#pragma unroll
            for (int nt = 0; nt < 8; nt++) {
                s[nt][0] -= d0; s[nt][1] -= d0;
                s[nt][2] -= d1; s[nt][3] -= d1;
            }
        }
#pragma unroll
        for (int nt = 0; nt < 8; nt++) {
            pu[nt][0] = ex2_h2(cvt_f16x2(s[nt][1], s[nt][0]));
            pu[nt][1] = ex2_h2(cvt_f16x2(s[nt][3], s[nt][2]));
        }
    };

    for (int t = 0; t < 32; t++) {
        base = sb + (t & 1) * STAGE;
        CP_WAIT1();
        __syncthreads();

        // QK half0
        s_init();
#pragma unroll
        for (int i = 0; i < 8; i++) qk_piece(i, 0);
        softmax();              // -> pu (half0), updates m

        // interleave: PV(half0) || QK(half1)
        {
            // stash pu of half0 in-place (pv_piece reads pu before softmax overwrites)
            float ns0 = -mrow0, ns1 = -mrow1;
            // re-init s for half1 (after softmax consumed it)
#pragma unroll
            for (int nt = 0; nt < 8; nt++) {
                s[nt][0] = ns0; s[nt][1] = ns0;
                s[nt][2] = ns1; s[nt][3] = ns1;
            }
        }
#pragma unroll
        for (int ks = 0; ks < 4; ks++) {
            pv_piece(ks, 0);
            qk_piece(2 * ks, 64);
            qk_piece(2 * ks + 1, 64);
        }
        softmax();              // -> pu (half1)
#pragma unroll
        for (int ks = 0; ks < 4; ks++) pv_piece(ks, 64);

        __syncthreads();
        int tn = t + 2;
        if (tn < 32) {
            const uint32_t so = (t & 1) * STAGE;
            const int go = tn * 128;
            cp16(cpK + so, gK + go);       cp16(cpK + so + 16, gK + go + 8);
            cp16(cpV + so, gV + go);       cp16(cpV + so + 16, gV + go + 8);
        }
        CP_COMMIT();
    }

    // ---------------- finalize ----------------
    float l0 = __shfl_sync(0xffffffffu, ol[0], lane & 28);
    float l1 = __shfl_sync(0xffffffffu, ol[2], lane & 28);
    float i0 = 1.0f / l0, i1 = 1.0f / l1;
    int pix = qb + w * 16 + (lane >> 2);
#pragma unroll
    for (int nt = 0; nt < 4; nt++) {
        int d = nt * 8 + 2 * (lane & 3);
        g_gd[cbase + (size_t)d * HW + pix] = o[nt][0] * i0;
        g_gd[cbase + (size_t)(d + 1) * HW + pix] = o[nt][1] * i0;
        g_gd[cbase + (size_t)d * HW + pix + 8] = o[nt][2] * i1;
        g_gd[cbase + (size_t)(d + 1) * HW + pix + 8] = o[nt][3] * i1;
    }
}

// ================================================================
// merged Q + KV 1x1 conv via HMMA -> fp16 outputs (Q pre-scaled).
// grid (HW/32, BATCH, 2): z=0 -> Q from sr; z=1 -> K,V from g_mf.
// ================================================================
__global__ __launch_bounds__(256) void conv_qkv(
    const float* __restrict__ sr,
    const float* __restrict__ Wq, const float* __restrict__ bq,
    const float* __restrict__ Wk, const float* __restrict__ bk,
    const float* __restrict__ Wv, const float* __restrict__ bv) {
    __shared__ __align__(16) char sbuf[34816];
    const int tid = threadIdx.x;
    const int lane = tid & 31;
    const int w = tid >> 5;
    const int bb = blockIdx.y;
    const int p0 = blockIdx.x * 32;
    const bool dual = (blockIdx.z == 1);
    const float* X  = dual ? g_mf : sr;
    const float* W1 = dual ? Wk : Wq;
    const float* b1 = dual ? bk : bq;
    __half* H1 = dual ? g_kh : g_qh;
    const float hscale = dual ? 1.0f : SCALE2;
    const uint32_t sb = smem_u32(sbuf);
    const int brow = (lane & 7) + ((lane & 16) >> 1);
    const int bcol8 = (lane & 8) ? 8 : 0;

    float4 xreg[4];
#pragma unroll
    for (int i = 0; i < 4; i++) {
        int idx = i * 256 + tid;
        int ci = idx >> 3, px = (idx & 7) * 4;
        xreg[i] = *(const float4*)(X + ((size_t)bb * CC + ci) * HW + p0 + px);
    }

    uint32_t wa1[8][4], wa2[8][4];
    {
#pragma unroll
        for (int i = 0; i < 16; i++) {
            int idx = i * 256 + tid;
            int co = idx >> 5, ci = (idx & 31) * 4;
            float4 v = *(const float4*)(W1 + co * CC + ci);
            __half* d = (__half*)(sbuf) + co * 136 + ci;
            d[0] = __float2half(v.x); d[1] = __float2half(v.y);
            d[2] = __float2half(v.z); d[3] = __float2half(v.w);
        }
        __syncthreads();
        int row = w * 16 + (lane & 15);
        int colb = (lane >> 4) * 8;
#pragma unroll
        for (int ks = 0; ks < 8; ks++)
            ldsm4(wa1[ks], sb + (row * 136 + ks * 16 + colb) * 2);
        __syncthreads();
    }
    if (dual) {
#pragma unroll
        for (int i = 0; i < 16; i++) {
            int idx = i * 256 + tid;
            int co = idx >> 5, ci = (idx & 31) * 4;
            float4 v = *(const float4*)(Wv + co * CC + ci);
            __half* d = (__half*)(sbuf) + co * 136 + ci;
            d[0] = __float2half(v.x); d[1] = __float2half(v.y);
            d[2] = __float2half(v.z); d[3] = __float2half(v.w);
        }
        __syncthreads();
        int row = w * 16 + (lane & 15);
        int colb = (lane >> 4) * 8;
#pragma unroll
        for (int ks = 0; ks < 8; ks++)
            ldsm4(wa2[ks], sb + (row * 136 + ks * 16 + colb) * 2);
        __syncthreads();
    }

#pragma unroll
    for (int i = 0; i < 4; i++) {
        int idx = i * 256 + tid;
        int ci = idx >> 3, px = (idx & 7) * 4;
        float vv[4] = { xreg[i].x, xreg[i].y, xreg[i].z, xreg[i].w };
#pragma unroll
        for (int j = 0; j < 4; j++)
            *((__half*)(sbuf) + (px + j) * 136 + ci) = __float2half(vv[j]);
    }
    __syncthreads();

    float acc1[4][4], acc2[4][4];
#pragma unroll
    for (int nt = 0; nt < 4; nt++)
#pragma unroll
        for (int i = 0; i < 4; i++) { acc1[nt][i] = 0.0f; acc2[nt][i] = 0.0f; }

#pragma unroll
    for (int ks = 0; ks < 8; ks++) {
#pragma unroll
        for (int n0 = 0; n0 < 2; n0++) {
            uint32_t bh[4];
            ldsm4(bh, sb + ((n0 * 16 + brow) * 136 + ks * 16 + bcol8) * 2);
            mma16816(acc1[n0 * 2], wa1[ks], bh);
            mma16816(acc1[n0 * 2 + 1], wa1[ks], bh + 2);
            if (dual) {
                mma16816(acc2[n0 * 2], wa2[ks], bh);
                mma16816(acc2[n0 * 2 + 1], wa2[ks], bh + 2);
            }
        }
    }

    int coA = w * 16 + (lane >> 2);
    int coB = coA + 8;
    float b1A = b1[coA], b1B = b1[coB];
    float b2A = 0.0f, b2B = 0.0f;
    if (dual) { b2A = bv[coA]; b2B = bv[coB]; }
    size_t baseA = ((size_t)bb * CC + coA) * HW + p0;
    size_t baseB = ((size_t)bb * CC + coB) * HW + p0;
#pragma unroll
    for (int nt = 0; nt < 4; nt++) {
        int px = nt * 8 + 2 * (lane & 3);
        *(uint32_t*)(H1 + baseA + px) =
            cvt_f16x2((acc1[nt][1] + b1A) * hscale, (acc1[nt][0] + b1A) * hscale);
        *(uint32_t*)(H1 + baseB + px) =
            cvt_f16x2((acc1[nt][3] + b1B) * hscale, (acc1[nt][2] + b1B) * hscale);
        if (dual) {
            *(uint32_t*)(g_vh + baseA + px) =
                cvt_f16x2(acc2[nt][1] + b2A, acc2[nt][0] + b2A);
            *(uint32_t*)(g_vh + baseB + px) =
                cvt_f16x2(acc2[nt][3] + b2B, acc2[nt][2] + b2B);
        }
    }
}

// ================================================================
// output conv: fp32 2-term X + residual (unchanged numerics).
// ================================================================
__global__ __launch_bounds__(256) void conv_out(
    const float* __restrict__ X,
    const float* __restrict__ W1, const float* __restrict__ b1,
    float* __restrict__ Y1, const float* __restrict__ resid) {
    __shared__ __align__(16) char sbuf[34816];
    const int tid = threadIdx.x;
    const int lane = tid & 31;
    const int w = tid >> 5;
    const int bb = blockIdx.y;
    const int p0 = blockIdx.x * 32;
    const uint32_t sb = smem_u32(sbuf);
    const int brow = (lane & 7) + ((lane & 16) >> 1);
    const int bcol8 = (lane & 8) ? 8 : 0;

    float4 xreg[4];
#pragma unroll
    for (int i = 0; i < 4; i++) {
        int idx = i * 256 + tid;
        int ci = idx >> 3, px = (idx & 7) * 4;
        xreg[i] = *(const float4*)(X + ((size_t)bb * CC + ci) * HW + p0 + px);
    }

    uint32_t wa1[8][4];
    {
#pragma unroll
        for (int i = 0; i < 16; i++) {
            int idx = i * 256 + tid;
            int co = idx >> 5, ci = (idx & 31) * 4;
            float4 v = *(const float4*)(W1 + co * CC + ci);
            __half* d = (__half*)(sbuf) + co * 136 + ci;
            d[0] = __float2half(v.x); d[1] = __float2half(v.y);
            d[2] = __float2half(v.z); d[3] = __float2half(v.w);
        }
        __syncthreads();
        int row = w * 16 + (lane & 15);
        int colb = (lane >> 4) * 8;
#pragma unroll
        for (int ks = 0; ks < 8; ks++)
            ldsm4(wa1[ks], sb + (row * 136 + ks * 16 + colb) * 2);
        __syncthreads();
    }

#pragma unroll
    for (int i = 0; i < 4; i++) {
        int idx = i * 256 + tid;
        int ci = idx >> 3, px = (idx & 7) * 4;
        float vv[4] = { xreg[i].x, xreg[i].y, xreg[i].z, xreg[i].w };
#pragma unroll
        for (int j = 0; j < 4; j++) {
            __half hv = __float2half(vv[j]);
            *((__half*)(sbuf) + (px + j) * 136 + ci) = hv;
            *((__half*)(sbuf + 8704) + (px + j) * 136 + ci) =
                __float2half(vv[j] - __half2float(hv));
        }
    }
    __syncthreads();

    float acc1[4][4];
#pragma unroll
    for (int nt = 0; nt < 4; nt++)
#pragma unroll
        for (int i = 0; i < 4; i++) acc1[nt][i] = 0.0f;

#pragma unroll
    for (int ks = 0; ks < 8; ks++) {
#pragma unroll
        for (int n0 = 0; n0 < 2; n0++) {
            uint32_t bh[4], bl[4];
            uint32_t a = sb + ((n0 * 16 + brow) * 136 + ks * 16 + bcol8) * 2;
            ldsm4(bh, a);
            ldsm4(bl, a + 8704);
            mma16816(acc1[n0 * 2], wa1[ks], bh);
            mma16816(acc1[n0 * 2], wa1[ks], bl);
            mma16816(acc1[n0 * 2 + 1], wa1[ks], bh + 2);
            mma16816(acc1[n0 * 2 + 1], wa1[ks], bl + 2);
        }
    }

    int coA = w * 16 + (lane >> 2);
    int coB = coA + 8;
    float b1A = b1[coA], b1B = b1[coB];
    size_t baseA = ((size_t)bb * CC + coA) * HW + p0;
    size_t baseB = ((size_t)bb * CC + coB) * HW + p0;
#pragma unroll
    for (int nt = 0; nt < 4; nt++) {
        int px = nt * 8 + 2 * (lane & 3);
        float2 rA = *(const float2*)(resid + baseA + px);
        float2 rB = *(const float2*)(resid + baseB + px);
        *(float2*)(Y1 + baseA + px) =
            make_float2(acc1[nt][0] + b1A + rA.x, acc1[nt][1] + b1A + rA.y);
        *(float2*)(Y1 + baseB + px) =
            make_float2(acc1[nt][2] + b1B + rB.x, acc1[nt][3] + b1B + rB.y);
    }
}

// ================= fused mask convs: seg -> relu(conv3x3) -> conv3x3 =========
__global__ __launch_bounds__(256) void mask_fused(const float* __restrict__ seg,
                                                  const float* __restrict__ Wm1,
                                                  const float* __restrict__ bm1,
                                                  const float* __restrict__ Wm2,
                                                  const float* __restrict__ bm2) {
    int y = blockIdx.x, b = blockIdx.y;
    __shared__ float sseg[5][66];
    __shared__ float sm[32][3][66];
    const float* sgb = seg + (size_t)b * HW;
    for (int i = threadIdx.x; i < 5 * 66; i += 256) {
        int r = i / 66, x = i % 66;
        int yy = y + r - 2, xx = x - 1;
        sseg[r][x] = (yy >= 0 && yy < 64 && xx >= 0 && xx < 64)
                     ? sgb[yy * 64 + xx] : 0.0f;
    }
    __syncthreads();
    for (int i = threadIdx.x; i < 32 * 3 * 66; i += 256) {
        int c = i / 198, rem = i % 198, r = rem / 66, x = rem % 66;
        int yy = y + r - 1, xx = x - 1;
        float v = 0.0f;
        if (yy >= 0 && yy < 64 && xx >= 0 && xx < 64) {
            float acc = bm1[c];
            const float* wp = Wm1 + c * 9;
#pragma unroll
            for (int dy = 0; dy < 3; dy++)
#pragma unroll
                for (int dx = 0; dx < 3; dx++)
                    acc += wp[dy * 3 + dx] * sseg[r + dy][x + dx - 1];
            v = fmaxf(acc, 0.0f);
        }
        sm[c][r][x] = v;
    }
    __syncthreads();
    int co = threadIdx.x >> 1;
    int xh = (threadIdx.x & 1) * 32;
    float acc[32];
    float bb = bm2[co];
#pragma unroll
    for (int px = 0; px < 32; px++) acc[px] = bb;
    const float* w = Wm2 + co * 288;
    for (int ci = 0; ci < 32; ci++) {
#pragma unroll
        for (int r = 0; r < 3; r++) {
            const float* row = &sm[ci][r][xh];
            float rv[34];
#pragma unroll
            for (int t = 0; t < 34; t++) rv[t] = row[t];
#pragma unroll
            for (int dx = 0; dx < 3; dx++) {
                float wv = w[(ci * 3 + r) * 3 + dx];
#pragma unroll
                for (int px = 0; px < 32; px++) acc[px] += wv * rv[px + dx];
            }
        }
    }
    float* out = g_mf + ((size_t)b * CC + co) * HW + y * 64 + xh;
#pragma unroll
    for (int px = 0; px < 32; px++) out[px] = acc[px];
}

// ---------------- launch ----------------
extern "C" void kernel_launch(void* const* d_in, const int* in_sizes, int n_in,
                              void* d_out, int out_size) {
    const float* sr  = (const float*)d_in[0];
    const float* seg = (const float*)d_in[1];
    const float* Wq  = (const float*)d_in[2];
    const float* bq  = (const float*)d_in[3];
    const float* Wm1 = (const float*)d_in[4];
    const float* bm1 = (const float*)d_in[5];
    const float* Wm2 = (const float*)d_in[6];
    const float* bm2 = (const float*)d_in[7];
    const float* Wk  = (const float*)d_in[8];
    const float* bk  = (const float*)d_in[9];
    const float* Wv  = (const float*)d_in[10];
    const float* bv  = (const float*)d_in[11];
    const float* Wo  = (const float*)d_in[12];
    const float* bo  = (const float*)d_in[13];
    float* out = (float*)d_out;

    float* pg;
    cudaGetSymbolAddress((void**)&pg, g_gd);

    mask_fused<<<dim3(64, BATCH), 256>>>(seg, Wm1, bm1, Wm2, bm2);
    conv_qkv<<<dim3(HW / 32, BATCH, 2), 256>>>(sr, Wq, bq, Wk, bk, Wv, bv);
    attn_mma<<<dim3(32, HEADS, BATCH), 256>>>();
    conv_out<<<dim3(HW / 32, BATCH), 256>>>(pg, Wo, bo, out, sr);
}

// round 11
// speedup vs baseline: 6.0399x; 1.0914x over previous
#include <cuda_runtime.h>
#include <cuda_fp16.h>
#include <cstdint>
#include <cstddef>

#define BATCH 2
#define CC 128
#define HW 4096
#define HEADS 4
// 32^-0.5 * log2(e): softmax in base-2
#define SCALE2 0.25500526764086436f

// ---------------- scratch ----------------
__device__ float g_mf[BATCH * CC * HW];
__device__ float g_gd[BATCH * CC * HW];
__device__ __align__(16) __half g_qh[BATCH * CC * HW];
__device__ __align__(16) __half g_kh[BATCH * CC * HW];
__device__ __align__(16) __half g_vh[BATCH * CC * HW];

// ---------------- helpers ----------------
__device__ __forceinline__ uint32_t smem_u32(const void* p) {
    uint32_t a;
    asm("{ .reg .u64 t; cvta.to.shared.u64 t, %1; cvt.u32.u64 %0, t; }" : "=r"(a) : "l"(p));
    return a;
}
__device__ __forceinline__ float ex2f(float x) {
    float r; asm("ex2.approx.f32 %0, %1;" : "=f"(r) : "f"(x)); return r;
}
__device__ __forceinline__ uint32_t cvt_f16x2(float hi, float lo) {
    uint32_t r; asm("cvt.rn.f16x2.f32 %0, %1, %2;" : "=r"(r) : "f"(hi), "f"(lo)); return r;
}
__device__ __forceinline__ uint32_t ex2_h2(uint32_t a) {
    uint32_t r; asm("ex2.approx.f16x2 %0, %1;" : "=r"(r) : "r"(a)); return r;
}
__device__ __forceinline__ void ldsm4(uint32_t* r, uint32_t addr) {
    asm volatile("ldmatrix.sync.aligned.m8n8.x4.shared.b16 {%0,%1,%2,%3}, [%4];"
        : "=r"(r[0]), "=r"(r[1]), "=r"(r[2]), "=r"(r[3]) : "r"(addr));
}
__device__ __forceinline__ void ldsm4t(uint32_t* r, uint32_t addr) {
    asm volatile("ldmatrix.sync.aligned.m8n8.x4.trans.shared.b16 {%0,%1,%2,%3}, [%4];"
        : "=r"(r[0]), "=r"(r[1]), "=r"(r[2]), "=r"(r[3]) : "r"(addr));
}
__device__ __forceinline__ void mma16816(float* c, const uint32_t* a, const uint32_t* b) {
    asm volatile("mma.sync.aligned.m16n8k16.row.col.f32.f16.f16.f32 "
        "{%0,%1,%2,%3}, {%4,%5,%6,%7}, {%8,%9}, {%0,%1,%2,%3};"
        : "+f"(c[0]), "+f"(c[1]), "+f"(c[2]), "+f"(c[3])
        : "r"(a[0]), "r"(a[1]), "r"(a[2]), "r"(a[3]), "r"(b[0]), "r"(b[1]));
}
__device__ __forceinline__ void cp16(uint32_t saddr, const void* g) {
    asm volatile("cp.async.cg.shared.global [%0], [%1], 16;" :: "r"(saddr), "l"(g));
}
#define CP_COMMIT() asm volatile("cp.async.commit_group;" ::: "memory")
#define CP_WAIT1()  asm volatile("cp.async.wait_group 1;" ::: "memory")
#define CP_WAIT2()  asm volatile("cp.async.wait_group 2;" ::: "memory")

// ================================================================
// flash attention: fp16 QK/PV, Q fp16 prescaled via cp.async.
// Lazy-max softmax with threshold-8 trigger; shuffles only in the
// (rare) rescale branch. 3-stage cp.async ring -> single barrier/tile.
// grid (32, HEADS, BATCH), 256 threads (8 warps), warp = 16 queries.
// per-stage (17408 B): K [32 d][136 j] at +0, V at +8704.
// Q tile [32 d][136 q] persistent after the 3 stages. Dynamic smem.
// ================================================================
#define STAGE 17408
#define NSTAGE 3
#define SB_Q (NSTAGE * STAGE)              // 52224
#define SBUF_BYTES (SB_Q + 8704)           // 60928

__global__ void __launch_bounds__(256, 2) attn_mma() {
    extern __shared__ __align__(16) char sbuf[];
    const int tid = threadIdx.x;
    const int lane = tid & 31;
    const int w = tid >> 5;
    const int h = blockIdx.y, b = blockIdx.z;
    const int qb = blockIdx.x * 128;
    const size_t cbase = ((size_t)b * CC + h * 32) * HW;
    const __half* qgp = g_qh + cbase;
    const __half* kgp = g_kh + cbase;
    const __half* vgp = g_vh + cbase;
    const uint32_t sb = smem_u32(sbuf);

    // ---- cp.async prologue: Q (group0), K/V tile0 (group1), tile1 (group2) --
    const int cd = tid >> 3;          // d row 0..31
    const int cjh = (tid & 7) * 16;   // col (halves)
    const uint32_t offK = (uint32_t)(cd * 136 + cjh) * 2;        // intra-stage
    const uint32_t offV = 8704u + offK;
    const __half* gQ = qgp + (size_t)cd * HW + qb + cjh;
    const __half* gK = kgp + (size_t)cd * HW + cjh;
    const __half* gV = vgp + (size_t)cd * HW + cjh;
    cp16(sb + SB_Q + offK, gQ); cp16(sb + SB_Q + offK + 16, gQ + 8);
    CP_COMMIT();
    cp16(sb + offK, gK);       cp16(sb + offK + 16, gK + 8);
    cp16(sb + offV, gV);       cp16(sb + offV + 16, gV + 8);
    CP_COMMIT();
    cp16(sb + STAGE + offK, gK + 128); cp16(sb + STAGE + offK + 16, gK + 136);
    cp16(sb + STAGE + offV, gV + 128); cp16(sb + STAGE + offV + 16, gV + 136);
    CP_COMMIT();

    const int brow = (lane & 7) + ((lane & 16) >> 1);
    const int bcol8 = (lane & 8) ? 8 : 0;

    // ---- Q A-fragments from [d][q] via trans ldsm ----
    CP_WAIT2();
    __syncthreads();
    uint32_t qa[2][4];
#pragma unroll
    for (int ks = 0; ks < 2; ks++)
        ldsm4t(qa[ks], sb + SB_Q + ((ks * 16 + brow) * 136 + w * 16 + bcol8) * 2);

    // constant ones-column B-fragment (l accumulation)
    const uint32_t b2c[2] = { (lane < 4) ? 0x3C003C00u : 0u,
                              (lane < 4) ? 0x3C003C00u : 0u };

    float mrow0 = 0.0f, mrow1 = 0.0f;
    float o[4][4], ol[4];
#pragma unroll
    for (int nt = 0; nt < 4; nt++)
#pragma unroll
        for (int i = 0; i < 4; i++) o[nt][i] = 0.0f;
#pragma unroll
    for (int i = 0; i < 4; i++) ol[i] = 0.0f;

    float s[8][4];
    uint32_t pu[8][2];
    uint32_t base = 0;

    auto s_init = [&]() {
        float ns0 = -mrow0, ns1 = -mrow1;
#pragma unroll
        for (int nt = 0; nt < 8; nt++) {
            s[nt][0] = ns0; s[nt][1] = ns0;
            s[nt][2] = ns1; s[nt][3] = ns1;
        }
    };
    auto qk_piece = [&](int idx, int joff) {
        int ks = idx >> 2, n0 = idx & 3;
        uint32_t bh[4];
        ldsm4t(bh, base + ((ks * 16 + (lane & 15)) * 136 +
                           joff + n0 * 16 + (lane >> 4) * 8) * 2);
        mma16816(s[n0 * 2], qa[ks], bh);
        mma16816(s[n0 * 2 + 1], qa[ks], bh + 2);
    };
    auto pv_piece = [&](int ks, int joff) {
        uint32_t ah[4] = { pu[2 * ks][0], pu[2 * ks][1],
                           pu[2 * ks + 1][0], pu[2 * ks + 1][1] };
#pragma unroll
        for (int n0 = 0; n0 < 2; n0++) {
            uint32_t vh[4];
            ldsm4(vh, base + 8704 + ((n0 * 16 + brow) * 136 +
                                     joff + ks * 16 + bcol8) * 2);
            mma16816(o[n0 * 2], ah, vh);
            mma16816(o[n0 * 2 + 1], ah, vh + 2);
        }
        mma16816(ol, ah, b2c);
    };
    // Lazy softmax: fast path has NO cross-lane reduction. Rescale fires
    // only when a local max exceeds 8 (fp16 p headroom is 16 in log2).
    auto softmax = [&]() {
        float mt0 = s[0][0], mt1 = s[0][2];
#pragma unroll
        for (int nt = 0; nt < 8; nt++) {
            mt0 = fmaxf(mt0, fmaxf(s[nt][0], s[nt][1]));
            mt1 = fmaxf(mt1, fmaxf(s[nt][2], s[nt][3]));
        }
        if (__any_sync(0xffffffffu, fmaxf(mt0, mt1) > 8.0f)) {
            mt0 = fmaxf(mt0, __shfl_xor_sync(0xffffffffu, mt0, 1));
            mt0 = fmaxf(mt0, __shfl_xor_sync(0xffffffffu, mt0, 2));
            mt1 = fmaxf(mt1, __shfl_xor_sync(0xffffffffu, mt1, 1));
            mt1 = fmaxf(mt1, __shfl_xor_sync(0xffffffffu, mt1, 2));
            float d0 = fmaxf(mt0, 0.0f), d1 = fmaxf(mt1, 0.0f);
            float c0 = ex2f(-d0), c1 = ex2f(-d1);
            mrow0 += d0; mrow1 += d1;
#pragma unroll
            for (int nt = 0; nt < 4; nt++) {
                o[nt][0] *= c0; o[nt][1] *= c0;
                o[nt][2] *= c1; o[nt][3] *= c1;
            }
            ol[0] *= c0; ol[1] *= c0; ol[2] *= c1; ol[3] *= c1;
#pragma unroll
            for (int nt = 0; nt < 8; nt++) {
                s[nt][0] -= d0; s[nt][1] -= d0;
                s[nt][2] -= d1; s[nt][3] -= d1;
            }
        }
#pragma unroll
        for (int nt = 0; nt < 8; nt++) {
            pu[nt][0] = ex2_h2(cvt_f16x2(s[nt][1], s[nt][0]));
            pu[nt][1] = ex2_h2(cvt_f16x2(s[nt][3], s[nt][2]));
        }
    };

    int st = 0;  // stage index (t % 3)
    for (int t = 0; t < 32; t++) {
        base = sb + (uint32_t)st * STAGE;
        CP_WAIT1();
        __syncthreads();   // single barrier per tile (3-stage ring)

        // QK half0
        s_init();
#pragma unroll
        for (int i = 0; i < 8; i++) qk_piece(i, 0);
        softmax();              // -> pu (half0)

        // re-init s for half1, then interleave PV(half0) || QK(half1)
        {
            float ns0 = -mrow0, ns1 = -mrow1;
#pragma unroll
            for (int nt = 0; nt < 8; nt++) {
                s[nt][0] = ns0; s[nt][1] = ns0;
                s[nt][2] = ns1; s[nt][3] = ns1;
            }
        }
#pragma unroll
        for (int ks = 0; ks < 4; ks++) {
            pv_piece(ks, 0);
            qk_piece(2 * ks, 64);
            qk_piece(2 * ks + 1, 64);
        }
        softmax();              // -> pu (half1)
#pragma unroll
        for (int ks = 0; ks < 4; ks++) pv_piece(ks, 64);

        // prefetch tile t+2 into stage (st+2)%3 — no barrier needed:
        // all warps are inside iteration t (top barrier), reading stage st.
        int tn = t + 2;
        if (tn < 32) {
            int sd = st + 2; if (sd >= NSTAGE) sd -= NSTAGE;
            const uint32_t so = sb + (uint32_t)sd * STAGE;
            const int go = tn * 128;
            cp16(so + offK, gK + go);       cp16(so + offK + 16, gK + go + 8);
            cp16(so + offV, gV + go);       cp16(so + offV + 16, gV + go + 8);
        }
        CP_COMMIT();
        st = (st == NSTAGE - 1) ? 0 : st + 1;
    }

    // ---------------- finalize ----------------
    float l0 = __shfl_sync(0xffffffffu, ol[0], lane & 28);
    float l1 = __shfl_sync(0xffffffffu, ol[2], lane & 28);
    float i0 = 1.0f / l0, i1 = 1.0f / l1;
    int pix = qb + w * 16 + (lane >> 2);
#pragma unroll
    for (int nt = 0; nt < 4; nt++) {
        int d = nt * 8 + 2 * (lane & 3);
        g_gd[cbase + (size_t)d * HW + pix] = o[nt][0] * i0;
        g_gd[cbase + (size_t)(d + 1) * HW + pix] = o[nt][1] * i0;
        g_gd[cbase + (size_t)d * HW + pix + 8] = o[nt][2] * i1;
        g_gd[cbase + (size_t)(d + 1) * HW + pix + 8] = o[nt][3] * i1;
    }
}

// ================================================================
// merged Q + KV 1x1 conv via HMMA -> fp16 outputs (Q pre-scaled).
// grid (HW/32, BATCH, 2): z=0 -> Q from sr; z=1 -> K,V from g_mf.
// ================================================================
__global__ __launch_bounds__(256) void conv_qkv(
    const float* __restrict__ sr,
    const float* __restrict__ Wq, const float* __restrict__ bq,
    const float* __restrict__ Wk, const float* __restrict__ bk,
    const float* __restrict__ Wv, const float* __restrict__ bv) {
    __shared__ __align__(16) char sbufc[34816];
    const int tid = threadIdx.x;
    const int lane = tid & 31;
    const int w = tid >> 5;
    const int bb = blockIdx.y;
    const int p0 = blockIdx.x * 32;
    const bool dual = (blockIdx.z == 1);
    const float* X  = dual ? g_mf : sr;
    const float* W1 = dual ? Wk : Wq;
    const float* b1 = dual ? bk : bq;
    __half* H1 = dual ? g_kh : g_qh;
    const float hscale = dual ? 1.0f : SCALE2;
    const uint32_t sb = smem_u32(sbufc);
    const int brow = (lane & 7) + ((lane & 16) >> 1);
    const int bcol8 = (lane & 8) ? 8 : 0;

    float4 xreg[4];
#pragma unroll
    for (int i = 0; i < 4; i++) {
        int idx = i * 256 + tid;
        int ci = idx >> 3, px = (idx & 7) * 4;
        xreg[i] = *(const float4*)(X + ((size_t)bb * CC + ci) * HW + p0 + px);
    }

    uint32_t wa1[8][4], wa2[8][4];
    {
#pragma unroll
        for (int i = 0; i < 16; i++) {
            int idx = i * 256 + tid;
            int co = idx >> 5, ci = (idx & 31) * 4;
            float4 v = *(const float4*)(W1 + co * CC + ci);
            __half* d = (__half*)(sbufc) + co * 136 + ci;
            d[0] = __float2half(v.x); d[1] = __float2half(v.y);
            d[2] = __float2half(v.z); d[3] = __float2half(v.w);
        }
        __syncthreads();
        int row = w * 16 + (lane & 15);
        int colb = (lane >> 4) * 8;
#pragma unroll
        for (int ks = 0; ks < 8; ks++)
            ldsm4(wa1[ks], sb + (row * 136 + ks * 16 + colb) * 2);
        __syncthreads();
    }
    if (dual) {
#pragma unroll
        for (int i = 0; i < 16; i++) {
            int idx = i * 256 + tid;
            int co = idx >> 5, ci = (idx & 31) * 4;
            float4 v = *(const float4*)(Wv + co * CC + ci);
            __half* d = (__half*)(sbufc) + co * 136 + ci;
            d[0] = __float2half(v.x); d[1] = __float2half(v.y);
            d[2] = __float2half(v.z); d[3] = __float2half(v.w);
        }
        __syncthreads();
        int row = w * 16 + (lane & 15);
        int colb = (lane >> 4) * 8;
#pragma unroll
        for (int ks = 0; ks < 8; ks++)
            ldsm4(wa2[ks], sb + (row * 136 + ks * 16 + colb) * 2);
        __syncthreads();
    }

#pragma unroll
    for (int i = 0; i < 4; i++) {
        int idx = i * 256 + tid;
        int ci = idx >> 3, px = (idx & 7) * 4;
        float vv[4] = { xreg[i].x, xreg[i].y, xreg[i].z, xreg[i].w };
#pragma unroll
        for (int j = 0; j < 4; j++)
            *((__half*)(sbufc) + (px + j) * 136 + ci) = __float2half(vv[j]);
    }
    __syncthreads();

    float acc1[4][4], acc2[4][4];
#pragma unroll
    for (int nt = 0; nt < 4; nt++)
#pragma unroll
        for (int i = 0; i < 4; i++) { acc1[nt][i] = 0.0f; acc2[nt][i] = 0.0f; }

#pragma unroll
    for (int ks = 0; ks < 8; ks++) {
#pragma unroll
        for (int n0 = 0; n0 < 2; n0++) {
            uint32_t bh[4];
            ldsm4(bh, sb + ((n0 * 16 + brow) * 136 + ks * 16 + bcol8) * 2);
            mma16816(acc1[n0 * 2], wa1[ks], bh);
            mma16816(acc1[n0 * 2 + 1], wa1[ks], bh + 2);
            if (dual) {
                mma16816(acc2[n0 * 2], wa2[ks], bh);
                mma16816(acc2[n0 * 2 + 1], wa2[ks], bh + 2);
            }
        }
    }

    int coA = w * 16 + (lane >> 2);
    int coB = coA + 8;
    float b1A = b1[coA], b1B = b1[coB];
    float b2A = 0.0f, b2B = 0.0f;
    if (dual) { b2A = bv[coA]; b2B = bv[coB]; }
    size_t baseA = ((size_t)bb * CC + coA) * HW + p0;
    size_t baseB = ((size_t)bb * CC + coB) * HW + p0;
#pragma unroll
    for (int nt = 0; nt < 4; nt++) {
        int px = nt * 8 + 2 * (lane & 3);
        *(uint32_t*)(H1 + baseA + px) =
            cvt_f16x2((acc1[nt][1] + b1A) * hscale, (acc1[nt][0] + b1A) * hscale);
        *(uint32_t*)(H1 + baseB + px) =
            cvt_f16x2((acc1[nt][3] + b1B) * hscale, (acc1[nt][2] + b1B) * hscale);
        if (dual) {
            *(uint32_t*)(g_vh + baseA + px) =
                cvt_f16x2(acc2[nt][1] + b2A, acc2[nt][0] + b2A);
            *(uint32_t*)(g_vh + baseB + px) =
                cvt_f16x2(acc2[nt][3] + b2B, acc2[nt][2] + b2B);
        }
    }
}

// ================================================================
// output conv: fp32 2-term X + residual.
// ================================================================
__global__ __launch_bounds__(256) void conv_out(
    const float* __restrict__ X,
    const float* __restrict__ W1, const float* __restrict__ b1,
    float* __restrict__ Y1, const float* __restrict__ resid) {
    __shared__ __align__(16) char sbufc[34816];
    const int tid = threadIdx.x;
    const int lane = tid & 31;
    const int w = tid >> 5;
    const int bb = blockIdx.y;
    const int p0 = blockIdx.x * 32;
    const uint32_t sb = smem_u32(sbufc);
    const int brow = (lane & 7) + ((lane & 16) >> 1);
    const int bcol8 = (lane & 8) ? 8 : 0;

    float4 xreg[4];
#pragma unroll
    for (int i = 0; i < 4; i++) {
        int idx = i * 256 + tid;
        int ci = idx >> 3, px = (idx & 7) * 4;
        xreg[i] = *(const float4*)(X + ((size_t)bb * CC + ci) * HW + p0 + px);
    }

    uint32_t wa1[8][4];
    {
#pragma unroll
        for (int i = 0; i < 16; i++) {
            int idx = i * 256 + tid;
            int co = idx >> 5, ci = (idx & 31) * 4;
            float4 v = *(const float4*)(W1 + co * CC + ci);
            __half* d = (__half*)(sbufc) + co * 136 + ci;
            d[0] = __float2half(v.x); d[1] = __float2half(v.y);
            d[2] = __float2half(v.z); d[3] = __float2half(v.w);
        }
        __syncthreads();
        int row = w * 16 + (lane & 15);
        int colb = (lane >> 4) * 8;
#pragma unroll
        for (int ks = 0; ks < 8; ks++)
            ldsm4(wa1[ks], sb + (row * 136 + ks * 16 + colb) * 2);
        __syncthreads();
    }

#pragma unroll
    for (int i = 0; i < 4; i++) {
        int idx = i * 256 + tid;
        int ci = idx >> 3, px = (idx & 7) * 4;
        float vv[4] = { xreg[i].x, xreg[i].y, xreg[i].z, xreg[i].w };
#pragma unroll
        for (int j = 0; j < 4; j++) {
            __half hv = __float2half(vv[j]);
            *((__half*)(sbufc) + (px + j) * 136 + ci) = hv;
            *((__half*)(sbufc + 8704) + (px + j) * 136 + ci) =
                __float2half(vv[j] - __half2float(hv));
        }
    }
    __syncthreads();

    float acc1[4][4];
#pragma unroll
    for (int nt = 0; nt < 4; nt++)
#pragma unroll
        for (int i = 0; i < 4; i++) acc1[nt][i] = 0.0f;

#pragma unroll
    for (int ks = 0; ks < 8; ks++) {
#pragma unroll
        for (int n0 = 0; n0 < 2; n0++) {
            uint32_t bh[4], bl[4];
            uint32_t a = sb + ((n0 * 16 + brow) * 136 + ks * 16 + bcol8) * 2;
            ldsm4(bh, a);
            ldsm4(bl, a + 8704);
            mma16816(acc1[n0 * 2], wa1[ks], bh);
            mma16816(acc1[n0 * 2], wa1[ks], bl);
            mma16816(acc1[n0 * 2 + 1], wa1[ks], bh + 2);
            mma16816(acc1[n0 * 2 + 1], wa1[ks], bl + 2);
        }
    }

    int coA = w * 16 + (lane >> 2);
    int coB = coA + 8;
    float b1A = b1[coA], b1B = b1[coB];
    size_t baseA = ((size_t)bb * CC + coA) * HW + p0;
    size_t baseB = ((size_t)bb * CC + coB) * HW + p0;
#pragma unroll
    for (int nt = 0; nt < 4; nt++) {
        int px = nt * 8 + 2 * (lane & 3);
        float2 rA = *(const float2*)(resid + baseA + px);
        float2 rB = *(const float2*)(resid + baseB + px);
        *(float2*)(Y1 + baseA + px) =
            make_float2(acc1[nt][0] + b1A + rA.x, acc1[nt][1] + b1A + rA.y);
        *(float2*)(Y1 + baseB + px) =
            make_float2(acc1[nt][2] + b1B + rB.x, acc1[nt][3] + b1B + rB.y);
    }
}

// ================= fused mask convs: seg -> relu(conv3x3) -> conv3x3 =========
__global__ __launch_bounds__(256) void mask_fused(const float* __restrict__ seg,
                                                  const float* __restrict__ Wm1,
                                                  const float* __restrict__ bm1,
                                                  const float* __restrict__ Wm2,
                                                  const float* __restrict__ bm2) {
    int y = blockIdx.x, b = blockIdx.y;
    __shared__ float sseg[5][66];
    __shared__ float sm[32][3][66];
    const float* sgb = seg + (size_t)b * HW;
    for (int i = threadIdx.x; i < 5 * 66; i += 256) {
        int r = i / 66, x = i % 66;
        int yy = y + r - 2, xx = x - 1;
        sseg[r][x] = (yy >= 0 && yy < 64 && xx >= 0 && xx < 64)
                     ? sgb[yy * 64 + xx] : 0.0f;
    }
    __syncthreads();
    for (int i = threadIdx.x; i < 32 * 3 * 66; i += 256) {
        int c = i / 198, rem = i % 198, r = rem / 66, x = rem % 66;
        int yy = y + r - 1, xx = x - 1;
        float v = 0.0f;
        if (yy >= 0 && yy < 64 && xx >= 0 && xx < 64) {
            float acc = bm1[c];
            const float* wp = Wm1 + c * 9;
#pragma unroll
            for (int dy = 0; dy < 3; dy++)
#pragma unroll
                for (int dx = 0; dx < 3; dx++)
                    acc += wp[dy * 3 + dx] * sseg[r + dy][x + dx - 1];
            v = fmaxf(acc, 0.0f);
        }
        sm[c][r][x] = v;
    }
    __syncthreads();
    int co = threadIdx.x >> 1;
    int xh = (threadIdx.x & 1) * 32;
    float acc[32];
    float bb = bm2[co];
#pragma unroll
    for (int px = 0; px < 32; px++) acc[px] = bb;
    const float* w = Wm2 + co * 288;
    for (int ci = 0; ci < 32; ci++) {
#pragma unroll
        for (int r = 0; r < 3; r++) {
            const float* row = &sm[ci][r][xh];
            float rv[34];
#pragma unroll
            for (int t = 0; t < 34; t++) rv[t] = row[t];
#pragma unroll
            for (int dx = 0; dx < 3; dx++) {
                float wv = w[(ci * 3 + r) * 3 + dx];
#pragma unroll
                for (int px = 0; px < 32; px++) acc[px] += wv * rv[px + dx];
            }
        }
    }
    float* out = g_mf + ((size_t)b * CC + co) * HW + y * 64 + xh;
#pragma unroll
    for (int px = 0; px < 32; px++) out[px] = acc[px];
}

// ---------------- launch ----------------
extern "C" void kernel_launch(void* const* d_in, const int* in_sizes, int n_in,
                              void* d_out, int out_size) {
    const float* sr  = (const float*)d_in[0];
    const float* seg = (const float*)d_in[1];
    const float* Wq  = (const float*)d_in[2];
    const float* bq  = (const float*)d_in[3];
    const float* Wm1 = (const float*)d_in[4];
    const float* bm1 = (const float*)d_in[5];
    const float* Wm2 = (const float*)d_in[6];
    const float* bm2 = (const float*)d_in[7];
    const float* Wk  = (const float*)d_in[8];
    const float* bk  = (const float*)d_in[9];
    const float* Wv  = (const float*)d_in[10];
    const float* bv  = (const float*)d_in[11];
    const float* Wo  = (const float*)d_in[12];
    const float* bo  = (const float*)d_in[13];
    float* out = (float*)d_out;

    float* pg;
    cudaGetSymbolAddress((void**)&pg, g_gd);

    cudaFuncSetAttribute(attn_mma, cudaFuncAttributeMaxDynamicSharedMemorySize,
                         SBUF_BYTES);

    mask_fused<<<dim3(64, BATCH), 256>>>(seg, Wm1, bm1, Wm2, bm2);
    conv_qkv<<<dim3(HW / 32, BATCH, 2), 256>>>(sr, Wq, bq, Wk, bk, Wv, bv);
    attn_mma<<<dim3(32, HEADS, BATCH), 256, SBUF_BYTES>>>();
    conv_out<<<dim3(HW / 32, BATCH), 256>>>(pg, Wo, bo, out, sr);
}

// round 12
// speedup vs baseline: 6.4010x; 1.0598x over previous
#include <cuda_runtime.h>
#include <cuda_fp16.h>
#include <cstdint>
#include <cstddef>

#define BATCH 2
#define CC 128
#define HW 4096
#define HEADS 4
// 32^-0.5 * log2(e): softmax in base-2
#define SCALE2 0.25500526764086436f

// ---------------- scratch ----------------
__device__ float g_mf[BATCH * CC * HW];
__device__ float g_gd[BATCH * CC * HW];
__device__ __align__(16) __half g_qh[BATCH * CC * HW];
__device__ __align__(16) __half g_kh[BATCH * CC * HW];
__device__ __align__(16) __half g_vh[BATCH * CC * HW];

// ---------------- helpers ----------------
typedef unsigned long long ull;
__device__ __forceinline__ ull pk2(float a, float b) {
    ull r; asm("mov.b64 %0, {%1, %2};" : "=l"(r) : "f"(a), "f"(b)); return r;
}
__device__ __forceinline__ void upk2(ull v, float& a, float& b) {
    asm("mov.b64 {%0, %1}, %2;" : "=f"(a), "=f"(b) : "l"(v));
}
__device__ __forceinline__ ull fma2(ull a, ull b, ull c) {
    ull d; asm("fma.rn.f32x2 %0, %1, %2, %3;" : "=l"(d) : "l"(a), "l"(b), "l"(c)); return d;
}
__device__ __forceinline__ uint32_t smem_u32(const void* p) {
    uint32_t a;
    asm("{ .reg .u64 t; cvta.to.shared.u64 t, %1; cvt.u32.u64 %0, t; }" : "=r"(a) : "l"(p));
    return a;
}
__device__ __forceinline__ float ex2f(float x) {
    float r; asm("ex2.approx.f32 %0, %1;" : "=f"(r) : "f"(x)); return r;
}
__device__ __forceinline__ uint32_t cvt_f16x2(float hi, float lo) {
    uint32_t r; asm("cvt.rn.f16x2.f32 %0, %1, %2;" : "=r"(r) : "f"(hi), "f"(lo)); return r;
}
__device__ __forceinline__ uint32_t ex2_h2(uint32_t a) {
    uint32_t r; asm("ex2.approx.f16x2 %0, %1;" : "=r"(r) : "r"(a)); return r;
}
__device__ __forceinline__ void ldsm4(uint32_t* r, uint32_t addr) {
    asm volatile("ldmatrix.sync.aligned.m8n8.x4.shared.b16 {%0,%1,%2,%3}, [%4];"
        : "=r"(r[0]), "=r"(r[1]), "=r"(r[2]), "=r"(r[3]) : "r"(addr));
}
__device__ __forceinline__ void ldsm4t(uint32_t* r, uint32_t addr) {
    asm volatile("ldmatrix.sync.aligned.m8n8.x4.trans.shared.b16 {%0,%1,%2,%3}, [%4];"
        : "=r"(r[0]), "=r"(r[1]), "=r"(r[2]), "=r"(r[3]) : "r"(addr));
}
__device__ __forceinline__ void mma16816(float* c, const uint32_t* a, const uint32_t* b) {
    asm volatile("mma.sync.aligned.m16n8k16.row.col.f32.f16.f16.f32 "
        "{%0,%1,%2,%3}, {%4,%5,%6,%7}, {%8,%9}, {%0,%1,%2,%3};"
        : "+f"(c[0]), "+f"(c[1]), "+f"(c[2]), "+f"(c[3])
        : "r"(a[0]), "r"(a[1]), "r"(a[2]), "r"(a[3]), "r"(b[0]), "r"(b[1]));
}
__device__ __forceinline__ void cp16(uint32_t saddr, const void* g) {
    asm volatile("cp.async.cg.shared.global [%0], [%1], 16;" :: "r"(saddr), "l"(g));
}
#define CP_COMMIT() asm volatile("cp.async.commit_group;" ::: "memory")
#define CP_WAIT1()  asm volatile("cp.async.wait_group 1;" ::: "memory")
#define CP_WAIT2()  asm volatile("cp.async.wait_group 2;" ::: "memory")

// ================================================================
// flash attention (unchanged from R11): fp16 QK/PV, Q fp16 prescaled,
// lazy-max softmax (threshold-8 trigger), 3-stage cp.async ring.
// ================================================================
#define STAGE 17408
#define NSTAGE 3
#define SB_Q (NSTAGE * STAGE)
#define SBUF_BYTES (SB_Q + 8704)

__global__ void __launch_bounds__(256, 2) attn_mma() {
    extern __shared__ __align__(16) char sbuf[];
    const int tid = threadIdx.x;
    const int lane = tid & 31;
    const int w = tid >> 5;
    const int h = blockIdx.y, b = blockIdx.z;
    const int qb = blockIdx.x * 128;
    const size_t cbase = ((size_t)b * CC + h * 32) * HW;
    const __half* qgp = g_qh + cbase;
    const __half* kgp = g_kh + cbase;
    const __half* vgp = g_vh + cbase;
    const uint32_t sb = smem_u32(sbuf);

    const int cd = tid >> 3;
    const int cjh = (tid & 7) * 16;
    const uint32_t offK = (uint32_t)(cd * 136 + cjh) * 2;
    const uint32_t offV = 8704u + offK;
    const __half* gQ = qgp + (size_t)cd * HW + qb + cjh;
    const __half* gK = kgp + (size_t)cd * HW + cjh;
    const __half* gV = vgp + (size_t)cd * HW + cjh;
    cp16(sb + SB_Q + offK, gQ); cp16(sb + SB_Q + offK + 16, gQ + 8);
    CP_COMMIT();
    cp16(sb + offK, gK);       cp16(sb + offK + 16, gK + 8);
    cp16(sb + offV, gV);       cp16(sb + offV + 16, gV + 8);
    CP_COMMIT();
    cp16(sb + STAGE + offK, gK + 128); cp16(sb + STAGE + offK + 16, gK + 136);
    cp16(sb + STAGE + offV, gV + 128); cp16(sb + STAGE + offV + 16, gV + 136);
    CP_COMMIT();

    const int brow = (lane & 7) + ((lane & 16) >> 1);
    const int bcol8 = (lane & 8) ? 8 : 0;

    CP_WAIT2();
    __syncthreads();
    uint32_t qa[2][4];
#pragma unroll
    for (int ks = 0; ks < 2; ks++)
        ldsm4t(qa[ks], sb + SB_Q + ((ks * 16 + brow) * 136 + w * 16 + bcol8) * 2);

    const uint32_t b2c[2] = { (lane < 4) ? 0x3C003C00u : 0u,
                              (lane < 4) ? 0x3C003C00u : 0u };

    float mrow0 = 0.0f, mrow1 = 0.0f;
    float o[4][4], ol[4];
#pragma unroll
    for (int nt = 0; nt < 4; nt++)
#pragma unroll
        for (int i = 0; i < 4; i++) o[nt][i] = 0.0f;
#pragma unroll
    for (int i = 0; i < 4; i++) ol[i] = 0.0f;

    float s[8][4];
    uint32_t pu[8][2];
    uint32_t base = 0;

    auto s_init = [&]() {
        float ns0 = -mrow0, ns1 = -mrow1;
#pragma unroll
        for (int nt = 0; nt < 8; nt++) {
            s[nt][0] = ns0; s[nt][1] = ns0;
            s[nt][2] = ns1; s[nt][3] = ns1;
        }
    };
    auto qk_piece = [&](int idx, int joff) {
        int ks = idx >> 2, n0 = idx & 3;
        uint32_t bh[4];
        ldsm4t(bh, base + ((ks * 16 + (lane & 15)) * 136 +
                           joff + n0 * 16 + (lane >> 4) * 8) * 2);
        mma16816(s[n0 * 2], qa[ks], bh);
        mma16816(s[n0 * 2 + 1], qa[ks], bh + 2);
    };
    auto pv_piece = [&](int ks, int joff) {
        uint32_t ah[4] = { pu[2 * ks][0], pu[2 * ks][1],
                           pu[2 * ks + 1][0], pu[2 * ks + 1][1] };
#pragma unroll
        for (int n0 = 0; n0 < 2; n0++) {
            uint32_t vh[4];
            ldsm4(vh, base + 8704 + ((n0 * 16 + brow) * 136 +
                                     joff + ks * 16 + bcol8) * 2);
            mma16816(o[n0 * 2], ah, vh);
            mma16816(o[n0 * 2 + 1], ah, vh + 2);
        }
        mma16816(ol, ah, b2c);
    };
    auto softmax = [&]() {
        float mt0 = s[0][0], mt1 = s[0][2];
#pragma unroll
        for (int nt = 0; nt < 8; nt++) {
            mt0 = fmaxf(mt0, fmaxf(s[nt][0], s[nt][1]));
            mt1 = fmaxf(mt1, fmaxf(s[nt][2], s[nt][3]));
        }
        if (__any_sync(0xffffffffu, fmaxf(mt0, mt1) > 8.0f)) {
            mt0 = fmaxf(mt0, __shfl_xor_sync(0xffffffffu, mt0, 1));
            mt0 = fmaxf(mt0, __shfl_xor_sync(0xffffffffu, mt0, 2));
            mt1 = fmaxf(mt1, __shfl_xor_sync(0xffffffffu, mt1, 1));
            mt1 = fmaxf(mt1, __shfl_xor_sync(0xffffffffu, mt1, 2));
            float d0 = fmaxf(mt0, 0.0f), d1 = fmaxf(mt1, 0.0f);
            float c0 = ex2f(-d0), c1 = ex2f(-d1);
            mrow0 += d0; mrow1 += d1;
#pragma unroll
            for (int nt = 0; nt < 4; nt++) {
                o[nt][0] *= c0; o[nt][1] *= c0;
                o[nt][2] *= c1; o[nt][3] *= c1;
            }
            ol[0] *= c0; ol[1] *= c0; ol[2] *= c1; ol[3] *= c1;
#pragma unroll
            for (int nt = 0; nt < 8; nt++) {
                s[nt][0] -= d0; s[nt][1] -= d0;
                s[nt][2] -= d1; s[nt][3] -= d1;
            }
        }
#pragma unroll
        for (int nt = 0; nt < 8; nt++) {
            pu[nt][0] = ex2_h2(cvt_f16x2(s[nt][1], s[nt][0]));
            pu[nt][1] = ex2_h2(cvt_f16x2(s[nt][3], s[nt][2]));
        }
    };

    int st = 0;
    for (int t = 0; t < 32; t++) {
        base = sb + (uint32_t)st * STAGE;
        CP_WAIT1();
        __syncthreads();

        s_init();
#pragma unroll
        for (int i = 0; i < 8; i++) qk_piece(i, 0);
        softmax();

        {
            float ns0 = -mrow0, ns1 = -mrow1;
#pragma unroll
            for (int nt = 0; nt < 8; nt++) {
                s[nt][0] = ns0; s[nt][1] = ns0;
                s[nt][2] = ns1; s[nt][3] = ns1;
            }
        }
#pragma unroll
        for (int ks = 0; ks < 4; ks++) {
            pv_piece(ks, 0);
            qk_piece(2 * ks, 64);
            qk_piece(2 * ks + 1, 64);
        }
        softmax();
#pragma unroll
        for (int ks = 0; ks < 4; ks++) pv_piece(ks, 64);

        int tn = t + 2;
        if (tn < 32) {
            int sd = st + 2; if (sd >= NSTAGE) sd -= NSTAGE;
            const uint32_t so = sb + (uint32_t)sd * STAGE;
            const int go = tn * 128;
            cp16(so + offK, gK + go);       cp16(so + offK + 16, gK + go + 8);
            cp16(so + offV, gV + go);       cp16(so + offV + 16, gV + go + 8);
        }
        CP_COMMIT();
        st = (st == NSTAGE - 1) ? 0 : st + 1;
    }

    float l0 = __shfl_sync(0xffffffffu, ol[0], lane & 28);
    float l1 = __shfl_sync(0xffffffffu, ol[2], lane & 28);
    float i0 = 1.0f / l0, i1 = 1.0f / l1;
    int pix = qb + w * 16 + (lane >> 2);
#pragma unroll
    for (int nt = 0; nt < 4; nt++) {
        int d = nt * 8 + 2 * (lane & 3);
        g_gd[cbase + (size_t)d * HW + pix] = o[nt][0] * i0;
        g_gd[cbase + (size_t)(d + 1) * HW + pix] = o[nt][1] * i0;
        g_gd[cbase + (size_t)d * HW + pix + 8] = o[nt][2] * i1;
        g_gd[cbase + (size_t)(d + 1) * HW + pix + 8] = o[nt][3] * i1;
    }
}

// ================================================================
// input 1x1 conv via HMMA -> fp16 outputs. DUAL stages both W matrices
// into disjoint dynamic-smem halves with ONE sync pair.
// grid (HW/32, BATCH), 256 threads, warp = 16 co.
// smem: W1 [0,34816), W2 [34816,69632) (DUAL). X hi reuses [0,8704).
// ================================================================
template<bool DUAL>
__global__ __launch_bounds__(256) void conv_in(
    const float* __restrict__ X,
    const float* __restrict__ W1, const float* __restrict__ b1,
    __half* __restrict__ H1, float hscale,
    const float* __restrict__ W2, const float* __restrict__ b2,
    __half* __restrict__ H2) {
    extern __shared__ __align__(16) char dsm[];
    const int tid = threadIdx.x;
    const int lane = tid & 31;
    const int w = tid >> 5;
    const int bb = blockIdx.y;
    const int p0 = blockIdx.x * 32;
    const uint32_t sb = smem_u32(dsm);
    const int brow = (lane & 7) + ((lane & 16) >> 1);
    const int bcol8 = (lane & 8) ? 8 : 0;

    // X loads first (latency overlaps W staging)
    float4 xreg[4];
#pragma unroll
    for (int i = 0; i < 4; i++) {
        int idx = i * 256 + tid;
        int ci = idx >> 3, px = (idx & 7) * 4;
        xreg[i] = *(const float4*)(X + ((size_t)bb * CC + ci) * HW + p0 + px);
    }

    // stage W1 (and W2) with a single sync
#pragma unroll
    for (int i = 0; i < 16; i++) {
        int idx = i * 256 + tid;
        int co = idx >> 5, ci = (idx & 31) * 4;
        float4 v = *(const float4*)(W1 + co * CC + ci);
        __half* d = (__half*)(dsm) + co * 136 + ci;
        d[0] = __float2half(v.x); d[1] = __float2half(v.y);
        d[2] = __float2half(v.z); d[3] = __float2half(v.w);
    }
    if (DUAL) {
#pragma unroll
        for (int i = 0; i < 16; i++) {
            int idx = i * 256 + tid;
            int co = idx >> 5, ci = (idx & 31) * 4;
            float4 v = *(const float4*)(W2 + co * CC + ci);
            __half* d = (__half*)(dsm + 34816) + co * 136 + ci;
            d[0] = __float2half(v.x); d[1] = __float2half(v.y);
            d[2] = __float2half(v.z); d[3] = __float2half(v.w);
        }
    }
    __syncthreads();
    uint32_t wa1[8][4], wa2[8][4];
    {
        int row = w * 16 + (lane & 15);
        int colb = (lane >> 4) * 8;
#pragma unroll
        for (int ks = 0; ks < 8; ks++) {
            ldsm4(wa1[ks], sb + (row * 136 + ks * 16 + colb) * 2);
            if (DUAL)
                ldsm4(wa2[ks], sb + 34816 + (row * 136 + ks * 16 + colb) * 2);
        }
    }
    __syncthreads();

    // stage X hi into [0, 8704)
#pragma unroll
    for (int i = 0; i < 4; i++) {
        int idx = i * 256 + tid;
        int ci = idx >> 3, px = (idx & 7) * 4;
        float vv[4] = { xreg[i].x, xreg[i].y, xreg[i].z, xreg[i].w };
#pragma unroll
        for (int j = 0; j < 4; j++)
            *((__half*)(dsm) + (px + j) * 136 + ci) = __float2half(vv[j]);
    }
    __syncthreads();

    float acc1[4][4], acc2[4][4];
#pragma unroll
    for (int nt = 0; nt < 4; nt++)
#pragma unroll
        for (int i = 0; i < 4; i++) { acc1[nt][i] = 0.0f; acc2[nt][i] = 0.0f; }

#pragma unroll
    for (int ks = 0; ks < 8; ks++) {
#pragma unroll
        for (int n0 = 0; n0 < 2; n0++) {
            uint32_t bh[4];
            ldsm4(bh, sb + ((n0 * 16 + brow) * 136 + ks * 16 + bcol8) * 2);
            mma16816(acc1[n0 * 2], wa1[ks], bh);
            mma16816(acc1[n0 * 2 + 1], wa1[ks], bh + 2);
            if (DUAL) {
                mma16816(acc2[n0 * 2], wa2[ks], bh);
                mma16816(acc2[n0 * 2 + 1], wa2[ks], bh + 2);
            }
        }
    }

    int coA = w * 16 + (lane >> 2);
    int coB = coA + 8;
    float b1A = b1[coA], b1B = b1[coB];
    float b2A = 0.0f, b2B = 0.0f;
    if (DUAL) { b2A = b2[coA]; b2B = b2[coB]; }
    size_t baseA = ((size_t)bb * CC + coA) * HW + p0;
    size_t baseB = ((size_t)bb * CC + coB) * HW + p0;
#pragma unroll
    for (int nt = 0; nt < 4; nt++) {
        int px = nt * 8 + 2 * (lane & 3);
        *(uint32_t*)(H1 + baseA + px) =
            cvt_f16x2((acc1[nt][1] + b1A) * hscale, (acc1[nt][0] + b1A) * hscale);
        *(uint32_t*)(H1 + baseB + px) =
            cvt_f16x2((acc1[nt][3] + b1B) * hscale, (acc1[nt][2] + b1B) * hscale);
        if (DUAL) {
            *(uint32_t*)(H2 + baseA + px) =
                cvt_f16x2(acc2[nt][1] + b2A, acc2[nt][0] + b2A);
            *(uint32_t*)(H2 + baseB + px) =
                cvt_f16x2(acc2[nt][3] + b2B, acc2[nt][2] + b2B);
        }
    }
}

// ================================================================
// output conv: fp32 2-term X + residual (unchanged from R11).
// ================================================================
__global__ __launch_bounds__(256) void conv_out(
    const float* __restrict__ X,
    const float* __restrict__ W1, const float* __restrict__ b1,
    float* __restrict__ Y1, const float* __restrict__ resid) {
    __shared__ __align__(16) char sbufc[34816];
    const int tid = threadIdx.x;
    const int lane = tid & 31;
    const int w = tid >> 5;
    const int bb = blockIdx.y;
    const int p0 = blockIdx.x * 32;
    const uint32_t sb = smem_u32(sbufc);
    const int brow = (lane & 7) + ((lane & 16) >> 1);
    const int bcol8 = (lane & 8) ? 8 : 0;

    float4 xreg[4];
#pragma unroll
    for (int i = 0; i < 4; i++) {
        int idx = i * 256 + tid;
        int ci = idx >> 3, px = (idx & 7) * 4;
        xreg[i] = *(const float4*)(X + ((size_t)bb * CC + ci) * HW + p0 + px);
    }

    uint32_t wa1[8][4];
    {
#pragma unroll
        for (int i = 0; i < 16; i++) {
            int idx = i * 256 + tid;
            int co = idx >> 5, ci = (idx & 31) * 4;
            float4 v = *(const float4*)(W1 + co * CC + ci);
            __half* d = (__half*)(sbufc) + co * 136 + ci;
            d[0] = __float2half(v.x); d[1] = __float2half(v.y);
            d[2] = __float2half(v.z); d[3] = __float2half(v.w);
        }
        __syncthreads();
        int row = w * 16 + (lane & 15);
        int colb = (lane >> 4) * 8;
#pragma unroll
        for (int ks = 0; ks < 8; ks++)
            ldsm4(wa1[ks], sb + (row * 136 + ks * 16 + colb) * 2);
        __syncthreads();
    }

#pragma unroll
    for (int i = 0; i < 4; i++) {
        int idx = i * 256 + tid;
        int ci = idx >> 3, px = (idx & 7) * 4;
        float vv[4] = { xreg[i].x, xreg[i].y, xreg[i].z, xreg[i].w };
#pragma unroll
        for (int j = 0; j < 4; j++) {
            __half hv = __float2half(vv[j]);
            *((__half*)(sbufc) + (px + j) * 136 + ci) = hv;
            *((__half*)(sbufc + 8704) + (px + j) * 136 + ci) =
                __float2half(vv[j] - __half2float(hv));
        }
    }
    __syncthreads();

    float acc1[4][4];
#pragma unroll
    for (int nt = 0; nt < 4; nt++)
#pragma unroll
        for (int i = 0; i < 4; i++) acc1[nt][i] = 0.0f;

#pragma unroll
    for (int ks = 0; ks < 8; ks++) {
#pragma unroll
        for (int n0 = 0; n0 < 2; n0++) {
            uint32_t bh[4], bl[4];
            uint32_t a = sb + ((n0 * 16 + brow) * 136 + ks * 16 + bcol8) * 2;
            ldsm4(bh, a);
            ldsm4(bl, a + 8704);
            mma16816(acc1[n0 * 2], wa1[ks], bh);
            mma16816(acc1[n0 * 2], wa1[ks], bl);
            mma16816(acc1[n0 * 2 + 1], wa1[ks], bh + 2);
            mma16816(acc1[n0 * 2 + 1], wa1[ks], bl + 2);
        }
    }

    int coA = w * 16 + (lane >> 2);
    int coB = coA + 8;
    float b1A = b1[coA], b1B = b1[coB];
    size_t baseA = ((size_t)bb * CC + coA) * HW + p0;
    size_t baseB = ((size_t)bb * CC + coB) * HW + p0;
#pragma unroll
    for (int nt = 0; nt < 4; nt++) {
        int px = nt * 8 + 2 * (lane & 3);
        float2 rA = *(const float2*)(resid + baseA + px);
        float2 rB = *(const float2*)(resid + baseB + px);
        *(float2*)(Y1 + baseA + px) =
            make_float2(acc1[nt][0] + b1A + rA.x, acc1[nt][1] + b1A + rA.y);
        *(float2*)(Y1 + baseB + px) =
            make_float2(acc1[nt][2] + b1B + rB.x, acc1[nt][3] + b1B + rB.y);
    }
}

// ================= fused mask convs, conv2 on packed FMA2 =====================
// m1 stored ci-paired: smi[r][x][c2] = (m1[2*c2], m1[2*c2+1]). conv2 keeps
// even/odd-ci partial sums in the two lanes of fma.rn.f32x2 (exact fp32),
// summed in the epilogue.
__global__ __launch_bounds__(256) void mask_fused(const float* __restrict__ seg,
                                                  const float* __restrict__ Wm1,
                                                  const float* __restrict__ bm1,
                                                  const float* __restrict__ Wm2,
                                                  const float* __restrict__ bm2) {
    int y = blockIdx.x, b = blockIdx.y;
    __shared__ float sseg[5][66];
    __shared__ __align__(8) float2 smi[3][66][16];
    const float* sgb = seg + (size_t)b * HW;
    for (int i = threadIdx.x; i < 5 * 66; i += 256) {
        int r = i / 66, x = i % 66;
        int yy = y + r - 2, xx = x - 1;
        sseg[r][x] = (yy >= 0 && yy < 64 && xx >= 0 && xx < 64)
                     ? sgb[yy * 64 + xx] : 0.0f;
    }
    __syncthreads();
    for (int i = threadIdx.x; i < 32 * 3 * 66; i += 256) {
        int c = i / 198, rem = i % 198, r = rem / 66, x = rem % 66;
        int yy = y + r - 1, xx = x - 1;
        float v = 0.0f;
        if (yy >= 0 && yy < 64 && xx >= 0 && xx < 64) {
            float acc = bm1[c];
            const float* wp = Wm1 + c * 9;
#pragma unroll
            for (int dy = 0; dy < 3; dy++)
#pragma unroll
                for (int dx = 0; dx < 3; dx++)
                    acc += wp[dy * 3 + dx] * sseg[r + dy][x + dx - 1];
            v = fmaxf(acc, 0.0f);
        }
        ((float*)&smi[r][x][c >> 1])[c & 1] = v;
    }
    __syncthreads();

    int co = threadIdx.x >> 1;
    int xh = (threadIdx.x & 1) * 32;
    ull acc2[32];
    float bb = bm2[co];
#pragma unroll
    for (int p = 0; p < 32; p++) acc2[p] = pk2(bb, 0.0f);
    const float* wbase = Wm2 + co * 288;

    for (int c2 = 0; c2 < 16; c2++) {
#pragma unroll
        for (int r = 0; r < 3; r++) {
            ull rv[34];
#pragma unroll
            for (int t = 0; t < 34; t++)
                rv[t] = *(const ull*)&smi[r][xh + t][c2];
            const float* wp = wbase + (2 * c2) * 9 + r * 3;   // even ci
            const float* wq = wp + 9;                          // odd ci
#pragma unroll
            for (int dx = 0; dx < 3; dx++) {
                ull w2 = pk2(wp[dx], wq[dx]);
#pragma unroll
                for (int p = 0; p < 32; p++)
                    acc2[p] = fma2(w2, rv[p + dx], acc2[p]);
            }
        }
    }

    float* out = g_mf + ((size_t)b * CC + co) * HW + y * 64 + xh;
#pragma unroll
    for (int p = 0; p < 32; p++) {
        float lo, hi;
        upk2(acc2[p], lo, hi);
        out[p] = lo + hi;
    }
}

// ---------------- launch ----------------
extern "C" void kernel_launch(void* const* d_in, const int* in_sizes, int n_in,
                              void* d_out, int out_size) {
    const float* sr  = (const float*)d_in[0];
    const float* seg = (const float*)d_in[1];
    const float* Wq  = (const float*)d_in[2];
    const float* bq  = (const float*)d_in[3];
    const float* Wm1 = (const float*)d_in[4];
    const float* bm1 = (const float*)d_in[5];
    const float* Wm2 = (const float*)d_in[6];
    const float* bm2 = (const float*)d_in[7];
    const float* Wk  = (const float*)d_in[8];
    const float* bk  = (const float*)d_in[9];
    const float* Wv  = (const float*)d_in[10];
    const float* bv  = (const float*)d_in[11];
    const float* Wo  = (const float*)d_in[12];
    const float* bo  = (const float*)d_in[13];
    float* out = (float*)d_out;

    float *pmf, *pg;
    __half *pqh, *pkh, *pvh;
    cudaGetSymbolAddress((void**)&pmf, g_mf);
    cudaGetSymbolAddress((void**)&pg, g_gd);
    cudaGetSymbolAddress((void**)&pqh, g_qh);
    cudaGetSymbolAddress((void**)&pkh, g_kh);
    cudaGetSymbolAddress((void**)&pvh, g_vh);

    static cudaStream_t s2 = nullptr;
    static cudaEvent_t e0 = nullptr, e1 = nullptr;
    if (s2 == nullptr) {
        cudaStreamCreateWithFlags(&s2, cudaStreamNonBlocking);
        cudaEventCreateWithFlags(&e0, cudaEventDisableTiming);
        cudaEventCreateWithFlags(&e1, cudaEventDisableTiming);
    }

    cudaFuncSetAttribute(attn_mma, cudaFuncAttributeMaxDynamicSharedMemorySize,
                         SBUF_BYTES);
    cudaFuncSetAttribute(conv_in<true>,
                         cudaFuncAttributeMaxDynamicSharedMemorySize, 69632);

    // fork: Q conv (depends only on sr) runs on s2 concurrently with mask chain
    cudaEventRecord(e0, 0);
    cudaStreamWaitEvent(s2, e0, 0);
    conv_in<false><<<dim3(HW / 32, BATCH), 256, 34816, s2>>>(
        sr, Wq, bq, pqh, SCALE2, nullptr, nullptr, nullptr);
    cudaEventRecord(e1, s2);

    mask_fused<<<dim3(64, BATCH), 256>>>(seg, Wm1, bm1, Wm2, bm2);
    conv_in<true><<<dim3(HW / 32, BATCH), 256, 69632>>>(
        pmf, Wk, bk, pkh, 1.0f, Wv, bv, pvh);

    // join: attention needs Q, K, V
    cudaStreamWaitEvent(0, e1, 0);
    attn_mma<<<dim3(32, HEADS, BATCH), 256, SBUF_BYTES>>>();
    conv_out<<<dim3(HW / 32, BATCH), 256>>>(pg, Wo, bo, out, sr);
}

// round 13
// speedup vs baseline: 6.5826x; 1.0284x over previous
#include <cuda_runtime.h>
#include <cuda_fp16.h>
#include <cstdint>
#include <cstddef>

#define BATCH 2
#define CC 128
#define HW 4096
#define HEADS 4
// 32^-0.5 * log2(e): softmax in base-2
#define SCALE2 0.25500526764086436f

// ---------------- scratch ----------------
__device__ float g_mf[BATCH * CC * HW];
__device__ float g_gd[BATCH * CC * HW];
__device__ __align__(16) __half g_qh[BATCH * CC * HW];
__device__ __align__(16) __half g_kh[BATCH * CC * HW];
__device__ __align__(16) __half g_vh[BATCH * CC * HW];

// ---------------- helpers ----------------
typedef unsigned long long ull;
__device__ __forceinline__ ull pk2(float a, float b) {
    ull r; asm("mov.b64 %0, {%1, %2};" : "=l"(r) : "f"(a), "f"(b)); return r;
}
__device__ __forceinline__ void upk2(ull v, float& a, float& b) {
    asm("mov.b64 {%0, %1}, %2;" : "=f"(a), "=f"(b) : "l"(v));
}
__device__ __forceinline__ ull fma2(ull a, ull b, ull c) {
    ull d; asm("fma.rn.f32x2 %0, %1, %2, %3;" : "=l"(d) : "l"(a), "l"(b), "l"(c)); return d;
}
__device__ __forceinline__ uint32_t smem_u32(const void* p) {
    uint32_t a;
    asm("{ .reg .u64 t; cvta.to.shared.u64 t, %1; cvt.u32.u64 %0, t; }" : "=r"(a) : "l"(p));
    return a;
}
__device__ __forceinline__ float ex2f(float x) {
    float r; asm("ex2.approx.f32 %0, %1;" : "=f"(r) : "f"(x)); return r;
}
__device__ __forceinline__ uint32_t cvt_f16x2(float hi, float lo) {
    uint32_t r; asm("cvt.rn.f16x2.f32 %0, %1, %2;" : "=r"(r) : "f"(hi), "f"(lo)); return r;
}
__device__ __forceinline__ uint32_t ex2_h2(uint32_t a) {
    uint32_t r; asm("ex2.approx.f16x2 %0, %1;" : "=r"(r) : "r"(a)); return r;
}
__device__ __forceinline__ void ldsm4(uint32_t* r, uint32_t addr) {
    asm volatile("ldmatrix.sync.aligned.m8n8.x4.shared.b16 {%0,%1,%2,%3}, [%4];"
        : "=r"(r[0]), "=r"(r[1]), "=r"(r[2]), "=r"(r[3]) : "r"(addr));
}
__device__ __forceinline__ void ldsm4t(uint32_t* r, uint32_t addr) {
    asm volatile("ldmatrix.sync.aligned.m8n8.x4.trans.shared.b16 {%0,%1,%2,%3}, [%4];"
        : "=r"(r[0]), "=r"(r[1]), "=r"(r[2]), "=r"(r[3]) : "r"(addr));
}
__device__ __forceinline__ void mma16816(float* c, const uint32_t* a, const uint32_t* b) {
    asm volatile("mma.sync.aligned.m16n8k16.row.col.f32.f16.f16.f32 "
        "{%0,%1,%2,%3}, {%4,%5,%6,%7}, {%8,%9}, {%0,%1,%2,%3};"
        : "+f"(c[0]), "+f"(c[1]), "+f"(c[2]), "+f"(c[3])
        : "r"(a[0]), "r"(a[1]), "r"(a[2]), "r"(a[3]), "r"(b[0]), "r"(b[1]));
}
__device__ __forceinline__ void cp16(uint32_t saddr, const void* g) {
    asm volatile("cp.async.cg.shared.global [%0], [%1], 16;" :: "r"(saddr), "l"(g));
}
#define CP_COMMIT() asm volatile("cp.async.commit_group;" ::: "memory")
#define CP_WAIT1()  asm volatile("cp.async.wait_group 1;" ::: "memory")
#define CP_WAIT2()  asm volatile("cp.async.wait_group 2;" ::: "memory")

// ================================================================
// flash attention: fp16 QK/PV, Q fp16 prescaled, lazy-max softmax
// (threshold-8 trigger). Cross-tile pipeline: every QK interleaved
// under a PV. 4-stage cp.async ring, unroll-4 -> immediate addresses.
// grid (32, HEADS, BATCH), 256 threads (8 warps), warp = 16 queries.
// per-stage (17408 B): K [32 d][136 j] at +0, V at +8704.
// Q tile [32 d][136 q] persistent after the 4 stages. Dynamic smem.
// ================================================================
#define STAGE 17408
#define NSTAGE 4
#define SB_Q (NSTAGE * STAGE)                 // 69632
#define SBUF_BYTES (SB_Q + 8704)              // 78336

__global__ void __launch_bounds__(256, 2) attn_mma() {
    extern __shared__ __align__(16) char sbuf[];
    const int tid = threadIdx.x;
    const int lane = tid & 31;
    const int w = tid >> 5;
    const int h = blockIdx.y, b = blockIdx.z;
    const int qb = blockIdx.x * 128;
    const size_t cbase = ((size_t)b * CC + h * 32) * HW;
    const __half* qgp = g_qh + cbase;
    const __half* kgp = g_kh + cbase;
    const __half* vgp = g_vh + cbase;
    const uint32_t sb = smem_u32(sbuf);

    // ---- cp.async prologue: Q (g0), stage0 (g1), stage1 (g2) ----
    const int cd = tid >> 3;
    const int cjh = (tid & 7) * 16;
    const uint32_t offK = (uint32_t)(cd * 136 + cjh) * 2;
    const uint32_t offV = 8704u + offK;
    const __half* gQ = qgp + (size_t)cd * HW + qb + cjh;
    const __half* gK = kgp + (size_t)cd * HW + cjh;
    const __half* gV = vgp + (size_t)cd * HW + cjh;
    cp16(sb + SB_Q + offK, gQ); cp16(sb + SB_Q + offK + 16, gQ + 8);
    CP_COMMIT();
    cp16(sb + offK, gK);       cp16(sb + offK + 16, gK + 8);
    cp16(sb + offV, gV);       cp16(sb + offV + 16, gV + 8);
    CP_COMMIT();
    cp16(sb + STAGE + offK, gK + 128); cp16(sb + STAGE + offK + 16, gK + 136);
    cp16(sb + STAGE + offV, gV + 128); cp16(sb + STAGE + offV + 16, gV + 136);
    CP_COMMIT();

    const int brow = (lane & 7) + ((lane & 16) >> 1);
    const int bcol8 = (lane & 8) ? 8 : 0;

    // ---- Q A-fragments ----
    CP_WAIT2();
    __syncthreads();
    uint32_t qa[2][4];
#pragma unroll
    for (int ks = 0; ks < 2; ks++)
        ldsm4t(qa[ks], sb + SB_Q + ((ks * 16 + brow) * 136 + w * 16 + bcol8) * 2);

    const uint32_t b2c[2] = { (lane < 4) ? 0x3C003C00u : 0u,
                              (lane < 4) ? 0x3C003C00u : 0u };

    float mrow0 = 0.0f, mrow1 = 0.0f;
    float o[4][4], ol[4];
#pragma unroll
    for (int nt = 0; nt < 4; nt++)
#pragma unroll
        for (int i = 0; i < 4; i++) o[nt][i] = 0.0f;
#pragma unroll
    for (int i = 0; i < 4; i++) ol[i] = 0.0f;

    float s[8][4];
    uint32_t pu[8][2];

    auto s_init = [&]() {
        float ns0 = -mrow0, ns1 = -mrow1;
#pragma unroll
        for (int nt = 0; nt < 8; nt++) {
            s[nt][0] = ns0; s[nt][1] = ns0;
            s[nt][2] = ns1; s[nt][3] = ns1;
        }
    };
    auto qk_piece = [&](uint32_t base, int idx, int joff) {
        int ks = idx >> 2, n0 = idx & 3;
        uint32_t bh[4];
        ldsm4t(bh, base + ((ks * 16 + (lane & 15)) * 136 +
                           joff + n0 * 16 + (lane >> 4) * 8) * 2);
        mma16816(s[n0 * 2], qa[ks], bh);
        mma16816(s[n0 * 2 + 1], qa[ks], bh + 2);
    };
    auto pv_piece = [&](uint32_t base, int ks, int joff) {
        uint32_t ah[4] = { pu[2 * ks][0], pu[2 * ks][1],
                           pu[2 * ks + 1][0], pu[2 * ks + 1][1] };
#pragma unroll
        for (int n0 = 0; n0 < 2; n0++) {
            uint32_t vh[4];
            ldsm4(vh, base + 8704 + ((n0 * 16 + brow) * 136 +
                                     joff + ks * 16 + bcol8) * 2);
            mma16816(o[n0 * 2], ah, vh);
            mma16816(o[n0 * 2 + 1], ah, vh + 2);
        }
        mma16816(ol, ah, b2c);
    };
    auto softmax = [&]() {
        float mt0 = s[0][0], mt1 = s[0][2];
#pragma unroll
        for (int nt = 0; nt < 8; nt++) {
            mt0 = fmaxf(mt0, fmaxf(s[nt][0], s[nt][1]));
            mt1 = fmaxf(mt1, fmaxf(s[nt][2], s[nt][3]));
        }
        if (__any_sync(0xffffffffu, fmaxf(mt0, mt1) > 8.0f)) {
            mt0 = fmaxf(mt0, __shfl_xor_sync(0xffffffffu, mt0, 1));
            mt0 = fmaxf(mt0, __shfl_xor_sync(0xffffffffu, mt0, 2));
            mt1 = fmaxf(mt1, __shfl_xor_sync(0xffffffffu, mt1, 1));
            mt1 = fmaxf(mt1, __shfl_xor_sync(0xffffffffu, mt1, 2));
            float d0 = fmaxf(mt0, 0.0f), d1 = fmaxf(mt1, 0.0f);
            float c0 = ex2f(-d0), c1 = ex2f(-d1);
            mrow0 += d0; mrow1 += d1;
#pragma unroll
            for (int nt = 0; nt < 4; nt++) {
                o[nt][0] *= c0; o[nt][1] *= c0;
                o[nt][2] *= c1; o[nt][3] *= c1;
            }
            ol[0] *= c0; ol[1] *= c0; ol[2] *= c1; ol[3] *= c1;
#pragma unroll
            for (int nt = 0; nt < 8; nt++) {
                s[nt][0] -= d0; s[nt][1] -= d0;
                s[nt][2] -= d1; s[nt][3] -= d1;
            }
        }
#pragma unroll
        for (int nt = 0; nt < 8; nt++) {
            pu[nt][0] = ex2_h2(cvt_f16x2(s[nt][1], s[nt][0]));
            pu[nt][1] = ex2_h2(cvt_f16x2(s[nt][3], s[nt][2]));
        }
    };

    // ---- ensure stage0 visible, then issue QK(h0, tile0) ----
    CP_WAIT1();
    __syncthreads();
    s_init();
#pragma unroll
    for (int i = 0; i < 8; i++) qk_piece(sb, i, 0);

#pragma unroll 4
    for (int t = 0; t < 32; t++) {
        const uint32_t bcur = sb + (uint32_t)(t & 3) * STAGE;
        const uint32_t bnxt = sb + (uint32_t)((t + 1) & 3) * STAGE;

        softmax();            // h0 -> pu
        s_init();             // s for h1
        // PV(h0) || QK(h1)
#pragma unroll
        for (int ks = 0; ks < 4; ks++) {
            pv_piece(bcur, ks, 0);
            qk_piece(bcur, 2 * ks, 64);
            qk_piece(bcur, 2 * ks + 1, 64);
        }
        softmax();            // h1 -> pu

        // prefetch tile t+2 into stage (t+2)&3 (safe: laggards read t&3,(t+3)&3)
        if (t + 2 < 32) {
            const uint32_t so = sb + (uint32_t)((t + 2) & 3) * STAGE;
            const int go = (t + 2) * 128;
            cp16(so + offK, gK + go);       cp16(so + offK + 16, gK + go + 8);
            cp16(so + offV, gV + go);       cp16(so + offV + 16, gV + go + 8);
        }
        CP_COMMIT();
        CP_WAIT1();           // stage (t+1)&3 copies (mine) complete
        __syncthreads();      // all threads' copies visible

        if (t < 31) {
            s_init();         // s for h0 of t+1
            // PV(h1) || QK(h0, t+1)
#pragma unroll
            for (int ks = 0; ks < 4; ks++) {
                pv_piece(bcur, ks, 64);
                qk_piece(bnxt, 2 * ks, 0);
                qk_piece(bnxt, 2 * ks + 1, 0);
            }
        } else {
#pragma unroll
            for (int ks = 0; ks < 4; ks++) pv_piece(bcur, ks, 64);
        }
    }

    // ---------------- finalize ----------------
    float l0 = __shfl_sync(0xffffffffu, ol[0], lane & 28);
    float l1 = __shfl_sync(0xffffffffu, ol[2], lane & 28);
    float i0 = 1.0f / l0, i1 = 1.0f / l1;
    int pix = qb + w * 16 + (lane >> 2);
#pragma unroll
    for (int nt = 0; nt < 4; nt++) {
        int d = nt * 8 + 2 * (lane & 3);
        g_gd[cbase + (size_t)d * HW + pix] = o[nt][0] * i0;
        g_gd[cbase + (size_t)(d + 1) * HW + pix] = o[nt][1] * i0;
        g_gd[cbase + (size_t)d * HW + pix + 8] = o[nt][2] * i1;
        g_gd[cbase + (size_t)(d + 1) * HW + pix + 8] = o[nt][3] * i1;
    }
}

// ================================================================
// input 1x1 conv via HMMA -> fp16 outputs (unchanged from R12).
// ================================================================
template<bool DUAL>
__global__ __launch_bounds__(256) void conv_in(
    const float* __restrict__ X,
    const float* __restrict__ W1, const float* __restrict__ b1,
    __half* __restrict__ H1, float hscale,
    const float* __restrict__ W2, const float* __restrict__ b2,
    __half* __restrict__ H2) {
    extern __shared__ __align__(16) char dsm[];
    const int tid = threadIdx.x;
    const int lane = tid & 31;
    const int w = tid >> 5;
    const int bb = blockIdx.y;
    const int p0 = blockIdx.x * 32;
    const uint32_t sb = smem_u32(dsm);
    const int brow = (lane & 7) + ((lane & 16) >> 1);
    const int bcol8 = (lane & 8) ? 8 : 0;

    float4 xreg[4];
#pragma unroll
    for (int i = 0; i < 4; i++) {
        int idx = i * 256 + tid;
        int ci = idx >> 3, px = (idx & 7) * 4;
        xreg[i] = *(const float4*)(X + ((size_t)bb * CC + ci) * HW + p0 + px);
    }

#pragma unroll
    for (int i = 0; i < 16; i++) {
        int idx = i * 256 + tid;
        int co = idx >> 5, ci = (idx & 31) * 4;
        float4 v = *(const float4*)(W1 + co * CC + ci);
        __half* d = (__half*)(dsm) + co * 136 + ci;
        d[0] = __float2half(v.x); d[1] = __float2half(v.y);
        d[2] = __float2half(v.z); d[3] = __float2half(v.w);
    }
    if (DUAL) {
#pragma unroll
        for (int i = 0; i < 16; i++) {
            int idx = i * 256 + tid;
            int co = idx >> 5, ci = (idx & 31) * 4;
            float4 v = *(const float4*)(W2 + co * CC + ci);
            __half* d = (__half*)(dsm + 34816) + co * 136 + ci;
            d[0] = __float2half(v.x); d[1] = __float2half(v.y);
            d[2] = __float2half(v.z); d[3] = __float2half(v.w);
        }
    }
    __syncthreads();
    uint32_t wa1[8][4], wa2[8][4];
    {
        int row = w * 16 + (lane & 15);
        int colb = (lane >> 4) * 8;
#pragma unroll
        for (int ks = 0; ks < 8; ks++) {
            ldsm4(wa1[ks], sb + (row * 136 + ks * 16 + colb) * 2);
            if (DUAL)
                ldsm4(wa2[ks], sb + 34816 + (row * 136 + ks * 16 + colb) * 2);
        }
    }
    __syncthreads();

#pragma unroll
    for (int i = 0; i < 4; i++) {
        int idx = i * 256 + tid;
        int ci = idx >> 3, px = (idx & 7) * 4;
        float vv[4] = { xreg[i].x, xreg[i].y, xreg[i].z, xreg[i].w };
#pragma unroll
        for (int j = 0; j < 4; j++)
            *((__half*)(dsm) + (px + j) * 136 + ci) = __float2half(vv[j]);
    }
    __syncthreads();

    float acc1[4][4], acc2[4][4];
#pragma unroll
    for (int nt = 0; nt < 4; nt++)
#pragma unroll
        for (int i = 0; i < 4; i++) { acc1[nt][i] = 0.0f; acc2[nt][i] = 0.0f; }

#pragma unroll
    for (int ks = 0; ks < 8; ks++) {
#pragma unroll
        for (int n0 = 0; n0 < 2; n0++) {
            uint32_t bh[4];
            ldsm4(bh, sb + ((n0 * 16 + brow) * 136 + ks * 16 + bcol8) * 2);
            mma16816(acc1[n0 * 2], wa1[ks], bh);
            mma16816(acc1[n0 * 2 + 1], wa1[ks], bh + 2);
            if (DUAL) {
                mma16816(acc2[n0 * 2], wa2[ks], bh);
                mma16816(acc2[n0 * 2 + 1], wa2[ks], bh + 2);
            }
        }
    }

    int coA = w * 16 + (lane >> 2);
    int coB = coA + 8;
    float b1A = b1[coA], b1B = b1[coB];
    float b2A = 0.0f, b2B = 0.0f;
    if (DUAL) { b2A = b2[coA]; b2B = b2[coB]; }
    size_t baseA = ((size_t)bb * CC + coA) * HW + p0;
    size_t baseB = ((size_t)bb * CC + coB) * HW + p0;
#pragma unroll
    for (int nt = 0; nt < 4; nt++) {
        int px = nt * 8 + 2 * (lane & 3);
        *(uint32_t*)(H1 + baseA + px) =
            cvt_f16x2((acc1[nt][1] + b1A) * hscale, (acc1[nt][0] + b1A) * hscale);
        *(uint32_t*)(H1 + baseB + px) =
            cvt_f16x2((acc1[nt][3] + b1B) * hscale, (acc1[nt][2] + b1B) * hscale);
        if (DUAL) {
            *(uint32_t*)(H2 + baseA + px) =
                cvt_f16x2(acc2[nt][1] + b2A, acc2[nt][0] + b2A);
            *(uint32_t*)(H2 + baseB + px) =
                cvt_f16x2(acc2[nt][3] + b2B, acc2[nt][2] + b2B);
        }
    }
}

// ================================================================
// output conv: fp32 2-term X + residual (unchanged).
// ================================================================
__global__ __launch_bounds__(256) void conv_out(
    const float* __restrict__ X,
    const float* __restrict__ W1, const float* __restrict__ b1,
    float* __restrict__ Y1, const float* __restrict__ resid) {
    __shared__ __align__(16) char sbufc[34816];
    const int tid = threadIdx.x;
    const int lane = tid & 31;
    const int w = tid >> 5;
    const int bb = blockIdx.y;
    const int p0 = blockIdx.x * 32;
    const uint32_t sb = smem_u32(sbufc);
    const int brow = (lane & 7) + ((lane & 16) >> 1);
    const int bcol8 = (lane & 8) ? 8 : 0;

    float4 xreg[4];
#pragma unroll
    for (int i = 0; i < 4; i++) {
        int idx = i * 256 + tid;
        int ci = idx >> 3, px = (idx & 7) * 4;
        xreg[i] = *(const float4*)(X + ((size_t)bb * CC + ci) * HW + p0 + px);
    }

    uint32_t wa1[8][4];
    {
#pragma unroll
        for (int i = 0; i < 16; i++) {
            int idx = i * 256 + tid;
            int co = idx >> 5, ci = (idx & 31) * 4;
            float4 v = *(const float4*)(W1 + co * CC + ci);
            __half* d = (__half*)(sbufc) + co * 136 + ci;
            d[0] = __float2half(v.x); d[1] = __float2half(v.y);
            d[2] = __float2half(v.z); d[3] = __float2half(v.w);
        }
        __syncthreads();
        int row = w * 16 + (lane & 15);
        int colb = (lane >> 4) * 8;
#pragma unroll
        for (int ks = 0; ks < 8; ks++)
            ldsm4(wa1[ks], sb + (row * 136 + ks * 16 + colb) * 2);
        __syncthreads();
    }

#pragma unroll
    for (int i = 0; i < 4; i++) {
        int idx = i * 256 + tid;
        int ci = idx >> 3, px = (idx & 7) * 4;
        float vv[4] = { xreg[i].x, xreg[i].y, xreg[i].z, xreg[i].w };
#pragma unroll
        for (int j = 0; j < 4; j++) {
            __half hv = __float2half(vv[j]);
            *((__half*)(sbufc) + (px + j) * 136 + ci) = hv;
            *((__half*)(sbufc + 8704) + (px + j) * 136 + ci) =
                __float2half(vv[j] - __half2float(hv));
        }
    }
    __syncthreads();

    float acc1[4][4];
#pragma unroll
    for (int nt = 0; nt < 4; nt++)
#pragma unroll
        for (int i = 0; i < 4; i++) acc1[nt][i] = 0.0f;

#pragma unroll
    for (int ks = 0; ks < 8; ks++) {
#pragma unroll
        for (int n0 = 0; n0 < 2; n0++) {
            uint32_t bh[4], bl[4];
            uint32_t a = sb + ((n0 * 16 + brow) * 136 + ks * 16 + bcol8) * 2;
            ldsm4(bh, a);
            ldsm4(bl, a + 8704);
            mma16816(acc1[n0 * 2], wa1[ks], bh);
            mma16816(acc1[n0 * 2], wa1[ks], bl);
            mma16816(acc1[n0 * 2 + 1], wa1[ks], bh + 2);
            mma16816(acc1[n0 * 2 + 1], wa1[ks], bl + 2);
        }
    }

    int coA = w * 16 + (lane >> 2);
    int coB = coA + 8;
    float b1A = b1[coA], b1B = b1[coB];
    size_t baseA = ((size_t)bb * CC + coA) * HW + p0;
    size_t baseB = ((size_t)bb * CC + coB) * HW + p0;
#pragma unroll
    for (int nt = 0; nt < 4; nt++) {
        int px = nt * 8 + 2 * (lane & 3);
        float2 rA = *(const float2*)(resid + baseA + px);
        float2 rB = *(const float2*)(resid + baseB + px);
        *(float2*)(Y1 + baseA + px) =
            make_float2(acc1[nt][0] + b1A + rA.x, acc1[nt][1] + b1A + rA.y);
        *(float2*)(Y1 + baseB + px) =
            make_float2(acc1[nt][2] + b1B + rB.x, acc1[nt][3] + b1B + rB.y);
    }
}

// ================= fused mask convs, conv2 on packed FMA2 (unchanged) ========
__global__ __launch_bounds__(256) void mask_fused(const float* __restrict__ seg,
                                                  const float* __restrict__ Wm1,
                                                  const float* __restrict__ bm1,
                                                  const float* __restrict__ Wm2,
                                                  const float* __restrict__ bm2) {
    int y = blockIdx.x, b = blockIdx.y;
    __shared__ float sseg[5][66];
    __shared__ __align__(8) float2 smi[3][66][16];
    const float* sgb = seg + (size_t)b * HW;
    for (int i = threadIdx.x; i < 5 * 66; i += 256) {
        int r = i / 66, x = i % 66;
        int yy = y + r - 2, xx = x - 1;
        sseg[r][x] = (yy >= 0 && yy < 64 && xx >= 0 && xx < 64)
                     ? sgb[yy * 64 + xx] : 0.0f;
    }
    __syncthreads();
    for (int i = threadIdx.x; i < 32 * 3 * 66; i += 256) {
        int c = i / 198, rem = i % 198, r = rem / 66, x = rem % 66;
        int yy = y + r - 1, xx = x - 1;
        float v = 0.0f;
        if (yy >= 0 && yy < 64 && xx >= 0 && xx < 64) {
            float acc = bm1[c];
            const float* wp = Wm1 + c * 9;
#pragma unroll
            for (int dy = 0; dy < 3; dy++)
#pragma unroll
                for (int dx = 0; dx < 3; dx++)
                    acc += wp[dy * 3 + dx] * sseg[r + dy][x + dx - 1];
            v = fmaxf(acc, 0.0f);
        }
        ((float*)&smi[r][x][c >> 1])[c & 1] = v;
    }
    __syncthreads();

    int co = threadIdx.x >> 1;
    int xh = (threadIdx.x & 1) * 32;
    ull acc2[32];
    float bb = bm2[co];
#pragma unroll
    for (int p = 0; p < 32; p++) acc2[p] = pk2(bb, 0.0f);
    const float* wbase = Wm2 + co * 288;

    for (int c2 = 0; c2 < 16; c2++) {
#pragma unroll
        for (int r = 0; r < 3; r++) {
            ull rv[34];
#pragma unroll
            for (int t = 0; t < 34; t++)
                rv[t] = *(const ull*)&smi[r][xh + t][c2];
            const float* wp = wbase + (2 * c2) * 9 + r * 3;
            const float* wq = wp + 9;
#pragma unroll
            for (int dx = 0; dx < 3; dx++) {
                ull w2 = pk2(wp[dx], wq[dx]);
#pragma unroll
                for (int p = 0; p < 32; p++)
                    acc2[p] = fma2(w2, rv[p + dx], acc2[p]);
            }
        }
    }

    float* out = g_mf + ((size_t)b * CC + co) * HW + y * 64 + xh;
#pragma unroll
    for (int p = 0; p < 32; p++) {
        float lo, hi;
        upk2(acc2[p], lo, hi);
        out[p] = lo + hi;
    }
}

// ---------------- launch ----------------
extern "C" void kernel_launch(void* const* d_in, const int* in_sizes, int n_in,
                              void* d_out, int out_size) {
    const float* sr  = (const float*)d_in[0];
    const float* seg = (const float*)d_in[1];
    const float* Wq  = (const float*)d_in[2];
    const float* bq  = (const float*)d_in[3];
    const float* Wm1 = (const float*)d_in[4];
    const float* bm1 = (const float*)d_in[5];
    const float* Wm2 = (const float*)d_in[6];
    const float* bm2 = (const float*)d_in[7];
    const float* Wk  = (const float*)d_in[8];
    const float* bk  = (const float*)d_in[9];
    const float* Wv  = (const float*)d_in[10];
    const float* bv  = (const float*)d_in[11];
    const float* Wo  = (const float*)d_in[12];
    const float* bo  = (const float*)d_in[13];
    float* out = (float*)d_out;

    float *pmf, *pg;
    __half *pqh, *pkh, *pvh;
    cudaGetSymbolAddress((void**)&pmf, g_mf);
    cudaGetSymbolAddress((void**)&pg, g_gd);
    cudaGetSymbolAddress((void**)&pqh, g_qh);
    cudaGetSymbolAddress((void**)&pkh, g_kh);
    cudaGetSymbolAddress((void**)&pvh, g_vh);

    static cudaStream_t s2 = nullptr;
    static cudaEvent_t e0 = nullptr, e1 = nullptr;
    if (s2 == nullptr) {
        cudaStreamCreateWithFlags(&s2, cudaStreamNonBlocking);
        cudaEventCreateWithFlags(&e0, cudaEventDisableTiming);
        cudaEventCreateWithFlags(&e1, cudaEventDisableTiming);
    }

    cudaFuncSetAttribute(attn_mma, cudaFuncAttributeMaxDynamicSharedMemorySize,
                         SBUF_BYTES);
    cudaFuncSetAttribute(conv_in<true>,
                         cudaFuncAttributeMaxDynamicSharedMemorySize, 69632);

    cudaEventRecord(e0, 0);
    cudaStreamWaitEvent(s2, e0, 0);
    conv_in<false><<<dim3(HW / 32, BATCH), 256, 34816, s2>>>(
        sr, Wq, bq, pqh, SCALE2, nullptr, nullptr, nullptr);
    cudaEventRecord(e1, s2);

    mask_fused<<<dim3(64, BATCH), 256>>>(seg, Wm1, bm1, Wm2, bm2);
    conv_in<true><<<dim3(HW / 32, BATCH), 256, 69632>>>(
        pmf, Wk, bk, pkh, 1.0f, Wv, bv, pvh);

    cudaStreamWaitEvent(0, e1, 0);
    attn_mma<<<dim3(32, HEADS, BATCH), 256, SBUF_BYTES>>>();
    conv_out<<<dim3(HW / 32, BATCH), 256>>>(pg, Wo, bo, out, sr);
}